// round 7
// baseline (speedup 1.0000x reference)
#include <cuda_runtime.h>
#include <math.h>
#include <stdint.h>

#define HEADS  24
#define HDIM   128
#define BATCH  2
#define TXT    256
#define IMG    1024
#define SEQ    1280          // TXT + IMG
#define DMODEL 3072
#define INNER  3072          // HEADS*HDIM
#define ROWS   (BATCH*SEQ)   // 2560

// ---------------- scratch (static device globals: allowed) ----------------
__device__ float g_x  [ROWS * DMODEL];            // tf32-rounded concat
__device__ float g_qkv[ROWS * 3 * INNER];
__device__ float g_q  [BATCH * HEADS * SEQ * HDIM]; // tf32-rounded
__device__ float g_k  [BATCH * HEADS * SEQ * HDIM]; // tf32-rounded
__device__ float g_v  [BATCH * HEADS * SEQ * HDIM]; // tf32-rounded
__device__ float g_o  [ROWS * INNER];             // tf32-rounded attn out
__device__ float g_wq [DMODEL * 3 * INNER];       // tf32-rounded w_qkv
__device__ float g_wo [INNER * DMODEL];           // tf32-rounded w_out

__device__ __forceinline__ uint32_t f2tf32(float f) {
    uint32_t u;
    asm("cvt.rna.tf32.f32 %0, %1;" : "=r"(u) : "f"(f));
    return u;
}
__device__ __forceinline__ float rtf(float f) {
    return __uint_as_float(f2tf32(f));
}

// ---------------- 0. weight rounding ----------------
__global__ void cvtw_kernel(const float* __restrict__ src, float* __restrict__ dst,
                            int n4) {
    int idx = blockIdx.x * blockDim.x + threadIdx.x;
    if (idx >= n4) return;
    float4 v = ((const float4*)src)[idx];
    v.x = rtf(v.x); v.y = rtf(v.y); v.z = rtf(v.z); v.w = rtf(v.w);
    ((float4*)dst)[idx] = v;
}

// ---------------- 1. concat (+ tf32 round) ----------------
__global__ void concat_kernel(const float* __restrict__ hid,
                              const float* __restrict__ enc) {
    int idx = blockIdx.x * blockDim.x + threadIdx.x;
    const int total = ROWS * DMODEL / 4;
    if (idx >= total) return;
    int row  = idx / (DMODEL / 4);
    int col4 = idx % (DMODEL / 4);
    int b = row / SEQ, s = row % SEQ;
    const float4* src = (s < TXT)
        ? (const float4*)(enc + (size_t)(b * TXT + s) * DMODEL)
        : (const float4*)(hid + (size_t)(b * IMG + (s - TXT)) * DMODEL);
    float4 v = src[col4];
    v.x = rtf(v.x); v.y = rtf(v.y); v.z = rtf(v.z); v.w = rtf(v.w);
    ((float4*)g_x)[idx] = v;
}

// ---------------- 2/5. TF32 tensor-core GEMM v3 ----------------
// CTA 128x128, 128 threads = 4 warps, warp tile 64x64.
// BK=16, 4-stage cp.async ring (wait_group 2), 1 barrier per K-tile.
// A row-major [m][ASTRIDE=20], B row-major [k][BSTRIDE=136]; both
// fragment patterns enumerate all 32 banks -> conflict-free.
#define BKK 16
#define ASTRIDE 20
#define BSTRIDE 136
#define STAGE_A (128 * ASTRIDE)          // 2560 floats
#define STAGE_B (BKK * BSTRIDE)          // 2176 floats
#define STAGE   (STAGE_A + STAGE_B)      // 4736 floats = 18944 B
#define NSTAGES 4
#define GEMM_SMEM ((size_t)NSTAGES * STAGE * sizeof(float))   // 75776 B

template <int REMAP>
__global__ __launch_bounds__(128, 2)
void mma_gemm(int M, int N, int K,
              const float* __restrict__ A, const float* __restrict__ B,
              const float* __restrict__ bias, float* __restrict__ C) {
    extern __shared__ float sh[];
    int tid  = threadIdx.x;
    int lane = tid & 31, wid = tid >> 5;
    int wm = wid >> 1;        // 0..1 -> 64 rows
    int wn = wid & 1;         // 0..1 -> 64 cols
    int bm = blockIdx.y * 128;
    int bn = blockIdx.x * 128;
    int r4 = lane >> 2, kc = lane & 3;

    const float* Ab = A + (size_t)bm * K;
    const float* Bb = B + bn;

    float acc[4][8][4];
    #pragma unroll
    for (int i = 0; i < 4; i++)
        #pragma unroll
        for (int j = 0; j < 8; j++)
            #pragma unroll
            for (int r = 0; r < 4; r++) acc[i][j][r] = 0.f;

    auto copy_tile = [&](int k0, int s) {
        float* As = sh + s * STAGE;
        float* Bs = As + STAGE_A;
        #pragma unroll
        for (int i = 0; i < 4; i++) {
            int idx = tid + i * 128;
            int ar = idx >> 2, ac4 = idx & 3;      // 128 rows x 16 floats
            uint32_t da = (uint32_t)__cvta_generic_to_shared(
                As + ar * ASTRIDE + ac4 * 4);
            const float* sa = Ab + (size_t)ar * K + k0 + ac4 * 4;
            asm volatile("cp.async.cg.shared.global [%0], [%1], 16;"
                         :: "r"(da), "l"(sa));
            int brr = idx >> 5, bc4 = idx & 31;    // 16 rows x 128 floats
            uint32_t db = (uint32_t)__cvta_generic_to_shared(
                Bs + brr * BSTRIDE + bc4 * 4);
            const float* sb = Bb + (size_t)(k0 + brr) * N + bc4 * 4;
            asm volatile("cp.async.cg.shared.global [%0], [%1], 16;"
                         :: "r"(db), "l"(sb));
        }
        asm volatile("cp.async.commit_group;");
    };

    int nK = K / BKK;
    copy_tile(0, 0);
    copy_tile(BKK, 1);
    copy_tile(2 * BKK, 2);

    for (int kt = 0; kt < nK; kt++) {
        asm volatile("cp.async.wait_group 2;");
        __syncthreads();
        if (kt + 3 < nK) copy_tile((kt + 3) * BKK, (kt + 3) & 3);

        const float* As = sh + (kt & 3) * STAGE;
        const float* Bs = As + STAGE_A;

        #pragma unroll
        for (int kk = 0; kk < 2; kk++) {
            uint32_t af[4][4], bf[8][2];
            #pragma unroll
            for (int mt = 0; mt < 4; mt++) {
                const float* pa = As + (wm * 64 + mt * 16 + r4) * ASTRIDE + kk * 8 + kc;
                af[mt][0] = __float_as_uint(pa[0]);
                af[mt][1] = __float_as_uint(pa[8 * ASTRIDE]);
                af[mt][2] = __float_as_uint(pa[4]);
                af[mt][3] = __float_as_uint(pa[8 * ASTRIDE + 4]);
            }
            #pragma unroll
            for (int nt = 0; nt < 8; nt++) {
                const float* pb = Bs + (kk * 8 + kc) * BSTRIDE + wn * 64 + nt * 8 + r4;
                bf[nt][0] = __float_as_uint(pb[0]);
                bf[nt][1] = __float_as_uint(pb[4 * BSTRIDE]);
            }
            #pragma unroll
            for (int mt = 0; mt < 4; mt++)
                #pragma unroll
                for (int nt = 0; nt < 8; nt++) {
                    asm volatile(
                        "mma.sync.aligned.m16n8k8.row.col.f32.tf32.tf32.f32 "
                        "{%0,%1,%2,%3}, {%4,%5,%6,%7}, {%8,%9}, {%0,%1,%2,%3};"
                        : "+f"(acc[mt][nt][0]), "+f"(acc[mt][nt][1]),
                          "+f"(acc[mt][nt][2]), "+f"(acc[mt][nt][3])
                        : "r"(af[mt][0]), "r"(af[mt][1]),
                          "r"(af[mt][2]), "r"(af[mt][3]),
                          "r"(bf[nt][0]), "r"(bf[nt][1]));
                }
        }
    }

    #pragma unroll
    for (int mt = 0; mt < 4; mt++) {
        #pragma unroll
        for (int half = 0; half < 2; half++) {
            int m = bm + wm * 64 + mt * 16 + r4 + half * 8;
            float* crow;
            if (REMAP) {
                int b = m / SEQ, s = m % SEQ;
                int orow = (s < TXT) ? (BATCH * IMG + b * TXT + s)
                                     : (b * IMG + (s - TXT));
                crow = C + (size_t)orow * N;
            } else {
                crow = C + (size_t)m * N;
            }
            #pragma unroll
            for (int nt = 0; nt < 8; nt++) {
                int n = bn + wn * 64 + nt * 8 + kc * 2;
                float2 v;
                v.x = acc[mt][nt][half * 2 + 0] + bias[n];
                v.y = acc[mt][nt][half * 2 + 1] + bias[n + 1];
                *(float2*)(crow + n) = v;
            }
        }
    }
}

// ---------------- 3. LayerNorm + partial RoPE (+ tf32 round q/k/v) ----------
__global__ void ln_rope_kernel(const float* __restrict__ cosb,
                               const float* __restrict__ sinb) {
    int gw   = (blockIdx.x * blockDim.x + threadIdx.x) >> 5;
    int lane = threadIdx.x & 31;
    if (gw >= BATCH * SEQ * HEADS) return;
    int h = gw % HEADS;
    int s = (gw / HEADS) % SEQ;
    int b = gw / (HEADS * SEQ);
    const float* base = g_qkv + (size_t)(b * SEQ + s) * (3 * INNER) + h * HDIM;
    size_t orow = ((size_t)(b * HEADS + h) * SEQ + s) * HDIM;
    bool img = (s >= TXT);
    float c4[4], s4[4];
    if (img) {
        float4 cv = *(const float4*)(cosb + (size_t)(s - TXT) * HDIM + lane * 4);
        float4 sv = *(const float4*)(sinb + (size_t)(s - TXT) * HDIM + lane * 4);
        c4[0] = cv.x; c4[1] = cv.y; c4[2] = cv.z; c4[3] = cv.w;
        s4[0] = sv.x; s4[1] = sv.y; s4[2] = sv.z; s4[3] = sv.w;
    }
    float sgn = (lane < 16) ? -1.f : 1.f;
    #pragma unroll
    for (int qk = 0; qk < 2; qk++) {
        float4 xv = *(const float4*)(base + qk * INNER + lane * 4);
        float x[4] = {xv.x, xv.y, xv.z, xv.w};
        float sum = x[0] + x[1] + x[2] + x[3];
        #pragma unroll
        for (int o = 16; o > 0; o >>= 1) sum += __shfl_xor_sync(0xffffffffu, sum, o);
        float mu = sum * (1.f / 128.f);
        float vs = 0.f;
        #pragma unroll
        for (int i = 0; i < 4; i++) { float d = x[i] - mu; vs += d * d; x[i] = d; }
        #pragma unroll
        for (int o = 16; o > 0; o >>= 1) vs += __shfl_xor_sync(0xffffffffu, vs, o);
        float inv = rsqrtf(vs * (1.f / 128.f) + 1e-5f);
        #pragma unroll
        for (int i = 0; i < 4; i++) x[i] *= inv;
        if (img) {
            float p[4];
            #pragma unroll
            for (int i = 0; i < 4; i++) p[i] = __shfl_xor_sync(0xffffffffu, x[i], 16);
            #pragma unroll
            for (int i = 0; i < 4; i++) x[i] = x[i] * c4[i] + sgn * p[i] * s4[i];
        }
        float4 ov = {rtf(x[0]), rtf(x[1]), rtf(x[2]), rtf(x[3])};
        float* dst = qk == 0 ? g_q : g_k;
        *(float4*)(dst + orow + lane * 4) = ov;
    }
    {
        float4 vv = *(const float4*)(base + 2 * INNER + lane * 4);
        vv.x = rtf(vv.x); vv.y = rtf(vv.y); vv.z = rtf(vv.z); vv.w = rtf(vv.w);
        *(float4*)(g_v + orow + lane * 4) = vv;
    }
}

// ---------------- 4. flash attention, tf32 tensor cores ----------------
#define KST 132
#define VST 136
#define PST 68
#define ATT_SMEM ((64 * KST + 64 * VST + 4 * 16 * PST) * sizeof(float))

__global__ __launch_bounds__(128)
void attn_tc_kernel() {
    extern __shared__ float sm[];
    float* Ks = sm;
    float* Vs = Ks + 64 * KST;
    float* Ps = Vs + 64 * VST;

    int qt = blockIdx.x, h = blockIdx.y, b = blockIdx.z;
    int tid = threadIdx.x, lane = tid & 31, wid = tid >> 5;
    size_t hb = (size_t)(b * HEADS + h) * SEQ * HDIM;
    const float* qb = g_q + hb + (size_t)qt * 64 * HDIM;
    const float* kb = g_k + hb;
    const float* vb = g_v + hb;

    for (int i = tid; i < 64 * 32; i += 128) {
        int r = i >> 5, c4 = i & 31;
        *(float4*)(Ks + r * KST + c4 * 4) =
            *(const float4*)(qb + (size_t)r * HDIM + c4 * 4);
    }
    __syncthreads();

    uint32_t qf[16][4];
    {
        const float* p0 = Ks + (wid * 16 + (lane >> 2)) * KST + (lane & 3);
        #pragma unroll
        for (int kk = 0; kk < 16; kk++) {
            qf[kk][0] = __float_as_uint(p0[kk * 8]);
            qf[kk][1] = __float_as_uint(p0[8 * KST + kk * 8]);
            qf[kk][2] = __float_as_uint(p0[kk * 8 + 4]);
            qf[kk][3] = __float_as_uint(p0[8 * KST + kk * 8 + 4]);
        }
    }
    __syncthreads();

    float oacc[16][4];
    #pragma unroll
    for (int nt = 0; nt < 16; nt++)
        #pragma unroll
        for (int r = 0; r < 4; r++) oacc[nt][r] = 0.f;

    float m_lo = -INFINITY, m_hi = -INFINITY, l_lo = 0.f, l_hi = 0.f;
    const float scale = 0.08838834764831845f;
    float* Pw = Ps + wid * 16 * PST;

    for (int kt = 0; kt < SEQ / 64; kt++) {
        for (int i = tid; i < 64 * 32; i += 128) {
            int r = i >> 5, c4 = i & 31;
            *(float4*)(Ks + r * KST + c4 * 4) =
                *(const float4*)(kb + (size_t)(kt * 64 + r) * HDIM + c4 * 4);
            *(float4*)(Vs + r * VST + c4 * 4) =
                *(const float4*)(vb + (size_t)(kt * 64 + r) * HDIM + c4 * 4);
        }
        __syncthreads();

        float sacc[8][4];
        #pragma unroll
        for (int nt = 0; nt < 8; nt++)
            #pragma unroll
            for (int r = 0; r < 4; r++) sacc[nt][r] = 0.f;

        #pragma unroll
        for (int kk = 0; kk < 16; kk++) {
            uint32_t bf[8][2];
            #pragma unroll
            for (int nt = 0; nt < 8; nt++) {
                const float* p = Ks + (nt * 8 + (lane >> 2)) * KST + kk * 8 + (lane & 3);
                bf[nt][0] = __float_as_uint(p[0]);
                bf[nt][1] = __float_as_uint(p[4]);
            }
            #pragma unroll
            for (int nt = 0; nt < 8; nt++) {
                asm volatile(
                    "mma.sync.aligned.m16n8k8.row.col.f32.tf32.tf32.f32 "
                    "{%0,%1,%2,%3}, {%4,%5,%6,%7}, {%8,%9}, {%0,%1,%2,%3};"
                    : "+f"(sacc[nt][0]), "+f"(sacc[nt][1]),
                      "+f"(sacc[nt][2]), "+f"(sacc[nt][3])
                    : "r"(qf[kk][0]), "r"(qf[kk][1]),
                      "r"(qf[kk][2]), "r"(qf[kk][3]),
                      "r"(bf[nt][0]), "r"(bf[nt][1]));
            }
        }

        float mx_lo = m_lo, mx_hi = m_hi;
        #pragma unroll
        for (int nt = 0; nt < 8; nt++) {
            sacc[nt][0] *= scale; sacc[nt][1] *= scale;
            sacc[nt][2] *= scale; sacc[nt][3] *= scale;
            mx_lo = fmaxf(mx_lo, fmaxf(sacc[nt][0], sacc[nt][1]));
            mx_hi = fmaxf(mx_hi, fmaxf(sacc[nt][2], sacc[nt][3]));
        }
        #pragma unroll
        for (int o = 1; o <= 2; o <<= 1) {
            mx_lo = fmaxf(mx_lo, __shfl_xor_sync(0xffffffffu, mx_lo, o));
            mx_hi = fmaxf(mx_hi, __shfl_xor_sync(0xffffffffu, mx_hi, o));
        }
        float f_lo = __expf(m_lo - mx_lo);
        float f_hi = __expf(m_hi - mx_hi);
        float sum_lo = 0.f, sum_hi = 0.f;
        #pragma unroll
        for (int nt = 0; nt < 8; nt++) {
            float p0 = __expf(sacc[nt][0] - mx_lo);
            float p1 = __expf(sacc[nt][1] - mx_lo);
            float p2 = __expf(sacc[nt][2] - mx_hi);
            float p3 = __expf(sacc[nt][3] - mx_hi);
            sum_lo += p0 + p1; sum_hi += p2 + p3;
            int col = nt * 8 + 2 * (lane & 3);
            float2 w0 = {rtf(p0), rtf(p1)};
            float2 w1 = {rtf(p2), rtf(p3)};
            *(float2*)(Pw + (lane >> 2) * PST + col) = w0;
            *(float2*)(Pw + ((lane >> 2) + 8) * PST + col) = w1;
        }
        #pragma unroll
        for (int o = 1; o <= 2; o <<= 1) {
            sum_lo += __shfl_xor_sync(0xffffffffu, sum_lo, o);
            sum_hi += __shfl_xor_sync(0xffffffffu, sum_hi, o);
        }
        l_lo = l_lo * f_lo + sum_lo;
        l_hi = l_hi * f_hi + sum_hi;
        m_lo = mx_lo; m_hi = mx_hi;
        __syncwarp();

        #pragma unroll
        for (int nt = 0; nt < 16; nt++) {
            oacc[nt][0] *= f_lo; oacc[nt][1] *= f_lo;
            oacc[nt][2] *= f_hi; oacc[nt][3] *= f_hi;
        }
        #pragma unroll
        for (int kk = 0; kk < 8; kk++) {
            uint32_t af[4];
            const float* pa = Pw + (lane >> 2) * PST + kk * 8 + (lane & 3);
            af[0] = __float_as_uint(pa[0]);
            af[1] = __float_as_uint(pa[8 * PST]);
            af[2] = __float_as_uint(pa[4]);
            af[3] = __float_as_uint(pa[8 * PST + 4]);
            const float* vrow0 = Vs + (kk * 8 + (lane & 3)) * VST + (lane >> 2);
            const float* vrow1 = vrow0 + 4 * VST;
            #pragma unroll
            for (int nt = 0; nt < 16; nt++) {
                uint32_t b0 = __float_as_uint(vrow0[nt * 8]);
                uint32_t b1 = __float_as_uint(vrow1[nt * 8]);
                asm volatile(
                    "mma.sync.aligned.m16n8k8.row.col.f32.tf32.tf32.f32 "
                    "{%0,%1,%2,%3}, {%4,%5,%6,%7}, {%8,%9}, {%0,%1,%2,%3};"
                    : "+f"(oacc[nt][0]), "+f"(oacc[nt][1]),
                      "+f"(oacc[nt][2]), "+f"(oacc[nt][3])
                    : "r"(af[0]), "r"(af[1]), "r"(af[2]), "r"(af[3]),
                      "r"(b0), "r"(b1));
            }
        }
        __syncthreads();
    }

    float inv_lo = 1.f / l_lo, inv_hi = 1.f / l_hi;
    int r = qt * 64 + wid * 16 + (lane >> 2);
    float* ob0 = g_o + ((size_t)b * SEQ + r) * INNER + h * HDIM;
    float* ob1 = g_o + ((size_t)b * SEQ + r + 8) * INNER + h * HDIM;
    #pragma unroll
    for (int nt = 0; nt < 16; nt++) {
        int col = nt * 8 + 2 * (lane & 3);
        float2 v0 = {rtf(oacc[nt][0] * inv_lo), rtf(oacc[nt][1] * inv_lo)};
        float2 v1 = {rtf(oacc[nt][2] * inv_hi), rtf(oacc[nt][3] * inv_hi)};
        *(float2*)(ob0 + col) = v0;
        *(float2*)(ob1 + col) = v1;
    }
}

// ---------------- host ----------------
extern "C" void kernel_launch(void* const* d_in, const int* in_sizes, int n_in,
                              void* d_out, int out_size) {
    const float* hid   = (const float*)d_in[0];
    const float* enc   = (const float*)d_in[1];
    const float* cosb  = (const float*)d_in[2];
    const float* sinb  = (const float*)d_in[3];
    const float* w_qkv = (const float*)d_in[4];
    const float* b_qkv = (const float*)d_in[5];
    const float* w_out = (const float*)d_in[6];
    const float* b_out = (const float*)d_in[7];
    float* out = (float*)d_out;

    float *xp, *qkvp, *op, *wqp, *wop;
    cudaGetSymbolAddress((void**)&xp,   g_x);
    cudaGetSymbolAddress((void**)&qkvp, g_qkv);
    cudaGetSymbolAddress((void**)&op,   g_o);
    cudaGetSymbolAddress((void**)&wqp,  g_wq);
    cudaGetSymbolAddress((void**)&wop,  g_wo);

    static bool attr_set = false;
    if (!attr_set) {
        cudaFuncSetAttribute(mma_gemm<0>, cudaFuncAttributeMaxDynamicSharedMemorySize,
                             (int)GEMM_SMEM);
        cudaFuncSetAttribute(mma_gemm<1>, cudaFuncAttributeMaxDynamicSharedMemorySize,
                             (int)GEMM_SMEM);
        cudaFuncSetAttribute(attn_tc_kernel, cudaFuncAttributeMaxDynamicSharedMemorySize,
                             (int)ATT_SMEM);
        attr_set = true;
    }

    // 0. round weights to tf32
    {
        int n4q = DMODEL * 3 * INNER / 4;
        cvtw_kernel<<<(n4q + 255) / 256, 256>>>(w_qkv, wqp, n4q);
        int n4o = INNER * DMODEL / 4;
        cvtw_kernel<<<(n4o + 255) / 256, 256>>>(w_out, wop, n4o);
    }
    // 1. concat (+round)
    {
        int total = ROWS * DMODEL / 4;
        concat_kernel<<<(total + 255) / 256, 256>>>(hid, enc);
    }
    // 2. qkv gemm
    {
        dim3 grid(3 * INNER / 128, ROWS / 128);
        mma_gemm<0><<<grid, 128, GEMM_SMEM>>>(ROWS, 3 * INNER, DMODEL,
                                              xp, wqp, b_qkv, qkvp);
    }
    // 3. LN + RoPE (+round)
    {
        int warps = BATCH * SEQ * HEADS;
        ln_rope_kernel<<<(warps + 7) / 8, 256>>>(cosb, sinb);
    }
    // 4. attention
    {
        dim3 grid(SEQ / 64, HEADS, BATCH);
        attn_tc_kernel<<<grid, 128, ATT_SMEM>>>();
    }
    // 5. out proj with row remap
    {
        dim3 grid(DMODEL / 128, ROWS / 128);
        mma_gemm<1><<<grid, 128, GEMM_SMEM>>>(ROWS, DMODEL, DMODEL,
                                              op, wop, b_out, out);
    }
}

// round 8
// speedup vs baseline: 1.5247x; 1.5247x over previous
#include <cuda_runtime.h>
#include <math.h>
#include <stdint.h>

#define HEADS  24
#define HDIM   128
#define BATCH  2
#define TXT    256
#define IMG    1024
#define SEQ    1280          // TXT + IMG
#define DMODEL 3072
#define INNER  3072          // HEADS*HDIM
#define ROWS   (BATCH*SEQ)   // 2560

// ---------------- scratch (static device globals: allowed) ----------------
__device__ float g_x  [ROWS * DMODEL];            // tf32-rounded concat
__device__ float g_qkv[ROWS * 3 * INNER];
__device__ float g_q  [BATCH * HEADS * SEQ * HDIM]; // tf32-rounded
__device__ float g_k  [BATCH * HEADS * SEQ * HDIM]; // tf32-rounded
__device__ float g_v  [BATCH * HEADS * SEQ * HDIM]; // tf32-rounded
__device__ float g_o  [ROWS * INNER];             // tf32-rounded attn out
__device__ float g_wq [DMODEL * 3 * INNER];       // tf32-rounded w_qkv
__device__ float g_wo [INNER * DMODEL];           // tf32-rounded w_out

__device__ __forceinline__ uint32_t f2tf32(float f) {
    uint32_t u;
    asm("cvt.rna.tf32.f32 %0, %1;" : "=r"(u) : "f"(f));
    return u;
}
__device__ __forceinline__ float rtf(float f) {
    return __uint_as_float(f2tf32(f));
}

// ---------------- 0. weight rounding ----------------
__global__ void cvtw_kernel(const float* __restrict__ src, float* __restrict__ dst,
                            int n4) {
    int idx = blockIdx.x * blockDim.x + threadIdx.x;
    if (idx >= n4) return;
    float4 v = ((const float4*)src)[idx];
    v.x = rtf(v.x); v.y = rtf(v.y); v.z = rtf(v.z); v.w = rtf(v.w);
    ((float4*)dst)[idx] = v;
}

// ---------------- 1. concat (+ tf32 round) ----------------
__global__ void concat_kernel(const float* __restrict__ hid,
                              const float* __restrict__ enc) {
    int idx = blockIdx.x * blockDim.x + threadIdx.x;
    const int total = ROWS * DMODEL / 4;
    if (idx >= total) return;
    int row  = idx / (DMODEL / 4);
    int col4 = idx % (DMODEL / 4);
    int b = row / SEQ, s = row % SEQ;
    const float4* src = (s < TXT)
        ? (const float4*)(enc + (size_t)(b * TXT + s) * DMODEL)
        : (const float4*)(hid + (size_t)(b * IMG + (s - TXT)) * DMODEL);
    float4 v = src[col4];
    v.x = rtf(v.x); v.y = rtf(v.y); v.z = rtf(v.z); v.w = rtf(v.w);
    ((float4*)g_x)[idx] = v;
}

// ---------------- 2/5. TF32 tensor-core GEMM (R5 shape + 3-stage ring) ------
// CTA 128x128, 256 threads = 8 warps, warp tile 64x32 (R5 proven config).
// BK=32, 3-stage cp.async ring, wait_group 1 -> one tile of load slack.
#define ASTRIDE 36
#define BSTRIDE 136
#define STAGE_A (128 * ASTRIDE)          // 4608 floats
#define STAGE_B (32 * BSTRIDE)           // 4352 floats
#define STAGE   (STAGE_A + STAGE_B)      // 8960 floats = 35840 B
#define NSTAGES 3
#define GEMM_SMEM ((size_t)NSTAGES * STAGE * sizeof(float))   // 107520 B

template <int REMAP>
__global__ __launch_bounds__(256, 2)
void mma_gemm(int M, int N, int K,
              const float* __restrict__ A, const float* __restrict__ B,
              const float* __restrict__ bias, float* __restrict__ C) {
    extern __shared__ float sh[];
    int tid  = threadIdx.x;
    int lane = tid & 31, wid = tid >> 5;
    int wm = wid >> 2;        // 0..1 -> 64 rows
    int wn = wid & 3;         // 0..3 -> 32 cols
    int bm = blockIdx.y * 128;
    int bn = blockIdx.x * 128;
    int r4 = lane >> 2, kc = lane & 3;

    const float* Ab = A + (size_t)bm * K;
    const float* Bb = B + bn;

    float acc[4][4][4];
    #pragma unroll
    for (int i = 0; i < 4; i++)
        #pragma unroll
        for (int j = 0; j < 4; j++)
            #pragma unroll
            for (int r = 0; r < 4; r++) acc[i][j][r] = 0.f;

    auto copy_tile = [&](int k0, int s) {
        float* As = sh + s * STAGE;
        float* Bs = As + STAGE_A;
        #pragma unroll
        for (int i = 0; i < 4; i++) {
            int idx = tid + i * 256;
            int ar = idx >> 3, ac4 = idx & 7;
            uint32_t da = (uint32_t)__cvta_generic_to_shared(
                As + ar * ASTRIDE + ac4 * 4);
            const float* sa = Ab + (size_t)ar * K + k0 + ac4 * 4;
            asm volatile("cp.async.cg.shared.global [%0], [%1], 16;"
                         :: "r"(da), "l"(sa));
            int brr = idx >> 5, bc4 = idx & 31;
            uint32_t db = (uint32_t)__cvta_generic_to_shared(
                Bs + brr * BSTRIDE + bc4 * 4);
            const float* sb = Bb + (size_t)(k0 + brr) * N + bc4 * 4;
            asm volatile("cp.async.cg.shared.global [%0], [%1], 16;"
                         :: "r"(db), "l"(sb));
        }
        asm volatile("cp.async.commit_group;");
    };

    int nK = K / 32;
    copy_tile(0, 0);
    copy_tile(32, 1);

    int s_cur = 0, s_nxt = 2;            // stage to compute / stage to fill
    for (int kt = 0; kt < nK; kt++) {
        asm volatile("cp.async.wait_group 1;");
        __syncthreads();
        if (kt + 2 < nK) copy_tile((kt + 2) * 32, s_nxt);

        const float* As = sh + s_cur * STAGE;
        const float* Bs = As + STAGE_A;

        #pragma unroll
        for (int kk = 0; kk < 4; kk++) {
            uint32_t af[4][4], bf[4][2];
            #pragma unroll
            for (int mt = 0; mt < 4; mt++) {
                const float* pa = As + (wm * 64 + mt * 16 + r4) * ASTRIDE + kk * 8 + kc;
                af[mt][0] = __float_as_uint(pa[0]);
                af[mt][1] = __float_as_uint(pa[8 * ASTRIDE]);
                af[mt][2] = __float_as_uint(pa[4]);
                af[mt][3] = __float_as_uint(pa[8 * ASTRIDE + 4]);
            }
            #pragma unroll
            for (int nt = 0; nt < 4; nt++) {
                const float* pb = Bs + (kk * 8 + kc) * BSTRIDE + wn * 32 + nt * 8 + r4;
                bf[nt][0] = __float_as_uint(pb[0]);
                bf[nt][1] = __float_as_uint(pb[4 * BSTRIDE]);
            }
            #pragma unroll
            for (int mt = 0; mt < 4; mt++)
                #pragma unroll
                for (int nt = 0; nt < 4; nt++) {
                    asm volatile(
                        "mma.sync.aligned.m16n8k8.row.col.f32.tf32.tf32.f32 "
                        "{%0,%1,%2,%3}, {%4,%5,%6,%7}, {%8,%9}, {%0,%1,%2,%3};"
                        : "+f"(acc[mt][nt][0]), "+f"(acc[mt][nt][1]),
                          "+f"(acc[mt][nt][2]), "+f"(acc[mt][nt][3])
                        : "r"(af[mt][0]), "r"(af[mt][1]),
                          "r"(af[mt][2]), "r"(af[mt][3]),
                          "r"(bf[nt][0]), "r"(bf[nt][1]));
                }
        }
        s_cur = (s_cur == 2) ? 0 : s_cur + 1;
        s_nxt = (s_nxt == 2) ? 0 : s_nxt + 1;
    }

    #pragma unroll
    for (int mt = 0; mt < 4; mt++) {
        #pragma unroll
        for (int half = 0; half < 2; half++) {
            int m = bm + wm * 64 + mt * 16 + r4 + half * 8;
            float* crow;
            if (REMAP) {
                int b = m / SEQ, s = m % SEQ;
                int orow = (s < TXT) ? (BATCH * IMG + b * TXT + s)
                                     : (b * IMG + (s - TXT));
                crow = C + (size_t)orow * N;
            } else {
                crow = C + (size_t)m * N;
            }
            #pragma unroll
            for (int nt = 0; nt < 4; nt++) {
                int n = bn + wn * 32 + nt * 8 + kc * 2;
                float2 v;
                v.x = acc[mt][nt][half * 2 + 0] + bias[n];
                v.y = acc[mt][nt][half * 2 + 1] + bias[n + 1];
                *(float2*)(crow + n) = v;
            }
        }
    }
}

// ---------------- 3. LayerNorm + partial RoPE (+ tf32 round q/k/v) ----------
__global__ void ln_rope_kernel(const float* __restrict__ cosb,
                               const float* __restrict__ sinb) {
    int gw   = (blockIdx.x * blockDim.x + threadIdx.x) >> 5;
    int lane = threadIdx.x & 31;
    if (gw >= BATCH * SEQ * HEADS) return;
    int h = gw % HEADS;
    int s = (gw / HEADS) % SEQ;
    int b = gw / (HEADS * SEQ);
    const float* base = g_qkv + (size_t)(b * SEQ + s) * (3 * INNER) + h * HDIM;
    size_t orow = ((size_t)(b * HEADS + h) * SEQ + s) * HDIM;
    bool img = (s >= TXT);
    float c4[4], s4[4];
    if (img) {
        float4 cv = *(const float4*)(cosb + (size_t)(s - TXT) * HDIM + lane * 4);
        float4 sv = *(const float4*)(sinb + (size_t)(s - TXT) * HDIM + lane * 4);
        c4[0] = cv.x; c4[1] = cv.y; c4[2] = cv.z; c4[3] = cv.w;
        s4[0] = sv.x; s4[1] = sv.y; s4[2] = sv.z; s4[3] = sv.w;
    }
    float sgn = (lane < 16) ? -1.f : 1.f;
    #pragma unroll
    for (int qk = 0; qk < 2; qk++) {
        float4 xv = *(const float4*)(base + qk * INNER + lane * 4);
        float x[4] = {xv.x, xv.y, xv.z, xv.w};
        float sum = x[0] + x[1] + x[2] + x[3];
        #pragma unroll
        for (int o = 16; o > 0; o >>= 1) sum += __shfl_xor_sync(0xffffffffu, sum, o);
        float mu = sum * (1.f / 128.f);
        float vs = 0.f;
        #pragma unroll
        for (int i = 0; i < 4; i++) { float d = x[i] - mu; vs += d * d; x[i] = d; }
        #pragma unroll
        for (int o = 16; o > 0; o >>= 1) vs += __shfl_xor_sync(0xffffffffu, vs, o);
        float inv = rsqrtf(vs * (1.f / 128.f) + 1e-5f);
        #pragma unroll
        for (int i = 0; i < 4; i++) x[i] *= inv;
        if (img) {
            float p[4];
            #pragma unroll
            for (int i = 0; i < 4; i++) p[i] = __shfl_xor_sync(0xffffffffu, x[i], 16);
            #pragma unroll
            for (int i = 0; i < 4; i++) x[i] = x[i] * c4[i] + sgn * p[i] * s4[i];
        }
        float4 ov = {rtf(x[0]), rtf(x[1]), rtf(x[2]), rtf(x[3])};
        float* dst = qk == 0 ? g_q : g_k;
        *(float4*)(dst + orow + lane * 4) = ov;
    }
    {
        float4 vv = *(const float4*)(base + 2 * INNER + lane * 4);
        vv.x = rtf(vv.x); vv.y = rtf(vv.y); vv.z = rtf(vv.z); vv.w = rtf(vv.w);
        *(float4*)(g_v + orow + lane * 4) = vv;
    }
}

// ---------------- 4. flash attention, tf32 tensor cores ----------------
#define KST 132
#define VST 136
#define PST 68
#define ATT_SMEM ((64 * KST + 64 * VST + 4 * 16 * PST) * sizeof(float))

__global__ __launch_bounds__(128)
void attn_tc_kernel() {
    extern __shared__ float sm[];
    float* Ks = sm;
    float* Vs = Ks + 64 * KST;
    float* Ps = Vs + 64 * VST;

    int qt = blockIdx.x, h = blockIdx.y, b = blockIdx.z;
    int tid = threadIdx.x, lane = tid & 31, wid = tid >> 5;
    size_t hb = (size_t)(b * HEADS + h) * SEQ * HDIM;
    const float* qb = g_q + hb + (size_t)qt * 64 * HDIM;
    const float* kb = g_k + hb;
    const float* vb = g_v + hb;

    for (int i = tid; i < 64 * 32; i += 128) {
        int r = i >> 5, c4 = i & 31;
        *(float4*)(Ks + r * KST + c4 * 4) =
            *(const float4*)(qb + (size_t)r * HDIM + c4 * 4);
    }
    __syncthreads();

    uint32_t qf[16][4];
    {
        const float* p0 = Ks + (wid * 16 + (lane >> 2)) * KST + (lane & 3);
        #pragma unroll
        for (int kk = 0; kk < 16; kk++) {
            qf[kk][0] = __float_as_uint(p0[kk * 8]);
            qf[kk][1] = __float_as_uint(p0[8 * KST + kk * 8]);
            qf[kk][2] = __float_as_uint(p0[kk * 8 + 4]);
            qf[kk][3] = __float_as_uint(p0[8 * KST + kk * 8 + 4]);
        }
    }
    __syncthreads();

    float oacc[16][4];
    #pragma unroll
    for (int nt = 0; nt < 16; nt++)
        #pragma unroll
        for (int r = 0; r < 4; r++) oacc[nt][r] = 0.f;

    float m_lo = -INFINITY, m_hi = -INFINITY, l_lo = 0.f, l_hi = 0.f;
    const float scale = 0.08838834764831845f;
    float* Pw = Ps + wid * 16 * PST;

    for (int kt = 0; kt < SEQ / 64; kt++) {
        for (int i = tid; i < 64 * 32; i += 128) {
            int r = i >> 5, c4 = i & 31;
            *(float4*)(Ks + r * KST + c4 * 4) =
                *(const float4*)(kb + (size_t)(kt * 64 + r) * HDIM + c4 * 4);
            *(float4*)(Vs + r * VST + c4 * 4) =
                *(const float4*)(vb + (size_t)(kt * 64 + r) * HDIM + c4 * 4);
        }
        __syncthreads();

        float sacc[8][4];
        #pragma unroll
        for (int nt = 0; nt < 8; nt++)
            #pragma unroll
            for (int r = 0; r < 4; r++) sacc[nt][r] = 0.f;

        #pragma unroll
        for (int kk = 0; kk < 16; kk++) {
            uint32_t bf[8][2];
            #pragma unroll
            for (int nt = 0; nt < 8; nt++) {
                const float* p = Ks + (nt * 8 + (lane >> 2)) * KST + kk * 8 + (lane & 3);
                bf[nt][0] = __float_as_uint(p[0]);
                bf[nt][1] = __float_as_uint(p[4]);
            }
            #pragma unroll
            for (int nt = 0; nt < 8; nt++) {
                asm volatile(
                    "mma.sync.aligned.m16n8k8.row.col.f32.tf32.tf32.f32 "
                    "{%0,%1,%2,%3}, {%4,%5,%6,%7}, {%8,%9}, {%0,%1,%2,%3};"
                    : "+f"(sacc[nt][0]), "+f"(sacc[nt][1]),
                      "+f"(sacc[nt][2]), "+f"(sacc[nt][3])
                    : "r"(qf[kk][0]), "r"(qf[kk][1]),
                      "r"(qf[kk][2]), "r"(qf[kk][3]),
                      "r"(bf[nt][0]), "r"(bf[nt][1]));
            }
        }

        float mx_lo = m_lo, mx_hi = m_hi;
        #pragma unroll
        for (int nt = 0; nt < 8; nt++) {
            sacc[nt][0] *= scale; sacc[nt][1] *= scale;
            sacc[nt][2] *= scale; sacc[nt][3] *= scale;
            mx_lo = fmaxf(mx_lo, fmaxf(sacc[nt][0], sacc[nt][1]));
            mx_hi = fmaxf(mx_hi, fmaxf(sacc[nt][2], sacc[nt][3]));
        }
        #pragma unroll
        for (int o = 1; o <= 2; o <<= 1) {
            mx_lo = fmaxf(mx_lo, __shfl_xor_sync(0xffffffffu, mx_lo, o));
            mx_hi = fmaxf(mx_hi, __shfl_xor_sync(0xffffffffu, mx_hi, o));
        }
        float f_lo = __expf(m_lo - mx_lo);
        float f_hi = __expf(m_hi - mx_hi);
        float sum_lo = 0.f, sum_hi = 0.f;
        #pragma unroll
        for (int nt = 0; nt < 8; nt++) {
            float p0 = __expf(sacc[nt][0] - mx_lo);
            float p1 = __expf(sacc[nt][1] - mx_lo);
            float p2 = __expf(sacc[nt][2] - mx_hi);
            float p3 = __expf(sacc[nt][3] - mx_hi);
            sum_lo += p0 + p1; sum_hi += p2 + p3;
            int col = nt * 8 + 2 * (lane & 3);
            float2 w0 = {rtf(p0), rtf(p1)};
            float2 w1 = {rtf(p2), rtf(p3)};
            *(float2*)(Pw + (lane >> 2) * PST + col) = w0;
            *(float2*)(Pw + ((lane >> 2) + 8) * PST + col) = w1;
        }
        #pragma unroll
        for (int o = 1; o <= 2; o <<= 1) {
            sum_lo += __shfl_xor_sync(0xffffffffu, sum_lo, o);
            sum_hi += __shfl_xor_sync(0xffffffffu, sum_hi, o);
        }
        l_lo = l_lo * f_lo + sum_lo;
        l_hi = l_hi * f_hi + sum_hi;
        m_lo = mx_lo; m_hi = mx_hi;
        __syncwarp();

        #pragma unroll
        for (int nt = 0; nt < 16; nt++) {
            oacc[nt][0] *= f_lo; oacc[nt][1] *= f_lo;
            oacc[nt][2] *= f_hi; oacc[nt][3] *= f_hi;
        }
        #pragma unroll
        for (int kk = 0; kk < 8; kk++) {
            uint32_t af[4];
            const float* pa = Pw + (lane >> 2) * PST + kk * 8 + (lane & 3);
            af[0] = __float_as_uint(pa[0]);
            af[1] = __float_as_uint(pa[8 * PST]);
            af[2] = __float_as_uint(pa[4]);
            af[3] = __float_as_uint(pa[8 * PST + 4]);
            const float* vrow0 = Vs + (kk * 8 + (lane & 3)) * VST + (lane >> 2);
            const float* vrow1 = vrow0 + 4 * VST;
            #pragma unroll
            for (int nt = 0; nt < 16; nt++) {
                uint32_t b0 = __float_as_uint(vrow0[nt * 8]);
                uint32_t b1 = __float_as_uint(vrow1[nt * 8]);
                asm volatile(
                    "mma.sync.aligned.m16n8k8.row.col.f32.tf32.tf32.f32 "
                    "{%0,%1,%2,%3}, {%4,%5,%6,%7}, {%8,%9}, {%0,%1,%2,%3};"
                    : "+f"(oacc[nt][0]), "+f"(oacc[nt][1]),
                      "+f"(oacc[nt][2]), "+f"(oacc[nt][3])
                    : "r"(af[0]), "r"(af[1]), "r"(af[2]), "r"(af[3]),
                      "r"(b0), "r"(b1));
            }
        }
        __syncthreads();
    }

    float inv_lo = 1.f / l_lo, inv_hi = 1.f / l_hi;
    int r = qt * 64 + wid * 16 + (lane >> 2);
    float* ob0 = g_o + ((size_t)b * SEQ + r) * INNER + h * HDIM;
    float* ob1 = g_o + ((size_t)b * SEQ + r + 8) * INNER + h * HDIM;
    #pragma unroll
    for (int nt = 0; nt < 16; nt++) {
        int col = nt * 8 + 2 * (lane & 3);
        float2 v0 = {rtf(oacc[nt][0] * inv_lo), rtf(oacc[nt][1] * inv_lo)};
        float2 v1 = {rtf(oacc[nt][2] * inv_hi), rtf(oacc[nt][3] * inv_hi)};
        *(float2*)(ob0 + col) = v0;
        *(float2*)(ob1 + col) = v1;
    }
}

// ---------------- host ----------------
extern "C" void kernel_launch(void* const* d_in, const int* in_sizes, int n_in,
                              void* d_out, int out_size) {
    const float* hid   = (const float*)d_in[0];
    const float* enc   = (const float*)d_in[1];
    const float* cosb  = (const float*)d_in[2];
    const float* sinb  = (const float*)d_in[3];
    const float* w_qkv = (const float*)d_in[4];
    const float* b_qkv = (const float*)d_in[5];
    const float* w_out = (const float*)d_in[6];
    const float* b_out = (const float*)d_in[7];
    float* out = (float*)d_out;

    float *xp, *qkvp, *op, *wqp, *wop;
    cudaGetSymbolAddress((void**)&xp,   g_x);
    cudaGetSymbolAddress((void**)&qkvp, g_qkv);
    cudaGetSymbolAddress((void**)&op,   g_o);
    cudaGetSymbolAddress((void**)&wqp,  g_wq);
    cudaGetSymbolAddress((void**)&wop,  g_wo);

    static bool attr_set = false;
    if (!attr_set) {
        cudaFuncSetAttribute(mma_gemm<0>, cudaFuncAttributeMaxDynamicSharedMemorySize,
                             (int)GEMM_SMEM);
        cudaFuncSetAttribute(mma_gemm<1>, cudaFuncAttributeMaxDynamicSharedMemorySize,
                             (int)GEMM_SMEM);
        cudaFuncSetAttribute(attn_tc_kernel, cudaFuncAttributeMaxDynamicSharedMemorySize,
                             (int)ATT_SMEM);
        attr_set = true;
    }

    // 0. round weights to tf32
    {
        int n4q = DMODEL * 3 * INNER / 4;
        cvtw_kernel<<<(n4q + 255) / 256, 256>>>(w_qkv, wqp, n4q);
        int n4o = INNER * DMODEL / 4;
        cvtw_kernel<<<(n4o + 255) / 256, 256>>>(w_out, wop, n4o);
    }
    // 1. concat (+round)
    {
        int total = ROWS * DMODEL / 4;
        concat_kernel<<<(total + 255) / 256, 256>>>(hid, enc);
    }
    // 2. qkv gemm
    {
        dim3 grid(3 * INNER / 128, ROWS / 128);
        mma_gemm<0><<<grid, 256, GEMM_SMEM>>>(ROWS, 3 * INNER, DMODEL,
                                              xp, wqp, b_qkv, qkvp);
    }
    // 3. LN + RoPE (+round)
    {
        int warps = BATCH * SEQ * HEADS;
        ln_rope_kernel<<<(warps + 7) / 8, 256>>>(cosb, sinb);
    }
    // 4. attention
    {
        dim3 grid(SEQ / 64, HEADS, BATCH);
        attn_tc_kernel<<<grid, 128, ATT_SMEM>>>();
    }
    // 5. out proj with row remap
    {
        dim3 grid(DMODEL / 128, ROWS / 128);
        mma_gemm<1><<<grid, 256, GEMM_SMEM>>>(ROWS, DMODEL, DMODEL,
                                              op, wop, b_out, out);
    }
}

// round 10
// speedup vs baseline: 2.0839x; 1.3668x over previous
#include <cuda_runtime.h>
#include <cuda_fp16.h>
#include <math.h>
#include <stdint.h>

#define HEADS  24
#define HDIM   128
#define BATCH  2
#define TXT    256
#define IMG    1024
#define SEQ    1280          // TXT + IMG
#define DMODEL 3072
#define INNER  3072          // HEADS*HDIM
#define ROWS   (BATCH*SEQ)   // 2560

// ---------------- scratch (static device globals: allowed) ----------------
__device__ __half g_xh [ROWS * DMODEL];           // fp16 concat input
__device__ float  g_qkv[ROWS * 3 * INNER];        // fp32 qkv gemm out
__device__ float  g_q  [BATCH * HEADS * SEQ * HDIM]; // tf32-rounded fp32
__device__ float  g_k  [BATCH * HEADS * SEQ * HDIM];
__device__ float  g_v  [BATCH * HEADS * SEQ * HDIM];
__device__ __half g_oh [ROWS * INNER];            // fp16 attn out
__device__ __half g_wqh[DMODEL * 3 * INNER];      // TRANSPOSED fp16 w_qkv [N][K]
__device__ __half g_woh[INNER * DMODEL];          // TRANSPOSED fp16 w_out [N][K]

__device__ __forceinline__ uint32_t f2tf32(float f) {
    uint32_t u;
    asm("cvt.rna.tf32.f32 %0, %1;" : "=r"(u) : "f"(f));
    return u;
}
__device__ __forceinline__ float rtf(float f) {
    return __uint_as_float(f2tf32(f));
}

// ---------------- 0. weight transpose + fp16 round ----------------
// src [K][N] fp32 row-major -> dst [N][K] fp16 row-major (K-major rows).
__global__ void transpose_h(const float* __restrict__ src,
                            __half* __restrict__ dst, int K, int N) {
    __shared__ float t[32][33];
    int kb = blockIdx.y * 32, nb = blockIdx.x * 32;
    int tx = threadIdx.x, ty = threadIdx.y;   // 32 x 8
    #pragma unroll
    for (int i = 0; i < 32; i += 8)
        t[ty + i][tx] = src[(size_t)(kb + ty + i) * N + nb + tx];
    __syncthreads();
    #pragma unroll
    for (int i = 0; i < 32; i += 8)
        dst[(size_t)(nb + ty + i) * K + kb + tx] = __float2half_rn(t[tx][ty + i]);
}

// ---------------- 1. concat -> fp16 ----------------
__global__ void concat_kernel(const float* __restrict__ hid,
                              const float* __restrict__ enc) {
    int idx = blockIdx.x * blockDim.x + threadIdx.x;   // 8-float chunk
    const int total = ROWS * DMODEL / 8;
    if (idx >= total) return;
    int row = idx / (DMODEL / 8);
    int c8  = idx % (DMODEL / 8);
    int b = row / SEQ, s = row % SEQ;
    const float4* src = (s < TXT)
        ? (const float4*)(enc + (size_t)(b * TXT + s) * DMODEL)
        : (const float4*)(hid + (size_t)(b * IMG + (s - TXT)) * DMODEL);
    float4 v0 = src[c8 * 2], v1 = src[c8 * 2 + 1];
    __half2 h[4];
    h[0] = __floats2half2_rn(v0.x, v0.y);
    h[1] = __floats2half2_rn(v0.z, v0.w);
    h[2] = __floats2half2_rn(v1.x, v1.y);
    h[3] = __floats2half2_rn(v1.z, v1.w);
    *(uint4*)(g_xh + (size_t)row * DMODEL + c8 * 8) = *(uint4*)h;
}

// ---------------- 2/5. FP16 tensor-core GEMM (m16n8k16) ----------------
// CTA 128x128, 256 threads = 8 warps, warp tile 64x32, BK=32 halves.
// A [M][K] fp16, BT [N][K] fp16 (both K-contiguous in smem).
// Half stride 72 -> word stride 36 (== 4 mod 32): conflict-free fragments.
#define HSTR 72                           // halves per smem row
#define WSTR 36                           // 4-byte words per smem row
#define TILE_BYTES (128 * HSTR * 2)       // 18432 B (A or B)
#define STAGE_BYTES (2 * TILE_BYTES)      // 36864 B
#define GEMM_SMEM ((size_t)2 * STAGE_BYTES)   // 73728 B

template <int REMAP>
__global__ __launch_bounds__(256, 2)
void mma_gemm(int M, int N, int K,
              const __half* __restrict__ A, const __half* __restrict__ BT,
              const float* __restrict__ bias, float* __restrict__ C) {
    extern __shared__ char sh[];
    int tid  = threadIdx.x;
    int lane = tid & 31, wid = tid >> 5;
    int wm = wid >> 2;        // 0..1 -> 64 rows
    int wn = wid & 3;         // 0..3 -> 32 cols
    int bm = blockIdx.y * 128;
    int bn = blockIdx.x * 128;
    int r4 = lane >> 2, kc = lane & 3;

    const __half* Ab = A + (size_t)bm * K;
    const __half* Bb = BT + (size_t)bn * K;

    float acc[4][4][4];
    #pragma unroll
    for (int i = 0; i < 4; i++)
        #pragma unroll
        for (int j = 0; j < 4; j++)
            #pragma unroll
            for (int r = 0; r < 4; r++) acc[i][j][r] = 0.f;

    auto copy_tile = [&](int k0, int s) {
        char* As = sh + s * STAGE_BYTES;
        char* Bs = As + TILE_BYTES;
        #pragma unroll
        for (int i = 0; i < 2; i++) {
            int idx = tid + i * 256;          // 0..511
            int row = idx >> 2, c = idx & 3;  // 128 rows x 4 chunks(16B=8 halves)
            uint32_t da = (uint32_t)__cvta_generic_to_shared(
                As + row * (HSTR * 2) + c * 16);
            asm volatile("cp.async.cg.shared.global [%0], [%1], 16;"
                         :: "r"(da), "l"(Ab + (size_t)row * K + k0 + c * 8));
            uint32_t db = (uint32_t)__cvta_generic_to_shared(
                Bs + row * (HSTR * 2) + c * 16);
            asm volatile("cp.async.cg.shared.global [%0], [%1], 16;"
                         :: "r"(db), "l"(Bb + (size_t)row * K + k0 + c * 8));
        }
        asm volatile("cp.async.commit_group;");
    };

    int nK = K / 32;
    copy_tile(0, 0);

    for (int kt = 0; kt < nK; kt++) {
        asm volatile("cp.async.wait_group 0;");
        __syncthreads();
        if (kt + 1 < nK) copy_tile((kt + 1) * 32, (kt + 1) & 1);

        const uint32_t* Aw = (const uint32_t*)(sh + (kt & 1) * STAGE_BYTES);
        const uint32_t* Bw = (const uint32_t*)(sh + (kt & 1) * STAGE_BYTES + TILE_BYTES);

        #pragma unroll
        for (int kk = 0; kk < 2; kk++) {          // two k16 steps per BK=32
            uint32_t af[4][4], bf[4][2];
            #pragma unroll
            for (int mt = 0; mt < 4; mt++) {
                int base = (wm * 64 + mt * 16 + r4) * WSTR + kk * 8 + kc;
                af[mt][0] = Aw[base];
                af[mt][1] = Aw[base + 8 * WSTR];
                af[mt][2] = Aw[base + 4];
                af[mt][3] = Aw[base + 8 * WSTR + 4];
            }
            #pragma unroll
            for (int nt = 0; nt < 4; nt++) {
                int base = (wn * 32 + nt * 8 + r4) * WSTR + kk * 8 + kc;
                bf[nt][0] = Bw[base];
                bf[nt][1] = Bw[base + 4];
            }
            #pragma unroll
            for (int mt = 0; mt < 4; mt++)
                #pragma unroll
                for (int nt = 0; nt < 4; nt++) {
                    asm volatile(
                        "mma.sync.aligned.m16n8k16.row.col.f32.f16.f16.f32 "
                        "{%0,%1,%2,%3}, {%4,%5,%6,%7}, {%8,%9}, {%0,%1,%2,%3};"
                        : "+f"(acc[mt][nt][0]), "+f"(acc[mt][nt][1]),
                          "+f"(acc[mt][nt][2]), "+f"(acc[mt][nt][3])
                        : "r"(af[mt][0]), "r"(af[mt][1]),
                          "r"(af[mt][2]), "r"(af[mt][3]),
                          "r"(bf[nt][0]), "r"(bf[nt][1]));
                }
        }
        __syncthreads();
    }

    #pragma unroll
    for (int mt = 0; mt < 4; mt++) {
        #pragma unroll
        for (int half_ = 0; half_ < 2; half_++) {
            int m = bm + wm * 64 + mt * 16 + r4 + half_ * 8;
            float* crow;
            if (REMAP) {
                int b = m / SEQ, s = m % SEQ;
                int orow = (s < TXT) ? (BATCH * IMG + b * TXT + s)
                                     : (b * IMG + (s - TXT));
                crow = C + (size_t)orow * N;
            } else {
                crow = C + (size_t)m * N;
            }
            #pragma unroll
            for (int nt = 0; nt < 4; nt++) {
                int n = bn + wn * 32 + nt * 8 + kc * 2;
                float2 v;
                v.x = acc[mt][nt][half_ * 2 + 0] + bias[n];
                v.y = acc[mt][nt][half_ * 2 + 1] + bias[n + 1];
                *(float2*)(crow + n) = v;
            }
        }
    }
}

// ---------------- 3. LayerNorm + partial RoPE (+ tf32 round q/k/v) ----------
__global__ void ln_rope_kernel(const float* __restrict__ cosb,
                               const float* __restrict__ sinb) {
    int gw   = (blockIdx.x * blockDim.x + threadIdx.x) >> 5;
    int lane = threadIdx.x & 31;
    if (gw >= BATCH * SEQ * HEADS) return;
    int h = gw % HEADS;
    int s = (gw / HEADS) % SEQ;
    int b = gw / (HEADS * SEQ);
    const float* base = g_qkv + (size_t)(b * SEQ + s) * (3 * INNER) + h * HDIM;
    size_t orow = ((size_t)(b * HEADS + h) * SEQ + s) * HDIM;
    bool img = (s >= TXT);
    float c4[4], s4[4];
    if (img) {
        float4 cv = *(const float4*)(cosb + (size_t)(s - TXT) * HDIM + lane * 4);
        float4 sv = *(const float4*)(sinb + (size_t)(s - TXT) * HDIM + lane * 4);
        c4[0] = cv.x; c4[1] = cv.y; c4[2] = cv.z; c4[3] = cv.w;
        s4[0] = sv.x; s4[1] = sv.y; s4[2] = sv.z; s4[3] = sv.w;
    }
    float sgn = (lane < 16) ? -1.f : 1.f;
    #pragma unroll
    for (int qk = 0; qk < 2; qk++) {
        float4 xv = *(const float4*)(base + qk * INNER + lane * 4);
        float x[4] = {xv.x, xv.y, xv.z, xv.w};
        float sum = x[0] + x[1] + x[2] + x[3];
        #pragma unroll
        for (int o = 16; o > 0; o >>= 1) sum += __shfl_xor_sync(0xffffffffu, sum, o);
        float mu = sum * (1.f / 128.f);
        float vs = 0.f;
        #pragma unroll
        for (int i = 0; i < 4; i++) { float d = x[i] - mu; vs += d * d; x[i] = d; }
        #pragma unroll
        for (int o = 16; o > 0; o >>= 1) vs += __shfl_xor_sync(0xffffffffu, vs, o);
        float inv = rsqrtf(vs * (1.f / 128.f) + 1e-5f);
        #pragma unroll
        for (int i = 0; i < 4; i++) x[i] *= inv;
        if (img) {
            float p[4];
            #pragma unroll
            for (int i = 0; i < 4; i++) p[i] = __shfl_xor_sync(0xffffffffu, x[i], 16);
            #pragma unroll
            for (int i = 0; i < 4; i++) x[i] = x[i] * c4[i] + sgn * p[i] * s4[i];
        }
        float4 ov = {rtf(x[0]), rtf(x[1]), rtf(x[2]), rtf(x[3])};
        float* dst = qk == 0 ? g_q : g_k;
        *(float4*)(dst + orow + lane * 4) = ov;
    }
    {
        float4 vv = *(const float4*)(base + 2 * INNER + lane * 4);
        vv.x = rtf(vv.x); vv.y = rtf(vv.y); vv.z = rtf(vv.z); vv.w = rtf(vv.w);
        *(float4*)(g_v + orow + lane * 4) = vv;
    }
}

// ---------------- 4. flash attention, tf32 tensor cores ----------------
#define KST 132
#define VST 136
#define PST 68
#define ATT_SMEM ((64 * KST + 64 * VST + 4 * 16 * PST) * sizeof(float))

__global__ __launch_bounds__(128)
void attn_tc_kernel() {
    extern __shared__ float sm[];
    float* Ks = sm;
    float* Vs = Ks + 64 * KST;
    float* Ps = Vs + 64 * VST;

    int qt = blockIdx.x, h = blockIdx.y, b = blockIdx.z;
    int tid = threadIdx.x, lane = tid & 31, wid = tid >> 5;
    size_t hb = (size_t)(b * HEADS + h) * SEQ * HDIM;
    const float* qb = g_q + hb + (size_t)qt * 64 * HDIM;
    const float* kb = g_k + hb;
    const float* vb = g_v + hb;

    for (int i = tid; i < 64 * 32; i += 128) {
        int r = i >> 5, c4 = i & 31;
        *(float4*)(Ks + r * KST + c4 * 4) =
            *(const float4*)(qb + (size_t)r * HDIM + c4 * 4);
    }
    __syncthreads();

    uint32_t qf[16][4];
    {
        const float* p0 = Ks + (wid * 16 + (lane >> 2)) * KST + (lane & 3);
        #pragma unroll
        for (int kk = 0; kk < 16; kk++) {
            qf[kk][0] = __float_as_uint(p0[kk * 8]);
            qf[kk][1] = __float_as_uint(p0[8 * KST + kk * 8]);
            qf[kk][2] = __float_as_uint(p0[kk * 8 + 4]);
            qf[kk][3] = __float_as_uint(p0[8 * KST + kk * 8 + 4]);
        }
    }
    __syncthreads();

    float oacc[16][4];
    #pragma unroll
    for (int nt = 0; nt < 16; nt++)
        #pragma unroll
        for (int r = 0; r < 4; r++) oacc[nt][r] = 0.f;

    float m_lo = -INFINITY, m_hi = -INFINITY, l_lo = 0.f, l_hi = 0.f;
    const float scale = 0.08838834764831845f;
    float* Pw = Ps + wid * 16 * PST;

    for (int kt = 0; kt < SEQ / 64; kt++) {
        for (int i = tid; i < 64 * 32; i += 128) {
            int r = i >> 5, c4 = i & 31;
            *(float4*)(Ks + r * KST + c4 * 4) =
                *(const float4*)(kb + (size_t)(kt * 64 + r) * HDIM + c4 * 4);
            *(float4*)(Vs + r * VST + c4 * 4) =
                *(const float4*)(vb + (size_t)(kt * 64 + r) * HDIM + c4 * 4);
        }
        __syncthreads();

        float sacc[8][4];
        #pragma unroll
        for (int nt = 0; nt < 8; nt++)
            #pragma unroll
            for (int r = 0; r < 4; r++) sacc[nt][r] = 0.f;

        #pragma unroll
        for (int kk = 0; kk < 16; kk++) {
            uint32_t bf[8][2];
            #pragma unroll
            for (int nt = 0; nt < 8; nt++) {
                const float* p = Ks + (nt * 8 + (lane >> 2)) * KST + kk * 8 + (lane & 3);
                bf[nt][0] = __float_as_uint(p[0]);
                bf[nt][1] = __float_as_uint(p[4]);
            }
            #pragma unroll
            for (int nt = 0; nt < 8; nt++) {
                asm volatile(
                    "mma.sync.aligned.m16n8k8.row.col.f32.tf32.tf32.f32 "
                    "{%0,%1,%2,%3}, {%4,%5,%6,%7}, {%8,%9}, {%0,%1,%2,%3};"
                    : "+f"(sacc[nt][0]), "+f"(sacc[nt][1]),
                      "+f"(sacc[nt][2]), "+f"(sacc[nt][3])
                    : "r"(qf[kk][0]), "r"(qf[kk][1]),
                      "r"(qf[kk][2]), "r"(qf[kk][3]),
                      "r"(bf[nt][0]), "r"(bf[nt][1]));
            }
        }

        float mx_lo = m_lo, mx_hi = m_hi;
        #pragma unroll
        for (int nt = 0; nt < 8; nt++) {
            sacc[nt][0] *= scale; sacc[nt][1] *= scale;
            sacc[nt][2] *= scale; sacc[nt][3] *= scale;
            mx_lo = fmaxf(mx_lo, fmaxf(sacc[nt][0], sacc[nt][1]));
            mx_hi = fmaxf(mx_hi, fmaxf(sacc[nt][2], sacc[nt][3]));
        }
        #pragma unroll
        for (int o = 1; o <= 2; o <<= 1) {
            mx_lo = fmaxf(mx_lo, __shfl_xor_sync(0xffffffffu, mx_lo, o));
            mx_hi = fmaxf(mx_hi, __shfl_xor_sync(0xffffffffu, mx_hi, o));
        }
        float f_lo = __expf(m_lo - mx_lo);
        float f_hi = __expf(m_hi - mx_hi);
        float sum_lo = 0.f, sum_hi = 0.f;
        #pragma unroll
        for (int nt = 0; nt < 8; nt++) {
            float p0 = __expf(sacc[nt][0] - mx_lo);
            float p1 = __expf(sacc[nt][1] - mx_lo);
            float p2 = __expf(sacc[nt][2] - mx_hi);
            float p3 = __expf(sacc[nt][3] - mx_hi);
            sum_lo += p0 + p1; sum_hi += p2 + p3;
            int col = nt * 8 + 2 * (lane & 3);
            float2 w0 = {rtf(p0), rtf(p1)};
            float2 w1 = {rtf(p2), rtf(p3)};
            *(float2*)(Pw + (lane >> 2) * PST + col) = w0;
            *(float2*)(Pw + ((lane >> 2) + 8) * PST + col) = w1;
        }
        #pragma unroll
        for (int o = 1; o <= 2; o <<= 1) {
            sum_lo += __shfl_xor_sync(0xffffffffu, sum_lo, o);
            sum_hi += __shfl_xor_sync(0xffffffffu, sum_hi, o);
        }
        l_lo = l_lo * f_lo + sum_lo;
        l_hi = l_hi * f_hi + sum_hi;
        m_lo = mx_lo; m_hi = mx_hi;
        __syncwarp();

        #pragma unroll
        for (int nt = 0; nt < 16; nt++) {
            oacc[nt][0] *= f_lo; oacc[nt][1] *= f_lo;
            oacc[nt][2] *= f_hi; oacc[nt][3] *= f_hi;
        }
        #pragma unroll
        for (int kk = 0; kk < 8; kk++) {
            uint32_t af[4];
            const float* pa = Pw + (lane >> 2) * PST + kk * 8 + (lane & 3);
            af[0] = __float_as_uint(pa[0]);
            af[1] = __float_as_uint(pa[8 * PST]);
            af[2] = __float_as_uint(pa[4]);
            af[3] = __float_as_uint(pa[8 * PST + 4]);
            const float* vrow0 = Vs + (kk * 8 + (lane & 3)) * VST + (lane >> 2);
            const float* vrow1 = vrow0 + 4 * VST;
            #pragma unroll
            for (int nt = 0; nt < 16; nt++) {
                uint32_t b0 = __float_as_uint(vrow0[nt * 8]);
                uint32_t b1 = __float_as_uint(vrow1[nt * 8]);
                asm volatile(
                    "mma.sync.aligned.m16n8k8.row.col.f32.tf32.tf32.f32 "
                    "{%0,%1,%2,%3}, {%4,%5,%6,%7}, {%8,%9}, {%0,%1,%2,%3};"
                    : "+f"(oacc[nt][0]), "+f"(oacc[nt][1]),
                      "+f"(oacc[nt][2]), "+f"(oacc[nt][3])
                    : "r"(af[0]), "r"(af[1]), "r"(af[2]), "r"(af[3]),
                      "r"(b0), "r"(b1));
            }
        }
        __syncthreads();
    }

    // epilogue: normalize, convert to fp16 (g_oh feeds the out-proj GEMM)
    float inv_lo = 1.f / l_lo, inv_hi = 1.f / l_hi;
    int r = qt * 64 + wid * 16 + (lane >> 2);
    __half* ob0 = g_oh + ((size_t)b * SEQ + r) * INNER + h * HDIM;
    __half* ob1 = g_oh + ((size_t)b * SEQ + r + 8) * INNER + h * HDIM;
    #pragma unroll
    for (int nt = 0; nt < 16; nt++) {
        int col = nt * 8 + 2 * (lane & 3);
        __half2 v0 = __floats2half2_rn(oacc[nt][0] * inv_lo, oacc[nt][1] * inv_lo);
        __half2 v1 = __floats2half2_rn(oacc[nt][2] * inv_hi, oacc[nt][3] * inv_hi);
        *(__half2*)(ob0 + col) = v0;
        *(__half2*)(ob1 + col) = v1;
    }
}

// ---------------- host ----------------
extern "C" void kernel_launch(void* const* d_in, const int* in_sizes, int n_in,
                              void* d_out, int out_size) {
    const float* hid   = (const float*)d_in[0];
    const float* enc   = (const float*)d_in[1];
    const float* cosb  = (const float*)d_in[2];
    const float* sinb  = (const float*)d_in[3];
    const float* w_qkv = (const float*)d_in[4];
    const float* b_qkv = (const float*)d_in[5];
    const float* w_out = (const float*)d_in[6];
    const float* b_out = (const float*)d_in[7];
    float* out = (float*)d_out;

    __half *xhp, *ohp, *wqhp, *wohp;
    float *qkvp;
    cudaGetSymbolAddress((void**)&xhp,  g_xh);
    cudaGetSymbolAddress((void**)&qkvp, g_qkv);
    cudaGetSymbolAddress((void**)&ohp,  g_oh);
    cudaGetSymbolAddress((void**)&wqhp, g_wqh);
    cudaGetSymbolAddress((void**)&wohp, g_woh);

    static bool attr_set = false;
    if (!attr_set) {
        cudaFuncSetAttribute(mma_gemm<0>, cudaFuncAttributeMaxDynamicSharedMemorySize,
                             (int)GEMM_SMEM);
        cudaFuncSetAttribute(mma_gemm<1>, cudaFuncAttributeMaxDynamicSharedMemorySize,
                             (int)GEMM_SMEM);
        cudaFuncSetAttribute(attn_tc_kernel, cudaFuncAttributeMaxDynamicSharedMemorySize,
                             (int)ATT_SMEM);
        attr_set = true;
    }

    // 0. transpose + round weights: W[K][N] fp32 -> WT[N][K] fp16
    {
        dim3 blk(32, 8);
        dim3 gq(3 * INNER / 32, DMODEL / 32);
        transpose_h<<<gq, blk>>>(w_qkv, wqhp, DMODEL, 3 * INNER);
        dim3 go(DMODEL / 32, INNER / 32);
        transpose_h<<<go, blk>>>(w_out, wohp, INNER, DMODEL);
    }
    // 1. concat -> fp16
    {
        int total = ROWS * DMODEL / 8;
        concat_kernel<<<(total + 255) / 256, 256>>>(hid, enc);
    }
    // 2. qkv gemm (fp16 HMMA)
    {
        dim3 grid(3 * INNER / 128, ROWS / 128);
        mma_gemm<0><<<grid, 256, GEMM_SMEM>>>(ROWS, 3 * INNER, DMODEL,
                                              xhp, wqhp, b_qkv, qkvp);
    }
    // 3. LN + RoPE (+tf32 round)
    {
        int warps = BATCH * SEQ * HEADS;
        ln_rope_kernel<<<(warps + 7) / 8, 256>>>(cosb, sinb);
    }
    // 4. attention (tf32, unchanged)
    {
        dim3 grid(SEQ / 64, HEADS, BATCH);
        attn_tc_kernel<<<grid, 128, ATT_SMEM>>>();
    }
    // 5. out proj with row remap (fp16 HMMA)
    {
        dim3 grid(DMODEL / 128, ROWS / 128);
        mma_gemm<1><<<grid, 256, GEMM_SMEM>>>(ROWS, DMODEL, DMODEL,
                                              ohp, wohp, b_out, out);
    }
}

// round 11
// speedup vs baseline: 2.5360x; 1.2170x over previous
#include <cuda_runtime.h>
#include <cuda_fp16.h>
#include <math.h>
#include <stdint.h>

#define HEADS  24
#define HDIM   128
#define BATCH  2
#define TXT    256
#define IMG    1024
#define SEQ    1280          // TXT + IMG
#define DMODEL 3072
#define INNER  3072          // HEADS*HDIM
#define ROWS   (BATCH*SEQ)   // 2560

// ---------------- scratch (static device globals: allowed) ----------------
__device__ __half g_xh [ROWS * DMODEL];           // fp16 concat input
__device__ float  g_qkv[ROWS * 3 * INNER];        // fp32 qkv gemm out
__device__ __half g_qh [BATCH * HEADS * SEQ * HDIM]; // fp16 q (post LN/RoPE)
__device__ __half g_kh [BATCH * HEADS * SEQ * HDIM];
__device__ __half g_vh [BATCH * HEADS * SEQ * HDIM];
__device__ __half g_oh [ROWS * INNER];            // fp16 attn out
__device__ __half g_wqh[DMODEL * 3 * INNER];      // TRANSPOSED fp16 w_qkv [N][K]
__device__ __half g_woh[INNER * DMODEL];          // TRANSPOSED fp16 w_out [N][K]

// ---------------- mma / ldmatrix helpers ----------------
#define LDSM_X4(R0, R1, R2, R3, A) \
    asm volatile("ldmatrix.sync.aligned.m8n8.x4.shared.b16 {%0,%1,%2,%3}, [%4];" \
                 : "=r"(R0), "=r"(R1), "=r"(R2), "=r"(R3) : "r"(A))
#define LDSM_X4_T(R0, R1, R2, R3, A) \
    asm volatile("ldmatrix.sync.aligned.m8n8.x4.trans.shared.b16 {%0,%1,%2,%3}, [%4];" \
                 : "=r"(R0), "=r"(R1), "=r"(R2), "=r"(R3) : "r"(A))
#define HMMA(D, A0, A1, A2, A3, B0, B1) \
    asm volatile("mma.sync.aligned.m16n8k16.row.col.f32.f16.f16.f32 " \
                 "{%0,%1,%2,%3}, {%4,%5,%6,%7}, {%8,%9}, {%0,%1,%2,%3};" \
                 : "+f"((D)[0]), "+f"((D)[1]), "+f"((D)[2]), "+f"((D)[3]) \
                 : "r"(A0), "r"(A1), "r"(A2), "r"(A3), "r"(B0), "r"(B1))

// ---------------- 0. weight transpose + fp16 round ----------------
__global__ void transpose_h(const float* __restrict__ src,
                            __half* __restrict__ dst, int K, int N) {
    __shared__ float t[32][33];
    int kb = blockIdx.y * 32, nb = blockIdx.x * 32;
    int tx = threadIdx.x, ty = threadIdx.y;   // 32 x 8
    #pragma unroll
    for (int i = 0; i < 32; i += 8)
        t[ty + i][tx] = src[(size_t)(kb + ty + i) * N + nb + tx];
    __syncthreads();
    #pragma unroll
    for (int i = 0; i < 32; i += 8)
        dst[(size_t)(nb + ty + i) * K + kb + tx] = __float2half_rn(t[tx][ty + i]);
}

// ---------------- 1. concat -> fp16 ----------------
__global__ void concat_kernel(const float* __restrict__ hid,
                              const float* __restrict__ enc) {
    int idx = blockIdx.x * blockDim.x + threadIdx.x;   // 8-float chunk
    const int total = ROWS * DMODEL / 8;
    if (idx >= total) return;
    int row = idx / (DMODEL / 8);
    int c8  = idx % (DMODEL / 8);
    int b = row / SEQ, s = row % SEQ;
    const float4* src = (s < TXT)
        ? (const float4*)(enc + (size_t)(b * TXT + s) * DMODEL)
        : (const float4*)(hid + (size_t)(b * IMG + (s - TXT)) * DMODEL);
    float4 v0 = src[c8 * 2], v1 = src[c8 * 2 + 1];
    __half2 h[4];
    h[0] = __floats2half2_rn(v0.x, v0.y);
    h[1] = __floats2half2_rn(v0.z, v0.w);
    h[2] = __floats2half2_rn(v1.x, v1.y);
    h[3] = __floats2half2_rn(v1.z, v1.w);
    *(uint4*)(g_xh + (size_t)row * DMODEL + c8 * 8) = *(uint4*)h;
}

// ---------------- 2/5. FP16 GEMM (m16n8k16, ldmatrix) ----------------
// CTA 128x128, 256 threads = 8 warps, warp tile 64x32, BK=32 halves.
// Row stride 144B = 36 words (== 4 mod 32): ldmatrix conflict-free.
#define HSTR 72                           // halves per smem row
#define ROWB 144                          // bytes per smem row
#define TILE_BYTES (128 * ROWB)           // 18432 B
#define STAGE_BYTES (2 * TILE_BYTES)      // 36864 B
#define GEMM_SMEM ((size_t)2 * STAGE_BYTES)   // 73728 B

template <int REMAP>
__global__ __launch_bounds__(256, 2)
void mma_gemm(int M, int N, int K,
              const __half* __restrict__ A, const __half* __restrict__ BT,
              const float* __restrict__ bias, float* __restrict__ C) {
    extern __shared__ char sh[];
    uint32_t sh_u32 = (uint32_t)__cvta_generic_to_shared(sh);
    int tid  = threadIdx.x;
    int lane = tid & 31, wid = tid >> 5;
    int wm = wid >> 2;        // 0..1 -> 64 rows
    int wn = wid & 3;         // 0..3 -> 32 cols
    int bm = blockIdx.y * 128;
    int bn = blockIdx.x * 128;
    int r4 = lane >> 2, kc = lane & 3;

    const __half* Ab = A + (size_t)bm * K;
    const __half* Bb = BT + (size_t)bn * K;

    // per-thread ldmatrix base offsets (within a stage)
    uint32_t a_off = (uint32_t)((wm * 64 + (lane & 15)) * ROWB + (lane >> 4) * 16);
    uint32_t b_off = (uint32_t)(TILE_BYTES + (wn * 32 + (lane & 15)) * ROWB
                                + (lane >> 4) * 16);

    float acc[4][4][4];
    #pragma unroll
    for (int i = 0; i < 4; i++)
        #pragma unroll
        for (int j = 0; j < 4; j++)
            #pragma unroll
            for (int r = 0; r < 4; r++) acc[i][j][r] = 0.f;

    auto copy_tile = [&](int k0, int s) {
        char* As = sh + s * STAGE_BYTES;
        char* Bs = As + TILE_BYTES;
        #pragma unroll
        for (int i = 0; i < 2; i++) {
            int idx = tid + i * 256;          // 0..511
            int row = idx >> 2, c = idx & 3;  // 128 rows x 4 16B-chunks
            uint32_t da = (uint32_t)__cvta_generic_to_shared(
                As + row * ROWB + c * 16);
            asm volatile("cp.async.cg.shared.global [%0], [%1], 16;"
                         :: "r"(da), "l"(Ab + (size_t)row * K + k0 + c * 8));
            uint32_t db = (uint32_t)__cvta_generic_to_shared(
                Bs + row * ROWB + c * 16);
            asm volatile("cp.async.cg.shared.global [%0], [%1], 16;"
                         :: "r"(db), "l"(Bb + (size_t)row * K + k0 + c * 8));
        }
        asm volatile("cp.async.commit_group;");
    };

    int nK = K / 32;
    copy_tile(0, 0);

    for (int kt = 0; kt < nK; kt++) {
        asm volatile("cp.async.wait_group 0;");
        __syncthreads();
        if (kt + 1 < nK) copy_tile((kt + 1) * 32, (kt + 1) & 1);

        uint32_t sb = sh_u32 + (kt & 1) * STAGE_BYTES;

        #pragma unroll
        for (int kk = 0; kk < 2; kk++) {          // two k16 steps per BK=32
            uint32_t af[4][4], bf[4][2];
            #pragma unroll
            for (int mt = 0; mt < 4; mt++)
                LDSM_X4(af[mt][0], af[mt][1], af[mt][2], af[mt][3],
                        sb + a_off + mt * (16 * ROWB) + kk * 32);
            #pragma unroll
            for (int g = 0; g < 2; g++) {
                uint32_t r0, r1, r2, r3;
                LDSM_X4(r0, r1, r2, r3,
                        sb + b_off + g * (16 * ROWB) + kk * 32);
                bf[2 * g][0] = r0; bf[2 * g][1] = r2;       // rows n0-7
                bf[2 * g + 1][0] = r1; bf[2 * g + 1][1] = r3; // rows n8-15
            }
            #pragma unroll
            for (int mt = 0; mt < 4; mt++)
                #pragma unroll
                for (int nt = 0; nt < 4; nt++)
                    HMMA(acc[mt][nt], af[mt][0], af[mt][1], af[mt][2], af[mt][3],
                         bf[nt][0], bf[nt][1]);
        }
        __syncthreads();
    }

    #pragma unroll
    for (int mt = 0; mt < 4; mt++) {
        #pragma unroll
        for (int half_ = 0; half_ < 2; half_++) {
            int m = bm + wm * 64 + mt * 16 + r4 + half_ * 8;
            float* crow;
            if (REMAP) {
                int b = m / SEQ, s = m % SEQ;
                int orow = (s < TXT) ? (BATCH * IMG + b * TXT + s)
                                     : (b * IMG + (s - TXT));
                crow = C + (size_t)orow * N;
            } else {
                crow = C + (size_t)m * N;
            }
            #pragma unroll
            for (int nt = 0; nt < 4; nt++) {
                int n = bn + wn * 32 + nt * 8 + kc * 2;
                float2 v;
                v.x = acc[mt][nt][half_ * 2 + 0] + bias[n];
                v.y = acc[mt][nt][half_ * 2 + 1] + bias[n + 1];
                *(float2*)(crow + n) = v;
            }
        }
    }
}

// ---------------- 3. LayerNorm + partial RoPE -> fp16 q/k/v ----------------
__global__ void ln_rope_kernel(const float* __restrict__ cosb,
                               const float* __restrict__ sinb) {
    int gw   = (blockIdx.x * blockDim.x + threadIdx.x) >> 5;
    int lane = threadIdx.x & 31;
    if (gw >= BATCH * SEQ * HEADS) return;
    int h = gw % HEADS;
    int s = (gw / HEADS) % SEQ;
    int b = gw / (HEADS * SEQ);
    const float* base = g_qkv + (size_t)(b * SEQ + s) * (3 * INNER) + h * HDIM;
    size_t orow = ((size_t)(b * HEADS + h) * SEQ + s) * HDIM;
    bool img = (s >= TXT);
    float c4[4], s4[4];
    if (img) {
        float4 cv = *(const float4*)(cosb + (size_t)(s - TXT) * HDIM + lane * 4);
        float4 sv = *(const float4*)(sinb + (size_t)(s - TXT) * HDIM + lane * 4);
        c4[0] = cv.x; c4[1] = cv.y; c4[2] = cv.z; c4[3] = cv.w;
        s4[0] = sv.x; s4[1] = sv.y; s4[2] = sv.z; s4[3] = sv.w;
    }
    float sgn = (lane < 16) ? -1.f : 1.f;
    #pragma unroll
    for (int qk = 0; qk < 2; qk++) {
        float4 xv = *(const float4*)(base + qk * INNER + lane * 4);
        float x[4] = {xv.x, xv.y, xv.z, xv.w};
        float sum = x[0] + x[1] + x[2] + x[3];
        #pragma unroll
        for (int o = 16; o > 0; o >>= 1) sum += __shfl_xor_sync(0xffffffffu, sum, o);
        float mu = sum * (1.f / 128.f);
        float vs = 0.f;
        #pragma unroll
        for (int i = 0; i < 4; i++) { float d = x[i] - mu; vs += d * d; x[i] = d; }
        #pragma unroll
        for (int o = 16; o > 0; o >>= 1) vs += __shfl_xor_sync(0xffffffffu, vs, o);
        float inv = rsqrtf(vs * (1.f / 128.f) + 1e-5f);
        #pragma unroll
        for (int i = 0; i < 4; i++) x[i] *= inv;
        if (img) {
            float p[4];
            #pragma unroll
            for (int i = 0; i < 4; i++) p[i] = __shfl_xor_sync(0xffffffffu, x[i], 16);
            #pragma unroll
            for (int i = 0; i < 4; i++) x[i] = x[i] * c4[i] + sgn * p[i] * s4[i];
        }
        __half2 hv[2];
        hv[0] = __floats2half2_rn(x[0], x[1]);
        hv[1] = __floats2half2_rn(x[2], x[3]);
        __half* dst = qk == 0 ? g_qh : g_kh;
        *(uint2*)(dst + orow + lane * 4) = *(uint2*)hv;
    }
    {
        float4 vv = *(const float4*)(base + 2 * INNER + lane * 4);
        __half2 hv[2];
        hv[0] = __floats2half2_rn(vv.x, vv.y);
        hv[1] = __floats2half2_rn(vv.z, vv.w);
        *(uint2*)(g_vh + orow + lane * 4) = *(uint2*)hv;
    }
}

// ---------------- 4. flash attention, fp16 tensor cores ----------------
// 128 threads / 4 warps; q-tile 64 (16 rows/warp), kv-tile 64, D=128.
// K/Q/V smem rows: 136 halves = 272 B (68 words == 4 mod 32): LDSM-safe.
// P per-warp: 72 halves = 144 B rows: LDSM-safe.
#define KSTH 136
#define PSTH 72
#define ATT_SMEM ((2 * 64 * KSTH + 4 * 16 * PSTH) * 2)   // 44032 B

__global__ __launch_bounds__(128)
void attn_tc_kernel() {
    extern __shared__ __half smh[];
    __half* Ks = smh;                       // Q staging, then K tiles
    __half* Vs = Ks + 64 * KSTH;
    __half* Ps = Vs + 64 * KSTH;

    int qt = blockIdx.x, h = blockIdx.y, b = blockIdx.z;
    int tid = threadIdx.x, lane = tid & 31, wid = tid >> 5;
    size_t hb = (size_t)(b * HEADS + h) * SEQ * HDIM;
    const __half* qb = g_qh + hb + (size_t)qt * 64 * HDIM;
    const __half* kb = g_kh + hb;
    const __half* vb = g_vh + hb;

    uint32_t ks_u32 = (uint32_t)__cvta_generic_to_shared(Ks);
    uint32_t vs_u32 = (uint32_t)__cvta_generic_to_shared(Vs);
    __half* Pw = Ps + wid * 16 * PSTH;
    uint32_t pw_u32 = (uint32_t)__cvta_generic_to_shared(Pw);

    // ---- stage Q -> smem, extract fragments via ldmatrix ----
    for (int i = tid; i < 64 * 16; i += 128) {
        int r = i >> 4, c = i & 15;
        *(uint4*)(Ks + r * KSTH + c * 8) = *(const uint4*)(qb + r * HDIM + c * 8);
    }
    __syncthreads();
    uint32_t qf[8][4];
    {
        uint32_t qaddr = ks_u32 + (wid * 16 + (lane & 15)) * (KSTH * 2)
                       + (lane >> 4) * 16;
        #pragma unroll
        for (int kk = 0; kk < 8; kk++)
            LDSM_X4(qf[kk][0], qf[kk][1], qf[kk][2], qf[kk][3], qaddr + kk * 32);
    }
    __syncthreads();

    float oacc[16][4];
    #pragma unroll
    for (int nt = 0; nt < 16; nt++)
        #pragma unroll
        for (int r = 0; r < 4; r++) oacc[nt][r] = 0.f;

    float m_lo = -INFINITY, m_hi = -INFINITY, l_lo = 0.f, l_hi = 0.f;
    const float scale = 0.08838834764831845f;

    uint32_t kaddr = ks_u32 + (lane & 15) * (KSTH * 2) + (lane >> 4) * 16;
    uint32_t vaddr = vs_u32 + (lane & 15) * (KSTH * 2) + (lane >> 4) * 16;
    uint32_t paddr = pw_u32 + (lane & 15) * (PSTH * 2) + (lane >> 4) * 16;

    for (int kt = 0; kt < SEQ / 64; kt++) {
        for (int i = tid; i < 64 * 16; i += 128) {
            int r = i >> 4, c = i & 15;
            *(uint4*)(Ks + r * KSTH + c * 8) =
                *(const uint4*)(kb + (size_t)(kt * 64 + r) * HDIM + c * 8);
            *(uint4*)(Vs + r * KSTH + c * 8) =
                *(const uint4*)(vb + (size_t)(kt * 64 + r) * HDIM + c * 8);
        }
        __syncthreads();

        // ---- S = Q @ K^T (16 x 64 per warp) ----
        float sacc[8][4];
        #pragma unroll
        for (int nt = 0; nt < 8; nt++)
            #pragma unroll
            for (int r = 0; r < 4; r++) sacc[nt][r] = 0.f;

        #pragma unroll
        for (int kk = 0; kk < 8; kk++) {
            uint32_t bb[8][2];
            #pragma unroll
            for (int g = 0; g < 4; g++) {
                uint32_t r0, r1, r2, r3;
                LDSM_X4(r0, r1, r2, r3, kaddr + g * (16 * KSTH * 2) + kk * 32);
                bb[2 * g][0] = r0; bb[2 * g][1] = r2;
                bb[2 * g + 1][0] = r1; bb[2 * g + 1][1] = r3;
            }
            #pragma unroll
            for (int nt = 0; nt < 8; nt++)
                HMMA(sacc[nt], qf[kk][0], qf[kk][1], qf[kk][2], qf[kk][3],
                     bb[nt][0], bb[nt][1]);
        }

        // ---- online softmax (registers, 4-lane row groups) ----
        float mx_lo = m_lo, mx_hi = m_hi;
        #pragma unroll
        for (int nt = 0; nt < 8; nt++) {
            sacc[nt][0] *= scale; sacc[nt][1] *= scale;
            sacc[nt][2] *= scale; sacc[nt][3] *= scale;
            mx_lo = fmaxf(mx_lo, fmaxf(sacc[nt][0], sacc[nt][1]));
            mx_hi = fmaxf(mx_hi, fmaxf(sacc[nt][2], sacc[nt][3]));
        }
        #pragma unroll
        for (int o = 1; o <= 2; o <<= 1) {
            mx_lo = fmaxf(mx_lo, __shfl_xor_sync(0xffffffffu, mx_lo, o));
            mx_hi = fmaxf(mx_hi, __shfl_xor_sync(0xffffffffu, mx_hi, o));
        }
        float f_lo = __expf(m_lo - mx_lo);
        float f_hi = __expf(m_hi - mx_hi);
        float sum_lo = 0.f, sum_hi = 0.f;
        #pragma unroll
        for (int nt = 0; nt < 8; nt++) {
            float p0 = __expf(sacc[nt][0] - mx_lo);
            float p1 = __expf(sacc[nt][1] - mx_lo);
            float p2 = __expf(sacc[nt][2] - mx_hi);
            float p3 = __expf(sacc[nt][3] - mx_hi);
            sum_lo += p0 + p1; sum_hi += p2 + p3;
            int col = nt * 8 + 2 * (lane & 3);
            *(__half2*)(Pw + (lane >> 2) * PSTH + col) = __floats2half2_rn(p0, p1);
            *(__half2*)(Pw + ((lane >> 2) + 8) * PSTH + col) = __floats2half2_rn(p2, p3);
        }
        #pragma unroll
        for (int o = 1; o <= 2; o <<= 1) {
            sum_lo += __shfl_xor_sync(0xffffffffu, sum_lo, o);
            sum_hi += __shfl_xor_sync(0xffffffffu, sum_hi, o);
        }
        l_lo = l_lo * f_lo + sum_lo;
        l_hi = l_hi * f_hi + sum_hi;
        m_lo = mx_lo; m_hi = mx_hi;
        __syncwarp();

        // ---- rescale O, then O += P @ V (ldmatrix.trans for V) ----
        #pragma unroll
        for (int nt = 0; nt < 16; nt++) {
            oacc[nt][0] *= f_lo; oacc[nt][1] *= f_lo;
            oacc[nt][2] *= f_hi; oacc[nt][3] *= f_hi;
        }
        #pragma unroll
        for (int kkv = 0; kkv < 4; kkv++) {
            uint32_t pf0, pf1, pf2, pf3;
            LDSM_X4(pf0, pf1, pf2, pf3, paddr + kkv * 32);
            #pragma unroll
            for (int np = 0; np < 8; np++) {
                uint32_t v0, v1, v2, v3;
                LDSM_X4_T(v0, v1, v2, v3,
                          vaddr + kkv * (16 * KSTH * 2) + np * 32);
                HMMA(oacc[2 * np],     pf0, pf1, pf2, pf3, v0, v1);
                HMMA(oacc[2 * np + 1], pf0, pf1, pf2, pf3, v2, v3);
            }
        }
        __syncthreads();
    }

    // ---- epilogue: normalize, fp16 out (feeds out-proj GEMM) ----
    float inv_lo = 1.f / l_lo, inv_hi = 1.f / l_hi;
    int r = qt * 64 + wid * 16 + (lane >> 2);
    __half* ob0 = g_oh + ((size_t)b * SEQ + r) * INNER + h * HDIM;
    __half* ob1 = g_oh + ((size_t)b * SEQ + r + 8) * INNER + h * HDIM;
    #pragma unroll
    for (int nt = 0; nt < 16; nt++) {
        int col = nt * 8 + 2 * (lane & 3);
        *(__half2*)(ob0 + col) =
            __floats2half2_rn(oacc[nt][0] * inv_lo, oacc[nt][1] * inv_lo);
        *(__half2*)(ob1 + col) =
            __floats2half2_rn(oacc[nt][2] * inv_hi, oacc[nt][3] * inv_hi);
    }
}

// ---------------- host ----------------
extern "C" void kernel_launch(void* const* d_in, const int* in_sizes, int n_in,
                              void* d_out, int out_size) {
    const float* hid   = (const float*)d_in[0];
    const float* enc   = (const float*)d_in[1];
    const float* cosb  = (const float*)d_in[2];
    const float* sinb  = (const float*)d_in[3];
    const float* w_qkv = (const float*)d_in[4];
    const float* b_qkv = (const float*)d_in[5];
    const float* w_out = (const float*)d_in[6];
    const float* b_out = (const float*)d_in[7];
    float* out = (float*)d_out;

    __half *xhp, *ohp, *wqhp, *wohp;
    float *qkvp;
    cudaGetSymbolAddress((void**)&xhp,  g_xh);
    cudaGetSymbolAddress((void**)&qkvp, g_qkv);
    cudaGetSymbolAddress((void**)&ohp,  g_oh);
    cudaGetSymbolAddress((void**)&wqhp, g_wqh);
    cudaGetSymbolAddress((void**)&wohp, g_woh);

    static bool attr_set = false;
    if (!attr_set) {
        cudaFuncSetAttribute(mma_gemm<0>, cudaFuncAttributeMaxDynamicSharedMemorySize,
                             (int)GEMM_SMEM);
        cudaFuncSetAttribute(mma_gemm<1>, cudaFuncAttributeMaxDynamicSharedMemorySize,
                             (int)GEMM_SMEM);
        cudaFuncSetAttribute(attn_tc_kernel, cudaFuncAttributeMaxDynamicSharedMemorySize,
                             (int)ATT_SMEM);
        attr_set = true;
    }

    // 0. transpose + round weights: W[K][N] fp32 -> WT[N][K] fp16
    {
        dim3 blk(32, 8);
        dim3 gq(3 * INNER / 32, DMODEL / 32);
        transpose_h<<<gq, blk>>>(w_qkv, wqhp, DMODEL, 3 * INNER);
        dim3 go(DMODEL / 32, INNER / 32);
        transpose_h<<<go, blk>>>(w_out, wohp, INNER, DMODEL);
    }
    // 1. concat -> fp16
    {
        int total = ROWS * DMODEL / 8;
        concat_kernel<<<(total + 255) / 256, 256>>>(hid, enc);
    }
    // 2. qkv gemm (fp16 HMMA + ldmatrix)
    {
        dim3 grid(3 * INNER / 128, ROWS / 128);
        mma_gemm<0><<<grid, 256, GEMM_SMEM>>>(ROWS, 3 * INNER, DMODEL,
                                              xhp, wqhp, b_qkv, qkvp);
    }
    // 3. LN + RoPE -> fp16 q/k/v
    {
        int warps = BATCH * SEQ * HEADS;
        ln_rope_kernel<<<(warps + 7) / 8, 256>>>(cosb, sinb);
    }
    // 4. attention (fp16 HMMA + ldmatrix)
    {
        dim3 grid(SEQ / 64, HEADS, BATCH);
        attn_tc_kernel<<<grid, 128, ATT_SMEM>>>();
    }
    // 5. out proj with row remap (fp16 HMMA + ldmatrix)
    {
        dim3 grid(DMODEL / 128, ROWS / 128);
        mma_gemm<1><<<grid, 256, GEMM_SMEM>>>(ROWS, DMODEL, DMODEL,
                                              ohp, wohp, b_out, out);
    }
}

// round 12
// speedup vs baseline: 2.5626x; 1.0105x over previous
#include <cuda_runtime.h>
#include <cuda_fp16.h>
#include <math.h>
#include <stdint.h>

#define HEADS  24
#define HDIM   128
#define BATCH  2
#define TXT    256
#define IMG    1024
#define SEQ    1280          // TXT + IMG
#define DMODEL 3072
#define INNER  3072          // HEADS*HDIM
#define ROWS   (BATCH*SEQ)   // 2560

// ---------------- scratch (static device globals: allowed) ----------------
__device__ __half g_xh [ROWS * DMODEL];           // fp16 concat input
__device__ float  g_qkv[ROWS * 3 * INNER];        // fp32 qkv gemm out
__device__ __half g_qh [BATCH * HEADS * SEQ * HDIM]; // fp16 q (post LN/RoPE)
__device__ __half g_kh [BATCH * HEADS * SEQ * HDIM];
__device__ __half g_vh [BATCH * HEADS * SEQ * HDIM];
__device__ __half g_oh [ROWS * INNER];            // fp16 attn out
__device__ __half g_wqh[DMODEL * 3 * INNER];      // TRANSPOSED fp16 w_qkv [N][K]
__device__ __half g_woh[INNER * DMODEL];          // TRANSPOSED fp16 w_out [N][K]

// ---------------- mma / ldmatrix helpers ----------------
#define LDSM_X4(R0, R1, R2, R3, A) \
    asm volatile("ldmatrix.sync.aligned.m8n8.x4.shared.b16 {%0,%1,%2,%3}, [%4];" \
                 : "=r"(R0), "=r"(R1), "=r"(R2), "=r"(R3) : "r"(A))
#define LDSM_X4_T(R0, R1, R2, R3, A) \
    asm volatile("ldmatrix.sync.aligned.m8n8.x4.trans.shared.b16 {%0,%1,%2,%3}, [%4];" \
                 : "=r"(R0), "=r"(R1), "=r"(R2), "=r"(R3) : "r"(A))
#define HMMA(D, A0, A1, A2, A3, B0, B1) \
    asm volatile("mma.sync.aligned.m16n8k16.row.col.f32.f16.f16.f32 " \
                 "{%0,%1,%2,%3}, {%4,%5,%6,%7}, {%8,%9}, {%0,%1,%2,%3};" \
                 : "+f"((D)[0]), "+f"((D)[1]), "+f"((D)[2]), "+f"((D)[3]) \
                 : "r"(A0), "r"(A1), "r"(A2), "r"(A3), "r"(B0), "r"(B1))

// ---------------- 0. weight transpose + fp16 round ----------------
__global__ void transpose_h(const float* __restrict__ src,
                            __half* __restrict__ dst, int K, int N) {
    __shared__ float t[32][33];
    int kb = blockIdx.y * 32, nb = blockIdx.x * 32;
    int tx = threadIdx.x, ty = threadIdx.y;   // 32 x 8
    #pragma unroll
    for (int i = 0; i < 32; i += 8)
        t[ty + i][tx] = src[(size_t)(kb + ty + i) * N + nb + tx];
    __syncthreads();
    #pragma unroll
    for (int i = 0; i < 32; i += 8)
        dst[(size_t)(nb + ty + i) * K + kb + tx] = __float2half_rn(t[tx][ty + i]);
}

// ---------------- 1. concat -> fp16 ----------------
__global__ void concat_kernel(const float* __restrict__ hid,
                              const float* __restrict__ enc) {
    int idx = blockIdx.x * blockDim.x + threadIdx.x;   // 8-float chunk
    const int total = ROWS * DMODEL / 8;
    if (idx >= total) return;
    int row = idx / (DMODEL / 8);
    int c8  = idx % (DMODEL / 8);
    int b = row / SEQ, s = row % SEQ;
    const float4* src = (s < TXT)
        ? (const float4*)(enc + (size_t)(b * TXT + s) * DMODEL)
        : (const float4*)(hid + (size_t)(b * IMG + (s - TXT)) * DMODEL);
    float4 v0 = src[c8 * 2], v1 = src[c8 * 2 + 1];
    __half2 h[4];
    h[0] = __floats2half2_rn(v0.x, v0.y);
    h[1] = __floats2half2_rn(v0.z, v0.w);
    h[2] = __floats2half2_rn(v1.x, v1.y);
    h[3] = __floats2half2_rn(v1.z, v1.w);
    *(uint4*)(g_xh + (size_t)row * DMODEL + c8 * 8) = *(uint4*)h;
}

// ---------------- 2/5. FP16 GEMM (m16n8k16, ldmatrix) — unchanged ----------
#define HSTR 72
#define ROWB 144
#define TILE_BYTES (128 * ROWB)
#define STAGE_BYTES (2 * TILE_BYTES)
#define GEMM_SMEM ((size_t)2 * STAGE_BYTES)

template <int REMAP>
__global__ __launch_bounds__(256, 2)
void mma_gemm(int M, int N, int K,
              const __half* __restrict__ A, const __half* __restrict__ BT,
              const float* __restrict__ bias, float* __restrict__ C) {
    extern __shared__ char sh[];
    uint32_t sh_u32 = (uint32_t)__cvta_generic_to_shared(sh);
    int tid  = threadIdx.x;
    int lane = tid & 31, wid = tid >> 5;
    int wm = wid >> 2;
    int wn = wid & 3;
    int bm = blockIdx.y * 128;
    int bn = blockIdx.x * 128;
    int r4 = lane >> 2, kc = lane & 3;

    const __half* Ab = A + (size_t)bm * K;
    const __half* Bb = BT + (size_t)bn * K;

    uint32_t a_off = (uint32_t)((wm * 64 + (lane & 15)) * ROWB + (lane >> 4) * 16);
    uint32_t b_off = (uint32_t)(TILE_BYTES + (wn * 32 + (lane & 15)) * ROWB
                                + (lane >> 4) * 16);

    float acc[4][4][4];
    #pragma unroll
    for (int i = 0; i < 4; i++)
        #pragma unroll
        for (int j = 0; j < 4; j++)
            #pragma unroll
            for (int r = 0; r < 4; r++) acc[i][j][r] = 0.f;

    auto copy_tile = [&](int k0, int s) {
        char* As = sh + s * STAGE_BYTES;
        char* Bs = As + TILE_BYTES;
        #pragma unroll
        for (int i = 0; i < 2; i++) {
            int idx = tid + i * 256;
            int row = idx >> 2, c = idx & 3;
            uint32_t da = (uint32_t)__cvta_generic_to_shared(
                As + row * ROWB + c * 16);
            asm volatile("cp.async.cg.shared.global [%0], [%1], 16;"
                         :: "r"(da), "l"(Ab + (size_t)row * K + k0 + c * 8));
            uint32_t db = (uint32_t)__cvta_generic_to_shared(
                Bs + row * ROWB + c * 16);
            asm volatile("cp.async.cg.shared.global [%0], [%1], 16;"
                         :: "r"(db), "l"(Bb + (size_t)row * K + k0 + c * 8));
        }
        asm volatile("cp.async.commit_group;");
    };

    int nK = K / 32;
    copy_tile(0, 0);

    for (int kt = 0; kt < nK; kt++) {
        asm volatile("cp.async.wait_group 0;");
        __syncthreads();
        if (kt + 1 < nK) copy_tile((kt + 1) * 32, (kt + 1) & 1);

        uint32_t sb = sh_u32 + (kt & 1) * STAGE_BYTES;

        #pragma unroll
        for (int kk = 0; kk < 2; kk++) {
            uint32_t af[4][4], bf[4][2];
            #pragma unroll
            for (int mt = 0; mt < 4; mt++)
                LDSM_X4(af[mt][0], af[mt][1], af[mt][2], af[mt][3],
                        sb + a_off + mt * (16 * ROWB) + kk * 32);
            #pragma unroll
            for (int g = 0; g < 2; g++) {
                uint32_t r0, r1, r2, r3;
                LDSM_X4(r0, r1, r2, r3,
                        sb + b_off + g * (16 * ROWB) + kk * 32);
                bf[2 * g][0] = r0; bf[2 * g][1] = r2;
                bf[2 * g + 1][0] = r1; bf[2 * g + 1][1] = r3;
            }
            #pragma unroll
            for (int mt = 0; mt < 4; mt++)
                #pragma unroll
                for (int nt = 0; nt < 4; nt++)
                    HMMA(acc[mt][nt], af[mt][0], af[mt][1], af[mt][2], af[mt][3],
                         bf[nt][0], bf[nt][1]);
        }
        __syncthreads();
    }

    #pragma unroll
    for (int mt = 0; mt < 4; mt++) {
        #pragma unroll
        for (int half_ = 0; half_ < 2; half_++) {
            int m = bm + wm * 64 + mt * 16 + r4 + half_ * 8;
            float* crow;
            if (REMAP) {
                int b = m / SEQ, s = m % SEQ;
                int orow = (s < TXT) ? (BATCH * IMG + b * TXT + s)
                                     : (b * IMG + (s - TXT));
                crow = C + (size_t)orow * N;
            } else {
                crow = C + (size_t)m * N;
            }
            #pragma unroll
            for (int nt = 0; nt < 4; nt++) {
                int n = bn + wn * 32 + nt * 8 + kc * 2;
                float2 v;
                v.x = acc[mt][nt][half_ * 2 + 0] + bias[n];
                v.y = acc[mt][nt][half_ * 2 + 1] + bias[n + 1];
                *(float2*)(crow + n) = v;
            }
        }
    }
}

// ---------------- 3. LayerNorm + partial RoPE -> fp16 q/k/v ----------------
__global__ void ln_rope_kernel(const float* __restrict__ cosb,
                               const float* __restrict__ sinb) {
    int gw   = (blockIdx.x * blockDim.x + threadIdx.x) >> 5;
    int lane = threadIdx.x & 31;
    if (gw >= BATCH * SEQ * HEADS) return;
    int h = gw % HEADS;
    int s = (gw / HEADS) % SEQ;
    int b = gw / (HEADS * SEQ);
    const float* base = g_qkv + (size_t)(b * SEQ + s) * (3 * INNER) + h * HDIM;
    size_t orow = ((size_t)(b * HEADS + h) * SEQ + s) * HDIM;
    bool img = (s >= TXT);
    float c4[4], s4[4];
    if (img) {
        float4 cv = *(const float4*)(cosb + (size_t)(s - TXT) * HDIM + lane * 4);
        float4 sv = *(const float4*)(sinb + (size_t)(s - TXT) * HDIM + lane * 4);
        c4[0] = cv.x; c4[1] = cv.y; c4[2] = cv.z; c4[3] = cv.w;
        s4[0] = sv.x; s4[1] = sv.y; s4[2] = sv.z; s4[3] = sv.w;
    }
    float sgn = (lane < 16) ? -1.f : 1.f;
    #pragma unroll
    for (int qk = 0; qk < 2; qk++) {
        float4 xv = *(const float4*)(base + qk * INNER + lane * 4);
        float x[4] = {xv.x, xv.y, xv.z, xv.w};
        float sum = x[0] + x[1] + x[2] + x[3];
        #pragma unroll
        for (int o = 16; o > 0; o >>= 1) sum += __shfl_xor_sync(0xffffffffu, sum, o);
        float mu = sum * (1.f / 128.f);
        float vs = 0.f;
        #pragma unroll
        for (int i = 0; i < 4; i++) { float d = x[i] - mu; vs += d * d; x[i] = d; }
        #pragma unroll
        for (int o = 16; o > 0; o >>= 1) vs += __shfl_xor_sync(0xffffffffu, vs, o);
        float inv = rsqrtf(vs * (1.f / 128.f) + 1e-5f);
        #pragma unroll
        for (int i = 0; i < 4; i++) x[i] *= inv;
        if (img) {
            float p[4];
            #pragma unroll
            for (int i = 0; i < 4; i++) p[i] = __shfl_xor_sync(0xffffffffu, x[i], 16);
            #pragma unroll
            for (int i = 0; i < 4; i++) x[i] = x[i] * c4[i] + sgn * p[i] * s4[i];
        }
        __half2 hv[2];
        hv[0] = __floats2half2_rn(x[0], x[1]);
        hv[1] = __floats2half2_rn(x[2], x[3]);
        __half* dst = qk == 0 ? g_qh : g_kh;
        *(uint2*)(dst + orow + lane * 4) = *(uint2*)hv;
    }
    {
        float4 vv = *(const float4*)(base + 2 * INNER + lane * 4);
        __half2 hv[2];
        hv[0] = __floats2half2_rn(vv.x, vv.y);
        hv[1] = __floats2half2_rn(vv.z, vv.w);
        *(uint2*)(g_vh + orow + lane * 4) = *(uint2*)hv;
    }
}

// ---------------- 4. flash attention, fp16 TC, 4-stage cp.async ------------
// 256 threads / 8 warps; q-tile 128 (16 rows/warp), kv-tile 64, D=128.
// KV stage: K 64x136 + V 64x136 halves = 34816 B; 4 stages + P(8x16x72).
#define KSTH 136
#define PSTH 72
#define KV_STAGE_H (2 * 64 * KSTH)                    // halves per stage
#define KV_STAGE_B (KV_STAGE_H * 2)                   // 34816 B
#define ATT_NKV (SEQ / 64)                            // 20
#define ATT_SMEM ((size_t)(4 * KV_STAGE_H + 8 * 16 * PSTH) * 2)  // 157696 B

__global__ __launch_bounds__(256)
void attn_tc_kernel() {
    extern __shared__ __half smh[];
    uint32_t sm_u32 = (uint32_t)__cvta_generic_to_shared(smh);
    __half* Ps = smh + 4 * KV_STAGE_H;

    int qt = blockIdx.x, h = blockIdx.y, b = blockIdx.z;
    int tid = threadIdx.x, lane = tid & 31, wid = tid >> 5;
    size_t hb = (size_t)(b * HEADS + h) * SEQ * HDIM;
    const __half* qb = g_qh + hb + (size_t)qt * 128 * HDIM;
    const __half* kb = g_kh + hb;
    const __half* vb = g_vh + hb;

    __half* Pw = Ps + wid * 16 * PSTH;
    uint32_t pw_u32 = (uint32_t)__cvta_generic_to_shared(Pw);
    uint32_t paddr = pw_u32 + (lane & 15) * (PSTH * 2) + (lane >> 4) * 16;

    // ---- cp.async K/V tile copy (64 rows x 16 chunks x {K,V}) ----
    auto copy_kv = [&](int kt, int s) {
        uint32_t kbase = sm_u32 + s * KV_STAGE_B;
        uint32_t vbase = kbase + 64 * KSTH * 2;
        #pragma unroll
        for (int i = 0; i < 4; i++) {
            int idx = tid + i * 256;          // 0..1023
            int row = idx >> 4, c = idx & 15;
            const __half* srck = kb + (size_t)(kt * 64 + row) * HDIM + c * 8;
            const __half* srcv = vb + (size_t)(kt * 64 + row) * HDIM + c * 8;
            asm volatile("cp.async.cg.shared.global [%0], [%1], 16;"
                         :: "r"(kbase + row * (KSTH * 2) + c * 16), "l"(srck));
            asm volatile("cp.async.cg.shared.global [%0], [%1], 16;"
                         :: "r"(vbase + row * (KSTH * 2) + c * 16), "l"(srcv));
        }
        asm volatile("cp.async.commit_group;");
    };

    // prefetch tiles 0,1,2 into stages 0,1,2
    copy_kv(0, 0);
    copy_kv(1, 1);
    copy_kv(2, 2);

    // ---- stage Q into stage-3 region (sync loads), extract fragments ----
    {
        __half* Qs = smh + 3 * KV_STAGE_H;
        for (int i = tid; i < 128 * 16; i += 256) {
            int r = i >> 4, c = i & 15;
            *(uint4*)(Qs + r * KSTH + c * 8) =
                *(const uint4*)(qb + (size_t)r * HDIM + c * 8);
        }
    }
    __syncthreads();
    uint32_t qf[8][4];
    {
        uint32_t qaddr = sm_u32 + 3 * KV_STAGE_B
                       + (wid * 16 + (lane & 15)) * (KSTH * 2) + (lane >> 4) * 16;
        #pragma unroll
        for (int kk = 0; kk < 8; kk++)
            LDSM_X4(qf[kk][0], qf[kk][1], qf[kk][2], qf[kk][3], qaddr + kk * 32);
    }
    __syncthreads();     // Q extraction done before stage 3 is overwritten

    float oacc[16][4];
    #pragma unroll
    for (int nt = 0; nt < 16; nt++)
        #pragma unroll
        for (int r = 0; r < 4; r++) oacc[nt][r] = 0.f;

    float m_lo = -INFINITY, m_hi = -INFINITY, l_lo = 0.f, l_hi = 0.f;
    const float scale = 0.08838834764831845f;

    for (int kt = 0; kt < ATT_NKV; kt++) {
        asm volatile("cp.async.wait_group 2;");   // tile kt landed
        __syncthreads();                          // visibility + stage-reuse fence
        {
            int tc = kt + 3; if (tc > ATT_NKV - 1) tc = ATT_NKV - 1;
            copy_kv(tc, (kt + 3) & 3);
        }

        uint32_t kbase = sm_u32 + (kt & 3) * KV_STAGE_B;
        uint32_t kaddr = kbase + (lane & 15) * (KSTH * 2) + (lane >> 4) * 16;
        uint32_t vaddr = kbase + 64 * KSTH * 2
                       + (lane & 15) * (KSTH * 2) + (lane >> 4) * 16;

        // ---- S = Q @ K^T (16 x 64 per warp) ----
        float sacc[8][4];
        #pragma unroll
        for (int nt = 0; nt < 8; nt++)
            #pragma unroll
            for (int r = 0; r < 4; r++) sacc[nt][r] = 0.f;

        #pragma unroll
        for (int kk = 0; kk < 8; kk++) {
            uint32_t bb[8][2];
            #pragma unroll
            for (int g = 0; g < 4; g++) {
                uint32_t r0, r1, r2, r3;
                LDSM_X4(r0, r1, r2, r3, kaddr + g * (16 * KSTH * 2) + kk * 32);
                bb[2 * g][0] = r0; bb[2 * g][1] = r2;
                bb[2 * g + 1][0] = r1; bb[2 * g + 1][1] = r3;
            }
            #pragma unroll
            for (int nt = 0; nt < 8; nt++)
                HMMA(sacc[nt], qf[kk][0], qf[kk][1], qf[kk][2], qf[kk][3],
                     bb[nt][0], bb[nt][1]);
        }

        // ---- online softmax (registers, 4-lane row groups) ----
        float mx_lo = m_lo, mx_hi = m_hi;
        #pragma unroll
        for (int nt = 0; nt < 8; nt++) {
            sacc[nt][0] *= scale; sacc[nt][1] *= scale;
            sacc[nt][2] *= scale; sacc[nt][3] *= scale;
            mx_lo = fmaxf(mx_lo, fmaxf(sacc[nt][0], sacc[nt][1]));
            mx_hi = fmaxf(mx_hi, fmaxf(sacc[nt][2], sacc[nt][3]));
        }
        #pragma unroll
        for (int o = 1; o <= 2; o <<= 1) {
            mx_lo = fmaxf(mx_lo, __shfl_xor_sync(0xffffffffu, mx_lo, o));
            mx_hi = fmaxf(mx_hi, __shfl_xor_sync(0xffffffffu, mx_hi, o));
        }
        float f_lo = __expf(m_lo - mx_lo);
        float f_hi = __expf(m_hi - mx_hi);
        float sum_lo = 0.f, sum_hi = 0.f;
        #pragma unroll
        for (int nt = 0; nt < 8; nt++) {
            float p0 = __expf(sacc[nt][0] - mx_lo);
            float p1 = __expf(sacc[nt][1] - mx_lo);
            float p2 = __expf(sacc[nt][2] - mx_hi);
            float p3 = __expf(sacc[nt][3] - mx_hi);
            sum_lo += p0 + p1; sum_hi += p2 + p3;
            int col = nt * 8 + 2 * (lane & 3);
            *(__half2*)(Pw + (lane >> 2) * PSTH + col) = __floats2half2_rn(p0, p1);
            *(__half2*)(Pw + ((lane >> 2) + 8) * PSTH + col) = __floats2half2_rn(p2, p3);
        }
        #pragma unroll
        for (int o = 1; o <= 2; o <<= 1) {
            sum_lo += __shfl_xor_sync(0xffffffffu, sum_lo, o);
            sum_hi += __shfl_xor_sync(0xffffffffu, sum_hi, o);
        }
        l_lo = l_lo * f_lo + sum_lo;
        l_hi = l_hi * f_hi + sum_hi;
        m_lo = mx_lo; m_hi = mx_hi;
        __syncwarp();

        // ---- rescale O, then O += P @ V (ldmatrix.trans for V) ----
        #pragma unroll
        for (int nt = 0; nt < 16; nt++) {
            oacc[nt][0] *= f_lo; oacc[nt][1] *= f_lo;
            oacc[nt][2] *= f_hi; oacc[nt][3] *= f_hi;
        }
        #pragma unroll
        for (int kkv = 0; kkv < 4; kkv++) {
            uint32_t pf0, pf1, pf2, pf3;
            LDSM_X4(pf0, pf1, pf2, pf3, paddr + kkv * 32);
            #pragma unroll
            for (int np = 0; np < 8; np++) {
                uint32_t v0, v1, v2, v3;
                LDSM_X4_T(v0, v1, v2, v3,
                          vaddr + kkv * (16 * KSTH * 2) + np * 32);
                HMMA(oacc[2 * np],     pf0, pf1, pf2, pf3, v0, v1);
                HMMA(oacc[2 * np + 1], pf0, pf1, pf2, pf3, v2, v3);
            }
        }
        // single barrier per iter (top of next iteration)
    }

    // ---- epilogue: normalize, fp16 out (feeds out-proj GEMM) ----
    float inv_lo = 1.f / l_lo, inv_hi = 1.f / l_hi;
    int r = qt * 128 + wid * 16 + (lane >> 2);
    __half* ob0 = g_oh + ((size_t)b * SEQ + r) * INNER + h * HDIM;
    __half* ob1 = g_oh + ((size_t)b * SEQ + r + 8) * INNER + h * HDIM;
    #pragma unroll
    for (int nt = 0; nt < 16; nt++) {
        int col = nt * 8 + 2 * (lane & 3);
        *(__half2*)(ob0 + col) =
            __floats2half2_rn(oacc[nt][0] * inv_lo, oacc[nt][1] * inv_lo);
        *(__half2*)(ob1 + col) =
            __floats2half2_rn(oacc[nt][2] * inv_hi, oacc[nt][3] * inv_hi);
    }
}

// ---------------- host ----------------
extern "C" void kernel_launch(void* const* d_in, const int* in_sizes, int n_in,
                              void* d_out, int out_size) {
    const float* hid   = (const float*)d_in[0];
    const float* enc   = (const float*)d_in[1];
    const float* cosb  = (const float*)d_in[2];
    const float* sinb  = (const float*)d_in[3];
    const float* w_qkv = (const float*)d_in[4];
    const float* b_qkv = (const float*)d_in[5];
    const float* w_out = (const float*)d_in[6];
    const float* b_out = (const float*)d_in[7];
    float* out = (float*)d_out;

    __half *xhp, *ohp, *wqhp, *wohp;
    float *qkvp;
    cudaGetSymbolAddress((void**)&xhp,  g_xh);
    cudaGetSymbolAddress((void**)&qkvp, g_qkv);
    cudaGetSymbolAddress((void**)&ohp,  g_oh);
    cudaGetSymbolAddress((void**)&wqhp, g_wqh);
    cudaGetSymbolAddress((void**)&wohp, g_woh);

    static bool attr_set = false;
    if (!attr_set) {
        cudaFuncSetAttribute(mma_gemm<0>, cudaFuncAttributeMaxDynamicSharedMemorySize,
                             (int)GEMM_SMEM);
        cudaFuncSetAttribute(mma_gemm<1>, cudaFuncAttributeMaxDynamicSharedMemorySize,
                             (int)GEMM_SMEM);
        cudaFuncSetAttribute(attn_tc_kernel, cudaFuncAttributeMaxDynamicSharedMemorySize,
                             (int)ATT_SMEM);
        attr_set = true;
    }

    // 0. transpose + round weights: W[K][N] fp32 -> WT[N][K] fp16
    {
        dim3 blk(32, 8);
        dim3 gq(3 * INNER / 32, DMODEL / 32);
        transpose_h<<<gq, blk>>>(w_qkv, wqhp, DMODEL, 3 * INNER);
        dim3 go(DMODEL / 32, INNER / 32);
        transpose_h<<<go, blk>>>(w_out, wohp, INNER, DMODEL);
    }
    // 1. concat -> fp16
    {
        int total = ROWS * DMODEL / 8;
        concat_kernel<<<(total + 255) / 256, 256>>>(hid, enc);
    }
    // 2. qkv gemm (fp16 HMMA + ldmatrix)
    {
        dim3 grid(3 * INNER / 128, ROWS / 128);
        mma_gemm<0><<<grid, 256, GEMM_SMEM>>>(ROWS, 3 * INNER, DMODEL,
                                              xhp, wqhp, b_qkv, qkvp);
    }
    // 3. LN + RoPE -> fp16 q/k/v
    {
        int warps = BATCH * SEQ * HEADS;
        ln_rope_kernel<<<(warps + 7) / 8, 256>>>(cosb, sinb);
    }
    // 4. attention (fp16 HMMA, q-tile 128, 4-stage cp.async)
    {
        dim3 grid(SEQ / 128, HEADS, BATCH);
        attn_tc_kernel<<<grid, 256, ATT_SMEM>>>();
    }
    // 5. out proj with row remap (fp16 HMMA + ldmatrix)
    {
        dim3 grid(DMODEL / 128, ROWS / 128);
        mma_gemm<1><<<grid, 256, GEMM_SMEM>>>(ROWS, DMODEL, DMODEL,
                                              ohp, wohp, b_out, out);
    }
}

// round 13
// speedup vs baseline: 2.6204x; 1.0225x over previous
#include <cuda_runtime.h>
#include <cuda_fp16.h>
#include <math.h>
#include <stdint.h>

#define HEADS  24
#define HDIM   128
#define BATCH  2
#define TXT    256
#define IMG    1024
#define SEQ    1280          // TXT + IMG
#define DMODEL 3072
#define INNER  3072          // HEADS*HDIM
#define ROWS   (BATCH*SEQ)   // 2560

// ---------------- scratch (static device globals: allowed) ----------------
__device__ __half g_xh [ROWS * DMODEL];           // fp16 concat input
__device__ __half g_qh [BATCH * HEADS * SEQ * HDIM]; // fp16 q (post LN/RoPE)
__device__ __half g_kh [BATCH * HEADS * SEQ * HDIM];
__device__ __half g_vh [BATCH * HEADS * SEQ * HDIM];
__device__ __half g_oh [ROWS * INNER];            // fp16 attn out
__device__ __half g_wqh[DMODEL * 3 * INNER];      // TRANSPOSED fp16 w_qkv [N][K]
__device__ __half g_woh[INNER * DMODEL];          // TRANSPOSED fp16 w_out [N][K]

// ---------------- mma / ldmatrix helpers ----------------
#define LDSM_X4(R0, R1, R2, R3, A) \
    asm volatile("ldmatrix.sync.aligned.m8n8.x4.shared.b16 {%0,%1,%2,%3}, [%4];" \
                 : "=r"(R0), "=r"(R1), "=r"(R2), "=r"(R3) : "r"(A))
#define LDSM_X4_T(R0, R1, R2, R3, A) \
    asm volatile("ldmatrix.sync.aligned.m8n8.x4.trans.shared.b16 {%0,%1,%2,%3}, [%4];" \
                 : "=r"(R0), "=r"(R1), "=r"(R2), "=r"(R3) : "r"(A))
#define HMMA(D, A0, A1, A2, A3, B0, B1) \
    asm volatile("mma.sync.aligned.m16n8k16.row.col.f32.f16.f16.f32 " \
                 "{%0,%1,%2,%3}, {%4,%5,%6,%7}, {%8,%9}, {%0,%1,%2,%3};" \
                 : "+f"((D)[0]), "+f"((D)[1]), "+f"((D)[2]), "+f"((D)[3]) \
                 : "r"(A0), "r"(A1), "r"(A2), "r"(A3), "r"(B0), "r"(B1))

// ---------------- 0. weight transpose + fp16 round ----------------
__global__ void transpose_h(const float* __restrict__ src,
                            __half* __restrict__ dst, int K, int N) {
    __shared__ float t[32][33];
    int kb = blockIdx.y * 32, nb = blockIdx.x * 32;
    int tx = threadIdx.x, ty = threadIdx.y;   // 32 x 8
    #pragma unroll
    for (int i = 0; i < 32; i += 8)
        t[ty + i][tx] = src[(size_t)(kb + ty + i) * N + nb + tx];
    __syncthreads();
    #pragma unroll
    for (int i = 0; i < 32; i += 8)
        dst[(size_t)(nb + ty + i) * K + kb + tx] = __float2half_rn(t[tx][ty + i]);
}

// ---------------- 1. concat -> fp16 ----------------
__global__ void concat_kernel(const float* __restrict__ hid,
                              const float* __restrict__ enc) {
    int idx = blockIdx.x * blockDim.x + threadIdx.x;   // 8-float chunk
    const int total = ROWS * DMODEL / 8;
    if (idx >= total) return;
    int row = idx / (DMODEL / 8);
    int c8  = idx % (DMODEL / 8);
    int b = row / SEQ, s = row % SEQ;
    const float4* src = (s < TXT)
        ? (const float4*)(enc + (size_t)(b * TXT + s) * DMODEL)
        : (const float4*)(hid + (size_t)(b * IMG + (s - TXT)) * DMODEL);
    float4 v0 = src[c8 * 2], v1 = src[c8 * 2 + 1];
    __half2 h[4];
    h[0] = __floats2half2_rn(v0.x, v0.y);
    h[1] = __floats2half2_rn(v0.z, v0.w);
    h[2] = __floats2half2_rn(v1.x, v1.y);
    h[3] = __floats2half2_rn(v1.z, v1.w);
    *(uint4*)(g_xh + (size_t)row * DMODEL + c8 * 8) = *(uint4*)h;
}

// ---------------- 2/5. FP16 GEMM (m16n8k16, ldmatrix) ----------------
// MODE 0: qkv gemm, fused bias+LN+RoPE epilogue -> fp16 g_qh/g_kh/g_vh.
// MODE 1: out-proj, bias + row-remap epilogue -> fp32 C.
#define HSTR 72
#define ROWB 144
#define TILE_BYTES (128 * ROWB)
#define STAGE_BYTES (2 * TILE_BYTES)
#define GEMM_SMEM ((size_t)2 * STAGE_BYTES)

template <int MODE>
__global__ __launch_bounds__(256, 2)
void mma_gemm(int M, int N, int K,
              const __half* __restrict__ A, const __half* __restrict__ BT,
              const float* __restrict__ bias, float* __restrict__ C,
              const float* __restrict__ cosb, const float* __restrict__ sinb) {
    extern __shared__ char sh[];
    uint32_t sh_u32 = (uint32_t)__cvta_generic_to_shared(sh);
    int tid  = threadIdx.x;
    int lane = tid & 31, wid = tid >> 5;
    int wm = wid >> 2;
    int wn = wid & 3;
    int bm = blockIdx.y * 128;
    int bn = blockIdx.x * 128;
    int r4 = lane >> 2, kc = lane & 3;

    const __half* Ab = A + (size_t)bm * K;
    const __half* Bb = BT + (size_t)bn * K;

    uint32_t a_off = (uint32_t)((wm * 64 + (lane & 15)) * ROWB + (lane >> 4) * 16);
    uint32_t b_off = (uint32_t)(TILE_BYTES + (wn * 32 + (lane & 15)) * ROWB
                                + (lane >> 4) * 16);

    float acc[4][4][4];
    #pragma unroll
    for (int i = 0; i < 4; i++)
        #pragma unroll
        for (int j = 0; j < 4; j++)
            #pragma unroll
            for (int r = 0; r < 4; r++) acc[i][j][r] = 0.f;

    auto copy_tile = [&](int k0, int s) {
        char* As = sh + s * STAGE_BYTES;
        char* Bs = As + TILE_BYTES;
        #pragma unroll
        for (int i = 0; i < 2; i++) {
            int idx = tid + i * 256;
            int row = idx >> 2, c = idx & 3;
            uint32_t da = (uint32_t)__cvta_generic_to_shared(
                As + row * ROWB + c * 16);
            asm volatile("cp.async.cg.shared.global [%0], [%1], 16;"
                         :: "r"(da), "l"(Ab + (size_t)row * K + k0 + c * 8));
            uint32_t db = (uint32_t)__cvta_generic_to_shared(
                Bs + row * ROWB + c * 16);
            asm volatile("cp.async.cg.shared.global [%0], [%1], 16;"
                         :: "r"(db), "l"(Bb + (size_t)row * K + k0 + c * 8));
        }
        asm volatile("cp.async.commit_group;");
    };

    int nK = K / 32;
    copy_tile(0, 0);

    for (int kt = 0; kt < nK; kt++) {
        asm volatile("cp.async.wait_group 0;");
        __syncthreads();
        if (kt + 1 < nK) copy_tile((kt + 1) * 32, (kt + 1) & 1);

        uint32_t sb = sh_u32 + (kt & 1) * STAGE_BYTES;

        #pragma unroll
        for (int kk = 0; kk < 2; kk++) {
            uint32_t af[4][4], bf[4][2];
            #pragma unroll
            for (int mt = 0; mt < 4; mt++)
                LDSM_X4(af[mt][0], af[mt][1], af[mt][2], af[mt][3],
                        sb + a_off + mt * (16 * ROWB) + kk * 32);
            #pragma unroll
            for (int g = 0; g < 2; g++) {
                uint32_t r0, r1, r2, r3;
                LDSM_X4(r0, r1, r2, r3,
                        sb + b_off + g * (16 * ROWB) + kk * 32);
                bf[2 * g][0] = r0; bf[2 * g][1] = r2;
                bf[2 * g + 1][0] = r1; bf[2 * g + 1][1] = r3;
            }
            #pragma unroll
            for (int mt = 0; mt < 4; mt++)
                #pragma unroll
                for (int nt = 0; nt < 4; nt++)
                    HMMA(acc[mt][nt], af[mt][0], af[mt][1], af[mt][2], af[mt][3],
                         bf[nt][0], bf[nt][1]);
        }
        __syncthreads();
    }

    // -------- epilogue --------
    // bias add (both modes)
    {
        float bv0[4], bv1[4];
        #pragma unroll
        for (int nt = 0; nt < 4; nt++) {
            int n = bn + wn * 32 + nt * 8 + kc * 2;
            bv0[nt] = bias[n]; bv1[nt] = bias[n + 1];
        }
        #pragma unroll
        for (int mt = 0; mt < 4; mt++)
            #pragma unroll
            for (int nt = 0; nt < 4; nt++) {
                acc[mt][nt][0] += bv0[nt]; acc[mt][nt][1] += bv1[nt];
                acc[mt][nt][2] += bv0[nt]; acc[mt][nt][3] += bv1[nt];
            }
    }

    if (MODE == 1) {
        #pragma unroll
        for (int mt = 0; mt < 4; mt++)
            #pragma unroll
            for (int hf = 0; hf < 2; hf++) {
                int m = bm + wm * 64 + mt * 16 + r4 + hf * 8;
                int b = m / SEQ, s = m % SEQ;
                int orow = (s < TXT) ? (BATCH * IMG + b * TXT + s)
                                     : (b * IMG + (s - TXT));
                float* crow = C + (size_t)orow * N;
                #pragma unroll
                for (int nt = 0; nt < 4; nt++) {
                    int n = bn + wn * 32 + nt * 8 + kc * 2;
                    float2 v;
                    v.x = acc[mt][nt][hf * 2 + 0];
                    v.y = acc[mt][nt][hf * 2 + 1];
                    *(float2*)(crow + n) = v;
                }
            }
        return;
    }

    // MODE 0: this CTA's 128 cols == one head of q/k/v.
    int type = bn / INNER;               // 0=q, 1=k, 2=v
    int head = (bn % INNER) / HDIM;

    if (type == 2) {
        // V: bias already added; store fp16 directly.
        #pragma unroll
        for (int mt = 0; mt < 4; mt++)
            #pragma unroll
            for (int hf = 0; hf < 2; hf++) {
                int m = bm + wm * 64 + mt * 16 + r4 + hf * 8;
                int b = m / SEQ, s = m % SEQ;
                __half* dst = g_vh
                    + ((size_t)(b * HEADS + head) * SEQ + s) * HDIM;
                #pragma unroll
                for (int nt = 0; nt < 4; nt++) {
                    int d = wn * 32 + nt * 8 + kc * 2;
                    *(__half2*)(dst + d) =
                        __floats2half2_rn(acc[mt][nt][hf * 2],
                                          acc[mt][nt][hf * 2 + 1]);
                }
            }
        return;
    }

    // q/k: LayerNorm over the 128 CTA-resident cols, then RoPE.
    float2* stats = (float2*)sh;                  // [128][4]
    __half* Qs    = (__half*)(sh + 4096);         // [128][136]

    // step 1: per-row partials (shfl within 4-lane kc group), write smem
    #pragma unroll
    for (int mt = 0; mt < 4; mt++)
        #pragma unroll
        for (int hf = 0; hf < 2; hf++) {
            float sum = 0.f, sq = 0.f;
            #pragma unroll
            for (int nt = 0; nt < 4; nt++) {
                float a = acc[mt][nt][hf * 2], c2 = acc[mt][nt][hf * 2 + 1];
                sum += a + c2; sq += a * a + c2 * c2;
            }
            sum += __shfl_xor_sync(0xffffffffu, sum, 1);
            sq  += __shfl_xor_sync(0xffffffffu, sq, 1);
            sum += __shfl_xor_sync(0xffffffffu, sum, 2);
            sq  += __shfl_xor_sync(0xffffffffu, sq, 2);
            if (kc == 0) {
                int rl = wm * 64 + mt * 16 + r4 + hf * 8;
                stats[rl * 4 + wn] = make_float2(sum, sq);
            }
        }
    __syncthreads();

    // step 2: normalize into fp16 smem tile
    #pragma unroll
    for (int mt = 0; mt < 4; mt++)
        #pragma unroll
        for (int hf = 0; hf < 2; hf++) {
            int rl = wm * 64 + mt * 16 + r4 + hf * 8;
            float sum = 0.f, sq = 0.f;
            #pragma unroll
            for (int w = 0; w < 4; w++) {
                float2 p = stats[rl * 4 + w];
                sum += p.x; sq += p.y;
            }
            float mu = sum * (1.f / 128.f);
            float var = fmaxf(sq * (1.f / 128.f) - mu * mu, 0.f);
            float inv = rsqrtf(var + 1e-5f);
            #pragma unroll
            for (int nt = 0; nt < 4; nt++) {
                int d = wn * 32 + nt * 8 + kc * 2;
                Qs[rl * 136 + d] =
                    __float2half_rn((acc[mt][nt][hf * 2] - mu) * inv);
                Qs[rl * 136 + d + 1] =
                    __float2half_rn((acc[mt][nt][hf * 2 + 1] - mu) * inv);
            }
        }
    __syncthreads();

    // step 3: RoPE (img rows) + store fp16
    __half* dstb = (type == 0) ? g_qh : g_kh;
    #pragma unroll
    for (int it = 0; it < 16; it++) {
        int i = tid + it * 256;
        int r = i >> 5, c4 = i & 31;
        int d0 = c4 * 4;
        int m = bm + r;
        int b = m / SEQ, s = m % SEQ;
        float x[4];
        #pragma unroll
        for (int j = 0; j < 4; j++) x[j] = __half2float(Qs[r * 136 + d0 + j]);
        if (s >= TXT) {
            int dp = d0 ^ 64;
            float sgn = (d0 < 64) ? -1.f : 1.f;
            float4 cv = *(const float4*)(cosb + (size_t)(s - TXT) * HDIM + d0);
            float4 sv = *(const float4*)(sinb + (size_t)(s - TXT) * HDIM + d0);
            float p[4];
            #pragma unroll
            for (int j = 0; j < 4; j++) p[j] = __half2float(Qs[r * 136 + dp + j]);
            x[0] = x[0] * cv.x + sgn * p[0] * sv.x;
            x[1] = x[1] * cv.y + sgn * p[1] * sv.y;
            x[2] = x[2] * cv.z + sgn * p[2] * sv.z;
            x[3] = x[3] * cv.w + sgn * p[3] * sv.w;
        }
        __half* dst = dstb + ((size_t)(b * HEADS + head) * SEQ + s) * HDIM + d0;
        ((__half2*)dst)[0] = __floats2half2_rn(x[0], x[1]);
        ((__half2*)dst)[1] = __floats2half2_rn(x[2], x[3]);
    }
}

// ---------------- 4. flash attention, fp16 TC, 4-stage cp.async ------------
#define KSTH 136
#define PSTH 72
#define KV_STAGE_H (2 * 64 * KSTH)
#define KV_STAGE_B (KV_STAGE_H * 2)
#define ATT_NKV (SEQ / 64)
#define ATT_SMEM ((size_t)(4 * KV_STAGE_H + 8 * 16 * PSTH) * 2)

__global__ __launch_bounds__(256)
void attn_tc_kernel() {
    extern __shared__ __half smh[];
    uint32_t sm_u32 = (uint32_t)__cvta_generic_to_shared(smh);
    __half* Ps = smh + 4 * KV_STAGE_H;

    int qt = blockIdx.x, h = blockIdx.y, b = blockIdx.z;
    int tid = threadIdx.x, lane = tid & 31, wid = tid >> 5;
    size_t hb = (size_t)(b * HEADS + h) * SEQ * HDIM;
    const __half* qb = g_qh + hb + (size_t)qt * 128 * HDIM;
    const __half* kb = g_kh + hb;
    const __half* vb = g_vh + hb;

    __half* Pw = Ps + wid * 16 * PSTH;
    uint32_t pw_u32 = (uint32_t)__cvta_generic_to_shared(Pw);
    uint32_t paddr = pw_u32 + (lane & 15) * (PSTH * 2) + (lane >> 4) * 16;

    auto copy_kv = [&](int kt, int s) {
        uint32_t kbase = sm_u32 + s * KV_STAGE_B;
        uint32_t vbase = kbase + 64 * KSTH * 2;
        #pragma unroll
        for (int i = 0; i < 4; i++) {
            int idx = tid + i * 256;
            int row = idx >> 4, c = idx & 15;
            const __half* srck = kb + (size_t)(kt * 64 + row) * HDIM + c * 8;
            const __half* srcv = vb + (size_t)(kt * 64 + row) * HDIM + c * 8;
            asm volatile("cp.async.cg.shared.global [%0], [%1], 16;"
                         :: "r"(kbase + row * (KSTH * 2) + c * 16), "l"(srck));
            asm volatile("cp.async.cg.shared.global [%0], [%1], 16;"
                         :: "r"(vbase + row * (KSTH * 2) + c * 16), "l"(srcv));
        }
        asm volatile("cp.async.commit_group;");
    };

    copy_kv(0, 0);
    copy_kv(1, 1);
    copy_kv(2, 2);

    {
        __half* Qs = smh + 3 * KV_STAGE_H;
        for (int i = tid; i < 128 * 16; i += 256) {
            int r = i >> 4, c = i & 15;
            *(uint4*)(Qs + r * KSTH + c * 8) =
                *(const uint4*)(qb + (size_t)r * HDIM + c * 8);
        }
    }
    __syncthreads();
    uint32_t qf[8][4];
    {
        uint32_t qaddr = sm_u32 + 3 * KV_STAGE_B
                       + (wid * 16 + (lane & 15)) * (KSTH * 2) + (lane >> 4) * 16;
        #pragma unroll
        for (int kk = 0; kk < 8; kk++)
            LDSM_X4(qf[kk][0], qf[kk][1], qf[kk][2], qf[kk][3], qaddr + kk * 32);
    }
    __syncthreads();

    float oacc[16][4];
    #pragma unroll
    for (int nt = 0; nt < 16; nt++)
        #pragma unroll
        for (int r = 0; r < 4; r++) oacc[nt][r] = 0.f;

    float m_lo = -INFINITY, m_hi = -INFINITY, l_lo = 0.f, l_hi = 0.f;
    const float scale = 0.08838834764831845f;

    for (int kt = 0; kt < ATT_NKV; kt++) {
        asm volatile("cp.async.wait_group 2;");
        __syncthreads();
        {
            int tc = kt + 3; if (tc > ATT_NKV - 1) tc = ATT_NKV - 1;
            copy_kv(tc, (kt + 3) & 3);
        }

        uint32_t kbase = sm_u32 + (kt & 3) * KV_STAGE_B;
        uint32_t kaddr = kbase + (lane & 15) * (KSTH * 2) + (lane >> 4) * 16;
        uint32_t vaddr = kbase + 64 * KSTH * 2
                       + (lane & 15) * (KSTH * 2) + (lane >> 4) * 16;

        float sacc[8][4];
        #pragma unroll
        for (int nt = 0; nt < 8; nt++)
            #pragma unroll
            for (int r = 0; r < 4; r++) sacc[nt][r] = 0.f;

        #pragma unroll
        for (int kk = 0; kk < 8; kk++) {
            uint32_t bb[8][2];
            #pragma unroll
            for (int g = 0; g < 4; g++) {
                uint32_t r0, r1, r2, r3;
                LDSM_X4(r0, r1, r2, r3, kaddr + g * (16 * KSTH * 2) + kk * 32);
                bb[2 * g][0] = r0; bb[2 * g][1] = r2;
                bb[2 * g + 1][0] = r1; bb[2 * g + 1][1] = r3;
            }
            #pragma unroll
            for (int nt = 0; nt < 8; nt++)
                HMMA(sacc[nt], qf[kk][0], qf[kk][1], qf[kk][2], qf[kk][3],
                     bb[nt][0], bb[nt][1]);
        }

        float mx_lo = m_lo, mx_hi = m_hi;
        #pragma unroll
        for (int nt = 0; nt < 8; nt++) {
            sacc[nt][0] *= scale; sacc[nt][1] *= scale;
            sacc[nt][2] *= scale; sacc[nt][3] *= scale;
            mx_lo = fmaxf(mx_lo, fmaxf(sacc[nt][0], sacc[nt][1]));
            mx_hi = fmaxf(mx_hi, fmaxf(sacc[nt][2], sacc[nt][3]));
        }
        #pragma unroll
        for (int o = 1; o <= 2; o <<= 1) {
            mx_lo = fmaxf(mx_lo, __shfl_xor_sync(0xffffffffu, mx_lo, o));
            mx_hi = fmaxf(mx_hi, __shfl_xor_sync(0xffffffffu, mx_hi, o));
        }
        float f_lo = __expf(m_lo - mx_lo);
        float f_hi = __expf(m_hi - mx_hi);
        float sum_lo = 0.f, sum_hi = 0.f;
        #pragma unroll
        for (int nt = 0; nt < 8; nt++) {
            float p0 = __expf(sacc[nt][0] - mx_lo);
            float p1 = __expf(sacc[nt][1] - mx_lo);
            float p2 = __expf(sacc[nt][2] - mx_hi);
            float p3 = __expf(sacc[nt][3] - mx_hi);
            sum_lo += p0 + p1; sum_hi += p2 + p3;
            int col = nt * 8 + 2 * (lane & 3);
            *(__half2*)(Pw + (lane >> 2) * PSTH + col) = __floats2half2_rn(p0, p1);
            *(__half2*)(Pw + ((lane >> 2) + 8) * PSTH + col) = __floats2half2_rn(p2, p3);
        }
        #pragma unroll
        for (int o = 1; o <= 2; o <<= 1) {
            sum_lo += __shfl_xor_sync(0xffffffffu, sum_lo, o);
            sum_hi += __shfl_xor_sync(0xffffffffu, sum_hi, o);
        }
        l_lo = l_lo * f_lo + sum_lo;
        l_hi = l_hi * f_hi + sum_hi;
        m_lo = mx_lo; m_hi = mx_hi;
        __syncwarp();

        #pragma unroll
        for (int nt = 0; nt < 16; nt++) {
            oacc[nt][0] *= f_lo; oacc[nt][1] *= f_lo;
            oacc[nt][2] *= f_hi; oacc[nt][3] *= f_hi;
        }
        #pragma unroll
        for (int kkv = 0; kkv < 4; kkv++) {
            uint32_t pf0, pf1, pf2, pf3;
            LDSM_X4(pf0, pf1, pf2, pf3, paddr + kkv * 32);
            #pragma unroll
            for (int np = 0; np < 8; np++) {
                uint32_t v0, v1, v2, v3;
                LDSM_X4_T(v0, v1, v2, v3,
                          vaddr + kkv * (16 * KSTH * 2) + np * 32);
                HMMA(oacc[2 * np],     pf0, pf1, pf2, pf3, v0, v1);
                HMMA(oacc[2 * np + 1], pf0, pf1, pf2, pf3, v2, v3);
            }
        }
    }

    float inv_lo = 1.f / l_lo, inv_hi = 1.f / l_hi;
    int r = qt * 128 + wid * 16 + (lane >> 2);
    __half* ob0 = g_oh + ((size_t)b * SEQ + r) * INNER + h * HDIM;
    __half* ob1 = g_oh + ((size_t)b * SEQ + r + 8) * INNER + h * HDIM;
    #pragma unroll
    for (int nt = 0; nt < 16; nt++) {
        int col = nt * 8 + 2 * (lane & 3);
        *(__half2*)(ob0 + col) =
            __floats2half2_rn(oacc[nt][0] * inv_lo, oacc[nt][1] * inv_lo);
        *(__half2*)(ob1 + col) =
            __floats2half2_rn(oacc[nt][2] * inv_hi, oacc[nt][3] * inv_hi);
    }
}

// ---------------- host ----------------
extern "C" void kernel_launch(void* const* d_in, const int* in_sizes, int n_in,
                              void* d_out, int out_size) {
    const float* hid   = (const float*)d_in[0];
    const float* enc   = (const float*)d_in[1];
    const float* cosb  = (const float*)d_in[2];
    const float* sinb  = (const float*)d_in[3];
    const float* w_qkv = (const float*)d_in[4];
    const float* b_qkv = (const float*)d_in[5];
    const float* w_out = (const float*)d_in[6];
    const float* b_out = (const float*)d_in[7];
    float* out = (float*)d_out;

    __half *xhp, *ohp, *wqhp, *wohp;
    cudaGetSymbolAddress((void**)&xhp,  g_xh);
    cudaGetSymbolAddress((void**)&ohp,  g_oh);
    cudaGetSymbolAddress((void**)&wqhp, g_wqh);
    cudaGetSymbolAddress((void**)&wohp, g_woh);

    static bool attr_set = false;
    if (!attr_set) {
        cudaFuncSetAttribute(mma_gemm<0>, cudaFuncAttributeMaxDynamicSharedMemorySize,
                             (int)GEMM_SMEM);
        cudaFuncSetAttribute(mma_gemm<1>, cudaFuncAttributeMaxDynamicSharedMemorySize,
                             (int)GEMM_SMEM);
        cudaFuncSetAttribute(attn_tc_kernel, cudaFuncAttributeMaxDynamicSharedMemorySize,
                             (int)ATT_SMEM);
        attr_set = true;
    }

    // 0. transpose + round weights: W[K][N] fp32 -> WT[N][K] fp16
    {
        dim3 blk(32, 8);
        dim3 gq(3 * INNER / 32, DMODEL / 32);
        transpose_h<<<gq, blk>>>(w_qkv, wqhp, DMODEL, 3 * INNER);
        dim3 go(DMODEL / 32, INNER / 32);
        transpose_h<<<go, blk>>>(w_out, wohp, INNER, DMODEL);
    }
    // 1. concat -> fp16
    {
        int total = ROWS * DMODEL / 8;
        concat_kernel<<<(total + 255) / 256, 256>>>(hid, enc);
    }
    // 2. qkv gemm with fused bias+LN+RoPE epilogue -> fp16 q/k/v
    {
        dim3 grid(3 * INNER / 128, ROWS / 128);
        mma_gemm<0><<<grid, 256, GEMM_SMEM>>>(ROWS, 3 * INNER, DMODEL,
                                              xhp, wqhp, b_qkv, nullptr,
                                              cosb, sinb);
    }
    // 3. attention (fp16 HMMA, q-tile 128, 4-stage cp.async)
    {
        dim3 grid(SEQ / 128, HEADS, BATCH);
        attn_tc_kernel<<<grid, 256, ATT_SMEM>>>();
    }
    // 4. out proj with row remap (fp16 HMMA + ldmatrix)
    {
        dim3 grid(DMODEL / 128, ROWS / 128);
        mma_gemm<1><<<grid, 256, GEMM_SMEM>>>(ROWS, DMODEL, DMODEL,
                                              ohp, wohp, b_out, out,
                                              nullptr, nullptr);
    }
}

// round 14
// speedup vs baseline: 3.0352x; 1.1583x over previous
#include <cuda_runtime.h>
#include <cuda_fp16.h>
#include <math.h>
#include <stdint.h>

#define HEADS  24
#define HDIM   128
#define BATCH  2
#define TXT    256
#define IMG    1024
#define SEQ    1280          // TXT + IMG
#define DMODEL 3072
#define INNER  3072          // HEADS*HDIM
#define ROWS   (BATCH*SEQ)   // 2560

// ---------------- scratch (static device globals: allowed) ----------------
__device__ __half g_xh [ROWS * DMODEL];           // fp16 concat input
__device__ __half g_qh [BATCH * HEADS * SEQ * HDIM]; // fp16 q (post LN/RoPE)
__device__ __half g_kh [BATCH * HEADS * SEQ * HDIM];
__device__ __half g_vh [BATCH * HEADS * SEQ * HDIM];
__device__ __half g_oh [ROWS * INNER];            // fp16 attn out
__device__ __half g_wqh[DMODEL * 3 * INNER];      // fp16 w_qkv [K][N] (no transpose)
__device__ __half g_woh[INNER * DMODEL];          // fp16 w_out [K][N]

// ---------------- mma / ldmatrix helpers ----------------
#define LDSM_X4(R0, R1, R2, R3, A) \
    asm volatile("ldmatrix.sync.aligned.m8n8.x4.shared.b16 {%0,%1,%2,%3}, [%4];" \
                 : "=r"(R0), "=r"(R1), "=r"(R2), "=r"(R3) : "r"(A))
#define LDSM_X4_T(R0, R1, R2, R3, A) \
    asm volatile("ldmatrix.sync.aligned.m8n8.x4.trans.shared.b16 {%0,%1,%2,%3}, [%4];" \
                 : "=r"(R0), "=r"(R1), "=r"(R2), "=r"(R3) : "r"(A))
#define HMMA(D, A0, A1, A2, A3, B0, B1) \
    asm volatile("mma.sync.aligned.m16n8k16.row.col.f32.f16.f16.f32 " \
                 "{%0,%1,%2,%3}, {%4,%5,%6,%7}, {%8,%9}, {%0,%1,%2,%3};" \
                 : "+f"((D)[0]), "+f"((D)[1]), "+f"((D)[2]), "+f"((D)[3]) \
                 : "r"(A0), "r"(A1), "r"(A2), "r"(A3), "r"(B0), "r"(B1))

// ---------------- 0. elementwise fp32 -> fp16 weight convert ----------------
__global__ void convert_h(const float* __restrict__ src,
                          __half* __restrict__ dst, int n8) {
    int idx = blockIdx.x * blockDim.x + threadIdx.x;
    if (idx >= n8) return;
    float4 v0 = ((const float4*)src)[idx * 2];
    float4 v1 = ((const float4*)src)[idx * 2 + 1];
    __half2 h[4];
    h[0] = __floats2half2_rn(v0.x, v0.y);
    h[1] = __floats2half2_rn(v0.z, v0.w);
    h[2] = __floats2half2_rn(v1.x, v1.y);
    h[3] = __floats2half2_rn(v1.z, v1.w);
    ((uint4*)dst)[idx] = *(uint4*)h;
}

// ---------------- 1. concat -> fp16 ----------------
__global__ void concat_kernel(const float* __restrict__ hid,
                              const float* __restrict__ enc) {
    int idx = blockIdx.x * blockDim.x + threadIdx.x;   // 8-float chunk
    const int total = ROWS * DMODEL / 8;
    if (idx >= total) return;
    int row = idx / (DMODEL / 8);
    int c8  = idx % (DMODEL / 8);
    int b = row / SEQ, s = row % SEQ;
    const float4* src = (s < TXT)
        ? (const float4*)(enc + (size_t)(b * TXT + s) * DMODEL)
        : (const float4*)(hid + (size_t)(b * IMG + (s - TXT)) * DMODEL);
    float4 v0 = src[c8 * 2], v1 = src[c8 * 2 + 1];
    __half2 h[4];
    h[0] = __floats2half2_rn(v0.x, v0.y);
    h[1] = __floats2half2_rn(v0.z, v0.w);
    h[2] = __floats2half2_rn(v1.x, v1.y);
    h[3] = __floats2half2_rn(v1.z, v1.w);
    *(uint4*)(g_xh + (size_t)row * DMODEL + c8 * 8) = *(uint4*)h;
}

// ---------------- 2/4. FP16 GEMM (m16n8k16) ----------------
// A [M][K] fp16 (non-trans LDSM); W [K][N] fp16, B tile stored [k][n] in smem,
// fragments via ldmatrix.trans (same pattern as the attention P@V path).
// MODE 0: qkv gemm, fused bias+LN+RoPE epilogue -> fp16 g_qh/g_kh/g_vh.
// MODE 1: out-proj, bias + row-remap epilogue -> fp32 C.
#define ROWB 144                           // A smem row stride (bytes)
#define ATILE_BYTES (128 * ROWB)           // 18432
#define BROWB 272                          // B smem row stride (136 halves)
#define BTILE_BYTES (32 * BROWB)           // 8704
#define STAGE_BYTES (ATILE_BYTES + BTILE_BYTES)   // 27136
#define GEMM_SMEM ((size_t)2 * STAGE_BYTES)       // 54272

template <int MODE>
__global__ __launch_bounds__(256, 2)
void mma_gemm(int M, int N, int K,
              const __half* __restrict__ A, const __half* __restrict__ W,
              const float* __restrict__ bias, float* __restrict__ C,
              const float* __restrict__ cosb, const float* __restrict__ sinb) {
    extern __shared__ char sh[];
    uint32_t sh_u32 = (uint32_t)__cvta_generic_to_shared(sh);
    int tid  = threadIdx.x;
    int lane = tid & 31, wid = tid >> 5;
    int wm = wid >> 2;
    int wn = wid & 3;
    int bm = blockIdx.y * 128;
    int bn = blockIdx.x * 128;
    int r4 = lane >> 2, kc = lane & 3;

    const __half* Ab = A + (size_t)bm * K;
    const __half* Wb = W + bn;               // [K][N], column offset bn

    uint32_t a_off = (uint32_t)((wm * 64 + (lane & 15)) * ROWB + (lane >> 4) * 16);
    uint32_t b_off = (uint32_t)(ATILE_BYTES + (lane & 15) * BROWB + (lane >> 4) * 16);

    float acc[4][4][4];
    #pragma unroll
    for (int i = 0; i < 4; i++)
        #pragma unroll
        for (int j = 0; j < 4; j++)
            #pragma unroll
            for (int r = 0; r < 4; r++) acc[i][j][r] = 0.f;

    auto copy_tile = [&](int k0, int s) {
        char* As = sh + s * STAGE_BYTES;
        char* Bs = As + ATILE_BYTES;
        // A: 128 rows x 4 chunks (16B = 8 halves of K)
        #pragma unroll
        for (int i = 0; i < 2; i++) {
            int idx = tid + i * 256;
            int row = idx >> 2, c = idx & 3;
            uint32_t da = (uint32_t)__cvta_generic_to_shared(
                As + row * ROWB + c * 16);
            asm volatile("cp.async.cg.shared.global [%0], [%1], 16;"
                         :: "r"(da), "l"(Ab + (size_t)row * K + k0 + c * 8));
        }
        // B: 32 k-rows x 16 chunks (16B = 8 halves of N)
        #pragma unroll
        for (int i = 0; i < 2; i++) {
            int idx = tid + i * 256;
            int row = idx >> 4, c = idx & 15;
            uint32_t db = (uint32_t)__cvta_generic_to_shared(
                Bs + row * BROWB + c * 16);
            asm volatile("cp.async.cg.shared.global [%0], [%1], 16;"
                         :: "r"(db), "l"(Wb + (size_t)(k0 + row) * N + c * 8));
        }
        asm volatile("cp.async.commit_group;");
    };

    int nK = K / 32;
    copy_tile(0, 0);

    for (int kt = 0; kt < nK; kt++) {
        asm volatile("cp.async.wait_group 0;");
        __syncthreads();
        if (kt + 1 < nK) copy_tile((kt + 1) * 32, (kt + 1) & 1);

        uint32_t sb = sh_u32 + (kt & 1) * STAGE_BYTES;

        #pragma unroll
        for (int kk = 0; kk < 2; kk++) {
            uint32_t af[4][4], bf[4][2];
            #pragma unroll
            for (int mt = 0; mt < 4; mt++)
                LDSM_X4(af[mt][0], af[mt][1], af[mt][2], af[mt][3],
                        sb + a_off + mt * (16 * ROWB) + kk * 32);
            #pragma unroll
            for (int g = 0; g < 2; g++) {
                uint32_t r0, r1, r2, r3;
                LDSM_X4_T(r0, r1, r2, r3,
                          sb + b_off + kk * (16 * BROWB)
                             + (wn * 32 + g * 16) * 2);
                bf[2 * g][0] = r0; bf[2 * g][1] = r1;       // n 0-7 of group
                bf[2 * g + 1][0] = r2; bf[2 * g + 1][1] = r3; // n 8-15
            }
            #pragma unroll
            for (int mt = 0; mt < 4; mt++)
                #pragma unroll
                for (int nt = 0; nt < 4; nt++)
                    HMMA(acc[mt][nt], af[mt][0], af[mt][1], af[mt][2], af[mt][3],
                         bf[nt][0], bf[nt][1]);
        }
        __syncthreads();
    }

    // -------- epilogue --------
    {
        float bv0[4], bv1[4];
        #pragma unroll
        for (int nt = 0; nt < 4; nt++) {
            int n = bn + wn * 32 + nt * 8 + kc * 2;
            bv0[nt] = bias[n]; bv1[nt] = bias[n + 1];
        }
        #pragma unroll
        for (int mt = 0; mt < 4; mt++)
            #pragma unroll
            for (int nt = 0; nt < 4; nt++) {
                acc[mt][nt][0] += bv0[nt]; acc[mt][nt][1] += bv1[nt];
                acc[mt][nt][2] += bv0[nt]; acc[mt][nt][3] += bv1[nt];
            }
    }

    if (MODE == 1) {
        #pragma unroll
        for (int mt = 0; mt < 4; mt++)
            #pragma unroll
            for (int hf = 0; hf < 2; hf++) {
                int m = bm + wm * 64 + mt * 16 + r4 + hf * 8;
                int b = m / SEQ, s = m % SEQ;
                int orow = (s < TXT) ? (BATCH * IMG + b * TXT + s)
                                     : (b * IMG + (s - TXT));
                float* crow = C + (size_t)orow * N;
                #pragma unroll
                for (int nt = 0; nt < 4; nt++) {
                    int n = bn + wn * 32 + nt * 8 + kc * 2;
                    float2 v;
                    v.x = acc[mt][nt][hf * 2 + 0];
                    v.y = acc[mt][nt][hf * 2 + 1];
                    *(float2*)(crow + n) = v;
                }
            }
        return;
    }

    // MODE 0: this CTA's 128 cols == one head of q/k/v.
    int type = bn / INNER;               // 0=q, 1=k, 2=v
    int head = (bn % INNER) / HDIM;

    if (type == 2) {
        #pragma unroll
        for (int mt = 0; mt < 4; mt++)
            #pragma unroll
            for (int hf = 0; hf < 2; hf++) {
                int m = bm + wm * 64 + mt * 16 + r4 + hf * 8;
                int b = m / SEQ, s = m % SEQ;
                __half* dst = g_vh
                    + ((size_t)(b * HEADS + head) * SEQ + s) * HDIM;
                #pragma unroll
                for (int nt = 0; nt < 4; nt++) {
                    int d = wn * 32 + nt * 8 + kc * 2;
                    *(__half2*)(dst + d) =
                        __floats2half2_rn(acc[mt][nt][hf * 2],
                                          acc[mt][nt][hf * 2 + 1]);
                }
            }
        return;
    }

    // q/k: LayerNorm over the 128 CTA-resident cols, then RoPE.
    float2* stats = (float2*)sh;                  // [128][4]
    __half* Qs    = (__half*)(sh + 4096);         // [128][136]

    #pragma unroll
    for (int mt = 0; mt < 4; mt++)
        #pragma unroll
        for (int hf = 0; hf < 2; hf++) {
            float sum = 0.f, sq = 0.f;
            #pragma unroll
            for (int nt = 0; nt < 4; nt++) {
                float a = acc[mt][nt][hf * 2], c2 = acc[mt][nt][hf * 2 + 1];
                sum += a + c2; sq += a * a + c2 * c2;
            }
            sum += __shfl_xor_sync(0xffffffffu, sum, 1);
            sq  += __shfl_xor_sync(0xffffffffu, sq, 1);
            sum += __shfl_xor_sync(0xffffffffu, sum, 2);
            sq  += __shfl_xor_sync(0xffffffffu, sq, 2);
            if (kc == 0) {
                int rl = wm * 64 + mt * 16 + r4 + hf * 8;
                stats[rl * 4 + wn] = make_float2(sum, sq);
            }
        }
    __syncthreads();

    #pragma unroll
    for (int mt = 0; mt < 4; mt++)
        #pragma unroll
        for (int hf = 0; hf < 2; hf++) {
            int rl = wm * 64 + mt * 16 + r4 + hf * 8;
            float sum = 0.f, sq = 0.f;
            #pragma unroll
            for (int w = 0; w < 4; w++) {
                float2 p = stats[rl * 4 + w];
                sum += p.x; sq += p.y;
            }
            float mu = sum * (1.f / 128.f);
            float var = fmaxf(sq * (1.f / 128.f) - mu * mu, 0.f);
            float inv = rsqrtf(var + 1e-5f);
            #pragma unroll
            for (int nt = 0; nt < 4; nt++) {
                int d = wn * 32 + nt * 8 + kc * 2;
                Qs[rl * 136 + d] =
                    __float2half_rn((acc[mt][nt][hf * 2] - mu) * inv);
                Qs[rl * 136 + d + 1] =
                    __float2half_rn((acc[mt][nt][hf * 2 + 1] - mu) * inv);
            }
        }
    __syncthreads();

    __half* dstb = (type == 0) ? g_qh : g_kh;
    #pragma unroll
    for (int it = 0; it < 16; it++) {
        int i = tid + it * 256;
        int r = i >> 5, c4 = i & 31;
        int d0 = c4 * 4;
        int m = bm + r;
        int b = m / SEQ, s = m % SEQ;
        float x[4];
        #pragma unroll
        for (int j = 0; j < 4; j++) x[j] = __half2float(Qs[r * 136 + d0 + j]);
        if (s >= TXT) {
            int dp = d0 ^ 64;
            float sgn = (d0 < 64) ? -1.f : 1.f;
            float4 cv = *(const float4*)(cosb + (size_t)(s - TXT) * HDIM + d0);
            float4 sv = *(const float4*)(sinb + (size_t)(s - TXT) * HDIM + d0);
            float p[4];
            #pragma unroll
            for (int j = 0; j < 4; j++) p[j] = __half2float(Qs[r * 136 + dp + j]);
            x[0] = x[0] * cv.x + sgn * p[0] * sv.x;
            x[1] = x[1] * cv.y + sgn * p[1] * sv.y;
            x[2] = x[2] * cv.z + sgn * p[2] * sv.z;
            x[3] = x[3] * cv.w + sgn * p[3] * sv.w;
        }
        __half* dst = dstb + ((size_t)(b * HEADS + head) * SEQ + s) * HDIM + d0;
        ((__half2*)dst)[0] = __floats2half2_rn(x[0], x[1]);
        ((__half2*)dst)[1] = __floats2half2_rn(x[2], x[3]);
    }
}

// ---------------- 3. flash attention, fp16 TC, 2-stage, 2 CTA/SM -----------
// 128 threads / 4 warps; q-tile 64 (16 rows/warp), kv-tile 64, D=128.
#define KSTH 136
#define PSTH 72
#define KV_STAGE_H (2 * 64 * KSTH)            // 17408 halves
#define KV_STAGE_B (KV_STAGE_H * 2)           // 34816 B
#define ATT_NKV (SEQ / 64)                    // 20
#define ATT_SMEM ((size_t)(2 * KV_STAGE_H + 4 * 16 * PSTH) * 2)   // 78848 B

__global__ __launch_bounds__(128)
void attn_tc_kernel() {
    extern __shared__ __half smh[];
    uint32_t sm_u32 = (uint32_t)__cvta_generic_to_shared(smh);
    __half* Ps = smh + 2 * KV_STAGE_H;

    int qt = blockIdx.x, h = blockIdx.y, b = blockIdx.z;
    int tid = threadIdx.x, lane = tid & 31, wid = tid >> 5;
    size_t hb = (size_t)(b * HEADS + h) * SEQ * HDIM;
    const __half* qb = g_qh + hb + (size_t)qt * 64 * HDIM;
    const __half* kb = g_kh + hb;
    const __half* vb = g_vh + hb;

    __half* Pw = Ps + wid * 16 * PSTH;
    uint32_t pw_u32 = (uint32_t)__cvta_generic_to_shared(Pw);
    uint32_t paddr = pw_u32 + (lane & 15) * (PSTH * 2) + (lane >> 4) * 16;

    // ---- stage Q into stage-0 region (sync loads), extract fragments ----
    for (int i = tid; i < 64 * 16; i += 128) {
        int r = i >> 4, c = i & 15;
        *(uint4*)(smh + r * KSTH + c * 8) =
            *(const uint4*)(qb + (size_t)r * HDIM + c * 8);
    }
    __syncthreads();
    uint32_t qf[8][4];
    {
        uint32_t qaddr = sm_u32 + (wid * 16 + (lane & 15)) * (KSTH * 2)
                       + (lane >> 4) * 16;
        #pragma unroll
        for (int kk = 0; kk < 8; kk++)
            LDSM_X4(qf[kk][0], qf[kk][1], qf[kk][2], qf[kk][3], qaddr + kk * 32);
    }
    __syncthreads();

    // ---- cp.async K/V tile copy ----
    auto copy_kv = [&](int kt, int s) {
        uint32_t kbase = sm_u32 + s * KV_STAGE_B;
        uint32_t vbase = kbase + 64 * KSTH * 2;
        #pragma unroll
        for (int i = 0; i < 8; i++) {
            int idx = tid + i * 128;          // 0..1023
            int row = idx >> 4, c = idx & 15;
            const __half* srck = kb + (size_t)(kt * 64 + row) * HDIM + c * 8;
            const __half* srcv = vb + (size_t)(kt * 64 + row) * HDIM + c * 8;
            asm volatile("cp.async.cg.shared.global [%0], [%1], 16;"
                         :: "r"(kbase + row * (KSTH * 2) + c * 16), "l"(srck));
            asm volatile("cp.async.cg.shared.global [%0], [%1], 16;"
                         :: "r"(vbase + row * (KSTH * 2) + c * 16), "l"(srcv));
        }
        asm volatile("cp.async.commit_group;");
    };

    copy_kv(0, 0);

    float oacc[16][4];
    #pragma unroll
    for (int nt = 0; nt < 16; nt++)
        #pragma unroll
        for (int r = 0; r < 4; r++) oacc[nt][r] = 0.f;

    float m_lo = -INFINITY, m_hi = -INFINITY, l_lo = 0.f, l_hi = 0.f;
    const float scale = 0.08838834764831845f;

    for (int kt = 0; kt < ATT_NKV; kt++) {
        asm volatile("cp.async.wait_group 0;");
        __syncthreads();
        if (kt + 1 < ATT_NKV) copy_kv(kt + 1, (kt + 1) & 1);

        uint32_t kbase = sm_u32 + (kt & 1) * KV_STAGE_B;
        uint32_t kaddr = kbase + (lane & 15) * (KSTH * 2) + (lane >> 4) * 16;
        uint32_t vaddr = kbase + 64 * KSTH * 2
                       + (lane & 15) * (KSTH * 2) + (lane >> 4) * 16;

        // ---- S = Q @ K^T (16 x 64 per warp) ----
        float sacc[8][4];
        #pragma unroll
        for (int nt = 0; nt < 8; nt++)
            #pragma unroll
            for (int r = 0; r < 4; r++) sacc[nt][r] = 0.f;

        #pragma unroll
        for (int kk = 0; kk < 8; kk++) {
            uint32_t bb[8][2];
            #pragma unroll
            for (int g = 0; g < 4; g++) {
                uint32_t r0, r1, r2, r3;
                LDSM_X4(r0, r1, r2, r3, kaddr + g * (16 * KSTH * 2) + kk * 32);
                bb[2 * g][0] = r0; bb[2 * g][1] = r2;
                bb[2 * g + 1][0] = r1; bb[2 * g + 1][1] = r3;
            }
            #pragma unroll
            for (int nt = 0; nt < 8; nt++)
                HMMA(sacc[nt], qf[kk][0], qf[kk][1], qf[kk][2], qf[kk][3],
                     bb[nt][0], bb[nt][1]);
        }

        // ---- online softmax ----
        float mx_lo = m_lo, mx_hi = m_hi;
        #pragma unroll
        for (int nt = 0; nt < 8; nt++) {
            sacc[nt][0] *= scale; sacc[nt][1] *= scale;
            sacc[nt][2] *= scale; sacc[nt][3] *= scale;
            mx_lo = fmaxf(mx_lo, fmaxf(sacc[nt][0], sacc[nt][1]));
            mx_hi = fmaxf(mx_hi, fmaxf(sacc[nt][2], sacc[nt][3]));
        }
        #pragma unroll
        for (int o = 1; o <= 2; o <<= 1) {
            mx_lo = fmaxf(mx_lo, __shfl_xor_sync(0xffffffffu, mx_lo, o));
            mx_hi = fmaxf(mx_hi, __shfl_xor_sync(0xffffffffu, mx_hi, o));
        }
        float f_lo = __expf(m_lo - mx_lo);
        float f_hi = __expf(m_hi - mx_hi);
        float sum_lo = 0.f, sum_hi = 0.f;
        #pragma unroll
        for (int nt = 0; nt < 8; nt++) {
            float p0 = __expf(sacc[nt][0] - mx_lo);
            float p1 = __expf(sacc[nt][1] - mx_lo);
            float p2 = __expf(sacc[nt][2] - mx_hi);
            float p3 = __expf(sacc[nt][3] - mx_hi);
            sum_lo += p0 + p1; sum_hi += p2 + p3;
            int col = nt * 8 + 2 * (lane & 3);
            *(__half2*)(Pw + (lane >> 2) * PSTH + col) = __floats2half2_rn(p0, p1);
            *(__half2*)(Pw + ((lane >> 2) + 8) * PSTH + col) = __floats2half2_rn(p2, p3);
        }
        #pragma unroll
        for (int o = 1; o <= 2; o <<= 1) {
            sum_lo += __shfl_xor_sync(0xffffffffu, sum_lo, o);
            sum_hi += __shfl_xor_sync(0xffffffffu, sum_hi, o);
        }
        l_lo = l_lo * f_lo + sum_lo;
        l_hi = l_hi * f_hi + sum_hi;
        m_lo = mx_lo; m_hi = mx_hi;
        __syncwarp();

        // ---- rescale O, then O += P @ V (ldmatrix.trans for V) ----
        #pragma unroll
        for (int nt = 0; nt < 16; nt++) {
            oacc[nt][0] *= f_lo; oacc[nt][1] *= f_lo;
            oacc[nt][2] *= f_hi; oacc[nt][3] *= f_hi;
        }
        #pragma unroll
        for (int kkv = 0; kkv < 4; kkv++) {
            uint32_t pf0, pf1, pf2, pf3;
            LDSM_X4(pf0, pf1, pf2, pf3, paddr + kkv * 32);
            #pragma unroll
            for (int np = 0; np < 8; np++) {
                uint32_t v0, v1, v2, v3;
                LDSM_X4_T(v0, v1, v2, v3,
                          vaddr + kkv * (16 * KSTH * 2) + np * 32);
                HMMA(oacc[2 * np],     pf0, pf1, pf2, pf3, v0, v1);
                HMMA(oacc[2 * np + 1], pf0, pf1, pf2, pf3, v2, v3);
            }
        }
    }

    // ---- epilogue ----
    float inv_lo = 1.f / l_lo, inv_hi = 1.f / l_hi;
    int r = qt * 64 + wid * 16 + (lane >> 2);
    __half* ob0 = g_oh + ((size_t)b * SEQ + r) * INNER + h * HDIM;
    __half* ob1 = g_oh + ((size_t)b * SEQ + r + 8) * INNER + h * HDIM;
    #pragma unroll
    for (int nt = 0; nt < 16; nt++) {
        int col = nt * 8 + 2 * (lane & 3);
        *(__half2*)(ob0 + col) =
            __floats2half2_rn(oacc[nt][0] * inv_lo, oacc[nt][1] * inv_lo);
        *(__half2*)(ob1 + col) =
            __floats2half2_rn(oacc[nt][2] * inv_hi, oacc[nt][3] * inv_hi);
    }
}

// ---------------- host ----------------
extern "C" void kernel_launch(void* const* d_in, const int* in_sizes, int n_in,
                              void* d_out, int out_size) {
    const float* hid   = (const float*)d_in[0];
    const float* enc   = (const float*)d_in[1];
    const float* cosb  = (const float*)d_in[2];
    const float* sinb  = (const float*)d_in[3];
    const float* w_qkv = (const float*)d_in[4];
    const float* b_qkv = (const float*)d_in[5];
    const float* w_out = (const float*)d_in[6];
    const float* b_out = (const float*)d_in[7];
    float* out = (float*)d_out;

    __half *xhp, *ohp, *wqhp, *wohp;
    cudaGetSymbolAddress((void**)&xhp,  g_xh);
    cudaGetSymbolAddress((void**)&ohp,  g_oh);
    cudaGetSymbolAddress((void**)&wqhp, g_wqh);
    cudaGetSymbolAddress((void**)&wohp, g_woh);

    static bool attr_set = false;
    if (!attr_set) {
        cudaFuncSetAttribute(mma_gemm<0>, cudaFuncAttributeMaxDynamicSharedMemorySize,
                             (int)GEMM_SMEM);
        cudaFuncSetAttribute(mma_gemm<1>, cudaFuncAttributeMaxDynamicSharedMemorySize,
                             (int)GEMM_SMEM);
        cudaFuncSetAttribute(attn_tc_kernel, cudaFuncAttributeMaxDynamicSharedMemorySize,
                             (int)ATT_SMEM);
        attr_set = true;
    }

    // 0. weights fp32 -> fp16, layout preserved [K][N]
    {
        int n8q = DMODEL * 3 * INNER / 8;
        convert_h<<<(n8q + 255) / 256, 256>>>(w_qkv, wqhp, n8q);
        int n8o = INNER * DMODEL / 8;
        convert_h<<<(n8o + 255) / 256, 256>>>(w_out, wohp, n8o);
    }
    // 1. concat -> fp16
    {
        int total = ROWS * DMODEL / 8;
        concat_kernel<<<(total + 255) / 256, 256>>>(hid, enc);
    }
    // 2. qkv gemm with fused bias+LN+RoPE epilogue -> fp16 q/k/v
    {
        dim3 grid(3 * INNER / 128, ROWS / 128);
        mma_gemm<0><<<grid, 256, GEMM_SMEM>>>(ROWS, 3 * INNER, DMODEL,
                                              xhp, wqhp, b_qkv, nullptr,
                                              cosb, sinb);
    }
    // 3. attention (fp16 HMMA, q-tile 64, 2-stage pipeline, 2 CTA/SM)
    {
        dim3 grid(SEQ / 64, HEADS, BATCH);
        attn_tc_kernel<<<grid, 128, ATT_SMEM>>>();
    }
    // 4. out proj with row remap
    {
        dim3 grid(DMODEL / 128, ROWS / 128);
        mma_gemm<1><<<grid, 256, GEMM_SMEM>>>(ROWS, DMODEL, DMODEL,
                                              ohp, wohp, b_out, out,
                                              nullptr, nullptr);
    }
}

// round 15
// speedup vs baseline: 3.1689x; 1.0440x over previous
#include <cuda_runtime.h>
#include <cuda_fp16.h>
#include <math.h>
#include <stdint.h>

#define HEADS  24
#define HDIM   128
#define BATCH  2
#define TXT    256
#define IMG    1024
#define SEQ    1280          // TXT + IMG
#define DMODEL 3072
#define INNER  3072          // HEADS*HDIM
#define ROWS   (BATCH*SEQ)   // 2560

// ---------------- scratch (static device globals: allowed) ----------------
__device__ __half g_xh [ROWS * DMODEL];           // fp16 concat input
__device__ __half g_qh [BATCH * HEADS * SEQ * HDIM]; // fp16 q (post LN/RoPE)
__device__ __half g_kh [BATCH * HEADS * SEQ * HDIM];
__device__ __half g_vh [BATCH * HEADS * SEQ * HDIM];
__device__ __half g_oh [ROWS * INNER];            // fp16 attn out
__device__ __half g_wqh[DMODEL * 3 * INNER];      // fp16 w_qkv [K][N]
__device__ __half g_woh[INNER * DMODEL];          // fp16 w_out [K][N]

// ---------------- mma / ldmatrix helpers ----------------
#define LDSM_X4(R0, R1, R2, R3, A) \
    asm volatile("ldmatrix.sync.aligned.m8n8.x4.shared.b16 {%0,%1,%2,%3}, [%4];" \
                 : "=r"(R0), "=r"(R1), "=r"(R2), "=r"(R3) : "r"(A))
#define LDSM_X4_T(R0, R1, R2, R3, A) \
    asm volatile("ldmatrix.sync.aligned.m8n8.x4.trans.shared.b16 {%0,%1,%2,%3}, [%4];" \
                 : "=r"(R0), "=r"(R1), "=r"(R2), "=r"(R3) : "r"(A))
#define HMMA(D, A0, A1, A2, A3, B0, B1) \
    asm volatile("mma.sync.aligned.m16n8k16.row.col.f32.f16.f16.f32 " \
                 "{%0,%1,%2,%3}, {%4,%5,%6,%7}, {%8,%9}, {%0,%1,%2,%3};" \
                 : "+f"((D)[0]), "+f"((D)[1]), "+f"((D)[2]), "+f"((D)[3]) \
                 : "r"(A0), "r"(A1), "r"(A2), "r"(A3), "r"(B0), "r"(B1))

// ---------------- 0. elementwise fp32 -> fp16 weight convert ----------------
__global__ void convert_h(const float* __restrict__ src,
                          __half* __restrict__ dst, int n8) {
    int idx = blockIdx.x * blockDim.x + threadIdx.x;
    if (idx >= n8) return;
    float4 v0 = ((const float4*)src)[idx * 2];
    float4 v1 = ((const float4*)src)[idx * 2 + 1];
    __half2 h[4];
    h[0] = __floats2half2_rn(v0.x, v0.y);
    h[1] = __floats2half2_rn(v0.z, v0.w);
    h[2] = __floats2half2_rn(v1.x, v1.y);
    h[3] = __floats2half2_rn(v1.z, v1.w);
    ((uint4*)dst)[idx] = *(uint4*)h;
}

// ---------------- 1. concat -> fp16 ----------------
__global__ void concat_kernel(const float* __restrict__ hid,
                              const float* __restrict__ enc) {
    int idx = blockIdx.x * blockDim.x + threadIdx.x;   // 8-float chunk
    const int total = ROWS * DMODEL / 8;
    if (idx >= total) return;
    int row = idx / (DMODEL / 8);
    int c8  = idx % (DMODEL / 8);
    int b = row / SEQ, s = row % SEQ;
    const float4* src = (s < TXT)
        ? (const float4*)(enc + (size_t)(b * TXT + s) * DMODEL)
        : (const float4*)(hid + (size_t)(b * IMG + (s - TXT)) * DMODEL);
    float4 v0 = src[c8 * 2], v1 = src[c8 * 2 + 1];
    __half2 h[4];
    h[0] = __floats2half2_rn(v0.x, v0.y);
    h[1] = __floats2half2_rn(v0.z, v0.w);
    h[2] = __floats2half2_rn(v1.x, v1.y);
    h[3] = __floats2half2_rn(v1.z, v1.w);
    *(uint4*)(g_xh + (size_t)row * DMODEL + c8 * 8) = *(uint4*)h;
}

// ---------------- 2/4. FP16 GEMM (m16n8k16, BK=64) ----------------
// A [M][K] fp16 (non-trans LDSM, row = 64 halves @ stride 144B);
// W [K][N] fp16, B tile [64 k-rows][128 n] in smem, trans-LDSM fragments.
// MODE 0: qkv gemm, fused bias+LN+RoPE epilogue -> fp16 g_qh/g_kh/g_vh.
// MODE 1: out-proj, bias + row-remap epilogue -> fp32 C.
#define BK 64
#define ROWB 144                           // A smem row stride (bytes)
#define ATILE_BYTES (128 * ROWB)           // 18432
#define BROWB 272                          // B smem row stride (136 halves)
#define BTILE_BYTES (BK * BROWB)           // 17408
#define STAGE_BYTES (ATILE_BYTES + BTILE_BYTES)   // 35840
#define GEMM_SMEM ((size_t)2 * STAGE_BYTES)       // 71680

template <int MODE>
__global__ __launch_bounds__(256, 2)
void mma_gemm(int M, int N, int K,
              const __half* __restrict__ A, const __half* __restrict__ W,
              const float* __restrict__ bias, float* __restrict__ C,
              const float* __restrict__ cosb, const float* __restrict__ sinb) {
    extern __shared__ char sh[];
    uint32_t sh_u32 = (uint32_t)__cvta_generic_to_shared(sh);
    int tid  = threadIdx.x;
    int lane = tid & 31, wid = tid >> 5;
    int wm = wid >> 2;
    int wn = wid & 3;
    int bm = blockIdx.y * 128;
    int bn = blockIdx.x * 128;
    int r4 = lane >> 2, kc = lane & 3;

    const __half* Ab = A + (size_t)bm * K;
    const __half* Wb = W + bn;               // [K][N], column offset bn

    uint32_t a_off = (uint32_t)((wm * 64 + (lane & 15)) * ROWB + (lane >> 4) * 16);
    uint32_t b_off = (uint32_t)(ATILE_BYTES + (lane & 15) * BROWB + (lane >> 4) * 16);

    float acc[4][4][4];
    #pragma unroll
    for (int i = 0; i < 4; i++)
        #pragma unroll
        for (int j = 0; j < 4; j++)
            #pragma unroll
            for (int r = 0; r < 4; r++) acc[i][j][r] = 0.f;

    auto copy_tile = [&](int k0, int s) {
        char* As = sh + s * STAGE_BYTES;
        char* Bs = As + ATILE_BYTES;
        // A: 128 rows x 8 chunks (16B = 8 halves of K)
        #pragma unroll
        for (int i = 0; i < 4; i++) {
            int idx = tid + i * 256;          // 0..1023
            int row = idx >> 3, c = idx & 7;
            uint32_t da = (uint32_t)__cvta_generic_to_shared(
                As + row * ROWB + c * 16);
            asm volatile("cp.async.cg.shared.global [%0], [%1], 16;"
                         :: "r"(da), "l"(Ab + (size_t)row * K + k0 + c * 8));
        }
        // B: 64 k-rows x 16 chunks (16B = 8 halves of N)
        #pragma unroll
        for (int i = 0; i < 4; i++) {
            int idx = tid + i * 256;          // 0..1023
            int row = idx >> 4, c = idx & 15;
            uint32_t db = (uint32_t)__cvta_generic_to_shared(
                Bs + row * BROWB + c * 16);
            asm volatile("cp.async.cg.shared.global [%0], [%1], 16;"
                         :: "r"(db), "l"(Wb + (size_t)(k0 + row) * N + c * 8));
        }
        asm volatile("cp.async.commit_group;");
    };

    int nK = K / BK;
    copy_tile(0, 0);

    for (int kt = 0; kt < nK; kt++) {
        asm volatile("cp.async.wait_group 0;");
        __syncthreads();
        if (kt + 1 < nK) copy_tile((kt + 1) * BK, (kt + 1) & 1);

        uint32_t sb = sh_u32 + (kt & 1) * STAGE_BYTES;

        #pragma unroll
        for (int kk = 0; kk < 4; kk++) {          // four k16 steps per BK=64
            uint32_t af[4][4], bf[4][2];
            #pragma unroll
            for (int mt = 0; mt < 4; mt++)
                LDSM_X4(af[mt][0], af[mt][1], af[mt][2], af[mt][3],
                        sb + a_off + mt * (16 * ROWB) + kk * 32);
            #pragma unroll
            for (int g = 0; g < 2; g++) {
                uint32_t r0, r1, r2, r3;
                LDSM_X4_T(r0, r1, r2, r3,
                          sb + b_off + kk * (16 * BROWB)
                             + (wn * 32 + g * 16) * 2);
                bf[2 * g][0] = r0; bf[2 * g][1] = r1;
                bf[2 * g + 1][0] = r2; bf[2 * g + 1][1] = r3;
            }
            #pragma unroll
            for (int mt = 0; mt < 4; mt++)
                #pragma unroll
                for (int nt = 0; nt < 4; nt++)
                    HMMA(acc[mt][nt], af[mt][0], af[mt][1], af[mt][2], af[mt][3],
                         bf[nt][0], bf[nt][1]);
        }
        __syncthreads();
    }

    // -------- epilogue --------
    {
        float bv0[4], bv1[4];
        #pragma unroll
        for (int nt = 0; nt < 4; nt++) {
            int n = bn + wn * 32 + nt * 8 + kc * 2;
            bv0[nt] = bias[n]; bv1[nt] = bias[n + 1];
        }
        #pragma unroll
        for (int mt = 0; mt < 4; mt++)
            #pragma unroll
            for (int nt = 0; nt < 4; nt++) {
                acc[mt][nt][0] += bv0[nt]; acc[mt][nt][1] += bv1[nt];
                acc[mt][nt][2] += bv0[nt]; acc[mt][nt][3] += bv1[nt];
            }
    }

    if (MODE == 1) {
        #pragma unroll
        for (int mt = 0; mt < 4; mt++)
            #pragma unroll
            for (int hf = 0; hf < 2; hf++) {
                int m = bm + wm * 64 + mt * 16 + r4 + hf * 8;
                int b = m / SEQ, s = m % SEQ;
                int orow = (s < TXT) ? (BATCH * IMG + b * TXT + s)
                                     : (b * IMG + (s - TXT));
                float* crow = C + (size_t)orow * N;
                #pragma unroll
                for (int nt = 0; nt < 4; nt++) {
                    int n = bn + wn * 32 + nt * 8 + kc * 2;
                    float2 v;
                    v.x = acc[mt][nt][hf * 2 + 0];
                    v.y = acc[mt][nt][hf * 2 + 1];
                    *(float2*)(crow + n) = v;
                }
            }
        return;
    }

    // MODE 0: this CTA's 128 cols == one head of q/k/v.
    int type = bn / INNER;               // 0=q, 1=k, 2=v
    int head = (bn % INNER) / HDIM;

    if (type == 2) {
        #pragma unroll
        for (int mt = 0; mt < 4; mt++)
            #pragma unroll
            for (int hf = 0; hf < 2; hf++) {
                int m = bm + wm * 64 + mt * 16 + r4 + hf * 8;
                int b = m / SEQ, s = m % SEQ;
                __half* dst = g_vh
                    + ((size_t)(b * HEADS + head) * SEQ + s) * HDIM;
                #pragma unroll
                for (int nt = 0; nt < 4; nt++) {
                    int d = wn * 32 + nt * 8 + kc * 2;
                    *(__half2*)(dst + d) =
                        __floats2half2_rn(acc[mt][nt][hf * 2],
                                          acc[mt][nt][hf * 2 + 1]);
                }
            }
        return;
    }

    // q/k: LayerNorm over the 128 CTA-resident cols, then RoPE.
    float2* stats = (float2*)sh;                  // [128][4]
    __half* Qs    = (__half*)(sh + 4096);         // [128][136]

    #pragma unroll
    for (int mt = 0; mt < 4; mt++)
        #pragma unroll
        for (int hf = 0; hf < 2; hf++) {
            float sum = 0.f, sq = 0.f;
            #pragma unroll
            for (int nt = 0; nt < 4; nt++) {
                float a = acc[mt][nt][hf * 2], c2 = acc[mt][nt][hf * 2 + 1];
                sum += a + c2; sq += a * a + c2 * c2;
            }
            sum += __shfl_xor_sync(0xffffffffu, sum, 1);
            sq  += __shfl_xor_sync(0xffffffffu, sq, 1);
            sum += __shfl_xor_sync(0xffffffffu, sum, 2);
            sq  += __shfl_xor_sync(0xffffffffu, sq, 2);
            if (kc == 0) {
                int rl = wm * 64 + mt * 16 + r4 + hf * 8;
                stats[rl * 4 + wn] = make_float2(sum, sq);
            }
        }
    __syncthreads();

    #pragma unroll
    for (int mt = 0; mt < 4; mt++)
        #pragma unroll
        for (int hf = 0; hf < 2; hf++) {
            int rl = wm * 64 + mt * 16 + r4 + hf * 8;
            float sum = 0.f, sq = 0.f;
            #pragma unroll
            for (int w = 0; w < 4; w++) {
                float2 p = stats[rl * 4 + w];
                sum += p.x; sq += p.y;
            }
            float mu = sum * (1.f / 128.f);
            float var = fmaxf(sq * (1.f / 128.f) - mu * mu, 0.f);
            float inv = rsqrtf(var + 1e-5f);
            #pragma unroll
            for (int nt = 0; nt < 4; nt++) {
                int d = wn * 32 + nt * 8 + kc * 2;
                Qs[rl * 136 + d] =
                    __float2half_rn((acc[mt][nt][hf * 2] - mu) * inv);
                Qs[rl * 136 + d + 1] =
                    __float2half_rn((acc[mt][nt][hf * 2 + 1] - mu) * inv);
            }
        }
    __syncthreads();

    __half* dstb = (type == 0) ? g_qh : g_kh;
    #pragma unroll
    for (int it = 0; it < 16; it++) {
        int i = tid + it * 256;
        int r = i >> 5, c4 = i & 31;
        int d0 = c4 * 4;
        int m = bm + r;
        int b = m / SEQ, s = m % SEQ;
        float x[4];
        #pragma unroll
        for (int j = 0; j < 4; j++) x[j] = __half2float(Qs[r * 136 + d0 + j]);
        if (s >= TXT) {
            int dp = d0 ^ 64;
            float sgn = (d0 < 64) ? -1.f : 1.f;
            float4 cv = *(const float4*)(cosb + (size_t)(s - TXT) * HDIM + d0);
            float4 sv = *(const float4*)(sinb + (size_t)(s - TXT) * HDIM + d0);
            float p[4];
            #pragma unroll
            for (int j = 0; j < 4; j++) p[j] = __half2float(Qs[r * 136 + dp + j]);
            x[0] = x[0] * cv.x + sgn * p[0] * sv.x;
            x[1] = x[1] * cv.y + sgn * p[1] * sv.y;
            x[2] = x[2] * cv.z + sgn * p[2] * sv.z;
            x[3] = x[3] * cv.w + sgn * p[3] * sv.w;
        }
        __half* dst = dstb + ((size_t)(b * HEADS + head) * SEQ + s) * HDIM + d0;
        ((__half2*)dst)[0] = __floats2half2_rn(x[0], x[1]);
        ((__half2*)dst)[1] = __floats2half2_rn(x[2], x[3]);
    }
}

// ---------------- 3. flash attention, fp16 TC, 2-stage, 2 CTA/SM -----------
#define KSTH 136
#define PSTH 72
#define KV_STAGE_H (2 * 64 * KSTH)            // 17408 halves
#define KV_STAGE_B (KV_STAGE_H * 2)           // 34816 B
#define ATT_NKV (SEQ / 64)                    // 20
#define ATT_SMEM ((size_t)(2 * KV_STAGE_H + 4 * 16 * PSTH) * 2)   // 78848 B

__global__ __launch_bounds__(128)
void attn_tc_kernel() {
    extern __shared__ __half smh[];
    uint32_t sm_u32 = (uint32_t)__cvta_generic_to_shared(smh);
    __half* Ps = smh + 2 * KV_STAGE_H;

    int qt = blockIdx.x, h = blockIdx.y, b = blockIdx.z;
    int tid = threadIdx.x, lane = tid & 31, wid = tid >> 5;
    size_t hb = (size_t)(b * HEADS + h) * SEQ * HDIM;
    const __half* qb = g_qh + hb + (size_t)qt * 64 * HDIM;
    const __half* kb = g_kh + hb;
    const __half* vb = g_vh + hb;

    __half* Pw = Ps + wid * 16 * PSTH;
    uint32_t pw_u32 = (uint32_t)__cvta_generic_to_shared(Pw);
    uint32_t paddr = pw_u32 + (lane & 15) * (PSTH * 2) + (lane >> 4) * 16;

    for (int i = tid; i < 64 * 16; i += 128) {
        int r = i >> 4, c = i & 15;
        *(uint4*)(smh + r * KSTH + c * 8) =
            *(const uint4*)(qb + (size_t)r * HDIM + c * 8);
    }
    __syncthreads();
    uint32_t qf[8][4];
    {
        uint32_t qaddr = sm_u32 + (wid * 16 + (lane & 15)) * (KSTH * 2)
                       + (lane >> 4) * 16;
        #pragma unroll
        for (int kk = 0; kk < 8; kk++)
            LDSM_X4(qf[kk][0], qf[kk][1], qf[kk][2], qf[kk][3], qaddr + kk * 32);
    }
    __syncthreads();

    auto copy_kv = [&](int kt, int s) {
        uint32_t kbase = sm_u32 + s * KV_STAGE_B;
        uint32_t vbase = kbase + 64 * KSTH * 2;
        #pragma unroll
        for (int i = 0; i < 8; i++) {
            int idx = tid + i * 128;
            int row = idx >> 4, c = idx & 15;
            const __half* srck = kb + (size_t)(kt * 64 + row) * HDIM + c * 8;
            const __half* srcv = vb + (size_t)(kt * 64 + row) * HDIM + c * 8;
            asm volatile("cp.async.cg.shared.global [%0], [%1], 16;"
                         :: "r"(kbase + row * (KSTH * 2) + c * 16), "l"(srck));
            asm volatile("cp.async.cg.shared.global [%0], [%1], 16;"
                         :: "r"(vbase + row * (KSTH * 2) + c * 16), "l"(srcv));
        }
        asm volatile("cp.async.commit_group;");
    };

    copy_kv(0, 0);

    float oacc[16][4];
    #pragma unroll
    for (int nt = 0; nt < 16; nt++)
        #pragma unroll
        for (int r = 0; r < 4; r++) oacc[nt][r] = 0.f;

    float m_lo = -INFINITY, m_hi = -INFINITY, l_lo = 0.f, l_hi = 0.f;
    const float scale = 0.08838834764831845f;

    for (int kt = 0; kt < ATT_NKV; kt++) {
        asm volatile("cp.async.wait_group 0;");
        __syncthreads();
        if (kt + 1 < ATT_NKV) copy_kv(kt + 1, (kt + 1) & 1);

        uint32_t kbase = sm_u32 + (kt & 1) * KV_STAGE_B;
        uint32_t kaddr = kbase + (lane & 15) * (KSTH * 2) + (lane >> 4) * 16;
        uint32_t vaddr = kbase + 64 * KSTH * 2
                       + (lane & 15) * (KSTH * 2) + (lane >> 4) * 16;

        float sacc[8][4];
        #pragma unroll
        for (int nt = 0; nt < 8; nt++)
            #pragma unroll
            for (int r = 0; r < 4; r++) sacc[nt][r] = 0.f;

        #pragma unroll
        for (int kk = 0; kk < 8; kk++) {
            uint32_t bb[8][2];
            #pragma unroll
            for (int g = 0; g < 4; g++) {
                uint32_t r0, r1, r2, r3;
                LDSM_X4(r0, r1, r2, r3, kaddr + g * (16 * KSTH * 2) + kk * 32);
                bb[2 * g][0] = r0; bb[2 * g][1] = r2;
                bb[2 * g + 1][0] = r1; bb[2 * g + 1][1] = r3;
            }
            #pragma unroll
            for (int nt = 0; nt < 8; nt++)
                HMMA(sacc[nt], qf[kk][0], qf[kk][1], qf[kk][2], qf[kk][3],
                     bb[nt][0], bb[nt][1]);
        }

        float mx_lo = m_lo, mx_hi = m_hi;
        #pragma unroll
        for (int nt = 0; nt < 8; nt++) {
            sacc[nt][0] *= scale; sacc[nt][1] *= scale;
            sacc[nt][2] *= scale; sacc[nt][3] *= scale;
            mx_lo = fmaxf(mx_lo, fmaxf(sacc[nt][0], sacc[nt][1]));
            mx_hi = fmaxf(mx_hi, fmaxf(sacc[nt][2], sacc[nt][3]));
        }
        #pragma unroll
        for (int o = 1; o <= 2; o <<= 1) {
            mx_lo = fmaxf(mx_lo, __shfl_xor_sync(0xffffffffu, mx_lo, o));
            mx_hi = fmaxf(mx_hi, __shfl_xor_sync(0xffffffffu, mx_hi, o));
        }
        float f_lo = __expf(m_lo - mx_lo);
        float f_hi = __expf(m_hi - mx_hi);
        float sum_lo = 0.f, sum_hi = 0.f;
        #pragma unroll
        for (int nt = 0; nt < 8; nt++) {
            float p0 = __expf(sacc[nt][0] - mx_lo);
            float p1 = __expf(sacc[nt][1] - mx_lo);
            float p2 = __expf(sacc[nt][2] - mx_hi);
            float p3 = __expf(sacc[nt][3] - mx_hi);
            sum_lo += p0 + p1; sum_hi += p2 + p3;
            int col = nt * 8 + 2 * (lane & 3);
            *(__half2*)(Pw + (lane >> 2) * PSTH + col) = __floats2half2_rn(p0, p1);
            *(__half2*)(Pw + ((lane >> 2) + 8) * PSTH + col) = __floats2half2_rn(p2, p3);
        }
        #pragma unroll
        for (int o = 1; o <= 2; o <<= 1) {
            sum_lo += __shfl_xor_sync(0xffffffffu, sum_lo, o);
            sum_hi += __shfl_xor_sync(0xffffffffu, sum_hi, o);
        }
        l_lo = l_lo * f_lo + sum_lo;
        l_hi = l_hi * f_hi + sum_hi;
        m_lo = mx_lo; m_hi = mx_hi;
        __syncwarp();

        #pragma unroll
        for (int nt = 0; nt < 16; nt++) {
            oacc[nt][0] *= f_lo; oacc[nt][1] *= f_lo;
            oacc[nt][2] *= f_hi; oacc[nt][3] *= f_hi;
        }
        #pragma unroll
        for (int kkv = 0; kkv < 4; kkv++) {
            uint32_t pf0, pf1, pf2, pf3;
            LDSM_X4(pf0, pf1, pf2, pf3, paddr + kkv * 32);
            #pragma unroll
            for (int np = 0; np < 8; np++) {
                uint32_t v0, v1, v2, v3;
                LDSM_X4_T(v0, v1, v2, v3,
                          vaddr + kkv * (16 * KSTH * 2) + np * 32);
                HMMA(oacc[2 * np],     pf0, pf1, pf2, pf3, v0, v1);
                HMMA(oacc[2 * np + 1], pf0, pf1, pf2, pf3, v2, v3);
            }
        }
    }

    float inv_lo = 1.f / l_lo, inv_hi = 1.f / l_hi;
    int r = qt * 64 + wid * 16 + (lane >> 2);
    __half* ob0 = g_oh + ((size_t)b * SEQ + r) * INNER + h * HDIM;
    __half* ob1 = g_oh + ((size_t)b * SEQ + r + 8) * INNER + h * HDIM;
    #pragma unroll
    for (int nt = 0; nt < 16; nt++) {
        int col = nt * 8 + 2 * (lane & 3);
        *(__half2*)(ob0 + col) =
            __floats2half2_rn(oacc[nt][0] * inv_lo, oacc[nt][1] * inv_lo);
        *(__half2*)(ob1 + col) =
            __floats2half2_rn(oacc[nt][2] * inv_hi, oacc[nt][3] * inv_hi);
    }
}

// ---------------- host ----------------
extern "C" void kernel_launch(void* const* d_in, const int* in_sizes, int n_in,
                              void* d_out, int out_size) {
    const float* hid   = (const float*)d_in[0];
    const float* enc   = (const float*)d_in[1];
    const float* cosb  = (const float*)d_in[2];
    const float* sinb  = (const float*)d_in[3];
    const float* w_qkv = (const float*)d_in[4];
    const float* b_qkv = (const float*)d_in[5];
    const float* w_out = (const float*)d_in[6];
    const float* b_out = (const float*)d_in[7];
    float* out = (float*)d_out;

    __half *xhp, *ohp, *wqhp, *wohp;
    cudaGetSymbolAddress((void**)&xhp,  g_xh);
    cudaGetSymbolAddress((void**)&ohp,  g_oh);
    cudaGetSymbolAddress((void**)&wqhp, g_wqh);
    cudaGetSymbolAddress((void**)&wohp, g_woh);

    static bool attr_set = false;
    if (!attr_set) {
        cudaFuncSetAttribute(mma_gemm<0>, cudaFuncAttributeMaxDynamicSharedMemorySize,
                             (int)GEMM_SMEM);
        cudaFuncSetAttribute(mma_gemm<1>, cudaFuncAttributeMaxDynamicSharedMemorySize,
                             (int)GEMM_SMEM);
        cudaFuncSetAttribute(attn_tc_kernel, cudaFuncAttributeMaxDynamicSharedMemorySize,
                             (int)ATT_SMEM);
        attr_set = true;
    }

    // 0. weights fp32 -> fp16, layout preserved [K][N]
    {
        int n8q = DMODEL * 3 * INNER / 8;
        convert_h<<<(n8q + 255) / 256, 256>>>(w_qkv, wqhp, n8q);
        int n8o = INNER * DMODEL / 8;
        convert_h<<<(n8o + 255) / 256, 256>>>(w_out, wohp, n8o);
    }
    // 1. concat -> fp16
    {
        int total = ROWS * DMODEL / 8;
        concat_kernel<<<(total + 255) / 256, 256>>>(hid, enc);
    }
    // 2. qkv gemm with fused bias+LN+RoPE epilogue -> fp16 q/k/v
    {
        dim3 grid(3 * INNER / 128, ROWS / 128);
        mma_gemm<0><<<grid, 256, GEMM_SMEM>>>(ROWS, 3 * INNER, DMODEL,
                                              xhp, wqhp, b_qkv, nullptr,
                                              cosb, sinb);
    }
    // 3. attention (fp16 HMMA, q-tile 64, 2-stage pipeline, 2 CTA/SM)
    {
        dim3 grid(SEQ / 64, HEADS, BATCH);
        attn_tc_kernel<<<grid, 128, ATT_SMEM>>>();
    }
    // 4. out proj with row remap
    {
        dim3 grid(DMODEL / 128, ROWS / 128);
        mma_gemm<1><<<grid, 256, GEMM_SMEM>>>(ROWS, DMODEL, DMODEL,
                                              ohp, wohp, b_out, out,
                                              nullptr, nullptr);
    }
}

// round 16
// speedup vs baseline: 3.2830x; 1.0360x over previous
#include <cuda_runtime.h>
#include <cuda_fp16.h>
#include <math.h>
#include <stdint.h>

#define HEADS  24
#define HDIM   128
#define BATCH  2
#define TXT    256
#define IMG    1024
#define SEQ    1280          // TXT + IMG
#define DMODEL 3072
#define INNER  3072          // HEADS*HDIM
#define ROWS   (BATCH*SEQ)   // 2560

// ---------------- scratch (static device globals: allowed) ----------------
__device__ __half g_xh [ROWS * DMODEL];           // fp16 concat input
__device__ __half g_qh [BATCH * HEADS * SEQ * HDIM]; // fp16 q (post LN/RoPE)
__device__ __half g_kh [BATCH * HEADS * SEQ * HDIM];
__device__ __half g_vh [BATCH * HEADS * SEQ * HDIM];
__device__ __half g_oh [ROWS * INNER];            // fp16 attn out
__device__ __half g_wqh[DMODEL * 3 * INNER];      // fp16 w_qkv [K][N]
__device__ __half g_woh[INNER * DMODEL];          // fp16 w_out [K][N]

// ---------------- mma / ldmatrix helpers ----------------
#define LDSM_X4(R0, R1, R2, R3, A) \
    asm volatile("ldmatrix.sync.aligned.m8n8.x4.shared.b16 {%0,%1,%2,%3}, [%4];" \
                 : "=r"(R0), "=r"(R1), "=r"(R2), "=r"(R3) : "r"(A))
#define LDSM_X4_T(R0, R1, R2, R3, A) \
    asm volatile("ldmatrix.sync.aligned.m8n8.x4.trans.shared.b16 {%0,%1,%2,%3}, [%4];" \
                 : "=r"(R0), "=r"(R1), "=r"(R2), "=r"(R3) : "r"(A))
#define HMMA(D, A0, A1, A2, A3, B0, B1) \
    asm volatile("mma.sync.aligned.m16n8k16.row.col.f32.f16.f16.f32 " \
                 "{%0,%1,%2,%3}, {%4,%5,%6,%7}, {%8,%9}, {%0,%1,%2,%3};" \
                 : "+f"((D)[0]), "+f"((D)[1]), "+f"((D)[2]), "+f"((D)[3]) \
                 : "r"(A0), "r"(A1), "r"(A2), "r"(A3), "r"(B0), "r"(B1))

// ---------------- 0. elementwise fp32 -> fp16 weight convert ----------------
__global__ void convert_h(const float* __restrict__ src,
                          __half* __restrict__ dst, int n8) {
    int idx = blockIdx.x * blockDim.x + threadIdx.x;
    if (idx >= n8) return;
    float4 v0 = ((const float4*)src)[idx * 2];
    float4 v1 = ((const float4*)src)[idx * 2 + 1];
    __half2 h[4];
    h[0] = __floats2half2_rn(v0.x, v0.y);
    h[1] = __floats2half2_rn(v0.z, v0.w);
    h[2] = __floats2half2_rn(v1.x, v1.y);
    h[3] = __floats2half2_rn(v1.z, v1.w);
    ((uint4*)dst)[idx] = *(uint4*)h;
}

// ---------------- 1. concat -> fp16 ----------------
__global__ void concat_kernel(const float* __restrict__ hid,
                              const float* __restrict__ enc) {
    int idx = blockIdx.x * blockDim.x + threadIdx.x;   // 8-float chunk
    const int total = ROWS * DMODEL / 8;
    if (idx >= total) return;
    int row = idx / (DMODEL / 8);
    int c8  = idx % (DMODEL / 8);
    int b = row / SEQ, s = row % SEQ;
    const float4* src = (s < TXT)
        ? (const float4*)(enc + (size_t)(b * TXT + s) * DMODEL)
        : (const float4*)(hid + (size_t)(b * IMG + (s - TXT)) * DMODEL);
    float4 v0 = src[c8 * 2], v1 = src[c8 * 2 + 1];
    __half2 h[4];
    h[0] = __floats2half2_rn(v0.x, v0.y);
    h[1] = __floats2half2_rn(v0.z, v0.w);
    h[2] = __floats2half2_rn(v1.x, v1.y);
    h[3] = __floats2half2_rn(v1.z, v1.w);
    *(uint4*)(g_xh + (size_t)row * DMODEL + c8 * 8) = *(uint4*)h;
}

// ---------------- 2/4. FP16 GEMM (m16n8k16, BK=64, 3-stage) ----------------
// A [M][K] fp16 (non-trans LDSM); W [K][N] fp16, trans-LDSM B fragments.
// 3-stage cp.async ring, wait_group 1, ONE barrier per K-tile.
// MODE 0: qkv gemm, fused bias+LN+RoPE epilogue -> fp16 g_qh/g_kh/g_vh.
// MODE 1: out-proj, bias + row-remap epilogue -> fp32 C.
#define BK 64
#define ROWB 144                           // A smem row stride (bytes)
#define ATILE_BYTES (128 * ROWB)           // 18432
#define BROWB 272                          // B smem row stride (136 halves)
#define BTILE_BYTES (BK * BROWB)           // 17408
#define STAGE_BYTES (ATILE_BYTES + BTILE_BYTES)   // 35840
#define GEMM_SMEM ((size_t)3 * STAGE_BYTES)       // 107520

template <int MODE>
__global__ __launch_bounds__(256, 2)
void mma_gemm(int M, int N, int K,
              const __half* __restrict__ A, const __half* __restrict__ W,
              const float* __restrict__ bias, float* __restrict__ C,
              const float* __restrict__ cosb, const float* __restrict__ sinb) {
    extern __shared__ char sh[];
    uint32_t sh_u32 = (uint32_t)__cvta_generic_to_shared(sh);
    int tid  = threadIdx.x;
    int lane = tid & 31, wid = tid >> 5;
    int wm = wid >> 2;
    int wn = wid & 3;
    int bm = blockIdx.y * 128;
    int bn = blockIdx.x * 128;
    int r4 = lane >> 2, kc = lane & 3;

    const __half* Ab = A + (size_t)bm * K;
    const __half* Wb = W + bn;               // [K][N], column offset bn

    uint32_t a_off = (uint32_t)((wm * 64 + (lane & 15)) * ROWB + (lane >> 4) * 16);
    uint32_t b_off = (uint32_t)(ATILE_BYTES + (lane & 15) * BROWB + (lane >> 4) * 16);

    float acc[4][4][4];
    #pragma unroll
    for (int i = 0; i < 4; i++)
        #pragma unroll
        for (int j = 0; j < 4; j++)
            #pragma unroll
            for (int r = 0; r < 4; r++) acc[i][j][r] = 0.f;

    auto copy_tile = [&](int k0, int s) {
        char* As = sh + s * STAGE_BYTES;
        char* Bs = As + ATILE_BYTES;
        #pragma unroll
        for (int i = 0; i < 4; i++) {
            int idx = tid + i * 256;          // 0..1023
            int row = idx >> 3, c = idx & 7;  // A: 128 rows x 8 chunks
            uint32_t da = (uint32_t)__cvta_generic_to_shared(
                As + row * ROWB + c * 16);
            asm volatile("cp.async.cg.shared.global [%0], [%1], 16;"
                         :: "r"(da), "l"(Ab + (size_t)row * K + k0 + c * 8));
        }
        #pragma unroll
        for (int i = 0; i < 4; i++) {
            int idx = tid + i * 256;          // B: 64 k-rows x 16 chunks
            int row = idx >> 4, c = idx & 15;
            uint32_t db = (uint32_t)__cvta_generic_to_shared(
                Bs + row * BROWB + c * 16);
            asm volatile("cp.async.cg.shared.global [%0], [%1], 16;"
                         :: "r"(db), "l"(Wb + (size_t)(k0 + row) * N + c * 8));
        }
        asm volatile("cp.async.commit_group;");
    };

    int nK = K / BK;                          // 48
    copy_tile(0, 0);
    copy_tile(BK, 1);

    int s_nxt = 2;
    for (int kt = 0; kt < nK; kt++) {
        asm volatile("cp.async.wait_group 1;");   // tile kt landed; kt+1 in flight
        __syncthreads();                          // single barrier per tile
        {
            int tc = kt + 2; if (tc > nK - 1) tc = nK - 1;   // clamp, always commit
            copy_tile(tc * BK, s_nxt);
            s_nxt = (s_nxt == 2) ? 0 : s_nxt + 1;
        }

        uint32_t sb = sh_u32 + (kt % 3) * STAGE_BYTES;

        #pragma unroll
        for (int kk = 0; kk < 4; kk++) {          // four k16 steps per BK=64
            uint32_t af[4][4], bf[4][2];
            #pragma unroll
            for (int mt = 0; mt < 4; mt++)
                LDSM_X4(af[mt][0], af[mt][1], af[mt][2], af[mt][3],
                        sb + a_off + mt * (16 * ROWB) + kk * 32);
            #pragma unroll
            for (int g = 0; g < 2; g++) {
                uint32_t r0, r1, r2, r3;
                LDSM_X4_T(r0, r1, r2, r3,
                          sb + b_off + kk * (16 * BROWB)
                             + (wn * 32 + g * 16) * 2);
                bf[2 * g][0] = r0; bf[2 * g][1] = r1;
                bf[2 * g + 1][0] = r2; bf[2 * g + 1][1] = r3;
            }
            #pragma unroll
            for (int mt = 0; mt < 4; mt++)
                #pragma unroll
                for (int nt = 0; nt < 4; nt++)
                    HMMA(acc[mt][nt], af[mt][0], af[mt][1], af[mt][2], af[mt][3],
                         bf[nt][0], bf[nt][1]);
        }
    }
    // drain in-flight clamped copies before smem reuse in the epilogue
    asm volatile("cp.async.wait_all;");
    __syncthreads();

    // -------- epilogue --------
    {
        float bv0[4], bv1[4];
        #pragma unroll
        for (int nt = 0; nt < 4; nt++) {
            int n = bn + wn * 32 + nt * 8 + kc * 2;
            bv0[nt] = bias[n]; bv1[nt] = bias[n + 1];
        }
        #pragma unroll
        for (int mt = 0; mt < 4; mt++)
            #pragma unroll
            for (int nt = 0; nt < 4; nt++) {
                acc[mt][nt][0] += bv0[nt]; acc[mt][nt][1] += bv1[nt];
                acc[mt][nt][2] += bv0[nt]; acc[mt][nt][3] += bv1[nt];
            }
    }

    if (MODE == 1) {
        #pragma unroll
        for (int mt = 0; mt < 4; mt++)
            #pragma unroll
            for (int hf = 0; hf < 2; hf++) {
                int m = bm + wm * 64 + mt * 16 + r4 + hf * 8;
                int b = m / SEQ, s = m % SEQ;
                int orow = (s < TXT) ? (BATCH * IMG + b * TXT + s)
                                     : (b * IMG + (s - TXT));
                float* crow = C + (size_t)orow * N;
                #pragma unroll
                for (int nt = 0; nt < 4; nt++) {
                    int n = bn + wn * 32 + nt * 8 + kc * 2;
                    float2 v;
                    v.x = acc[mt][nt][hf * 2 + 0];
                    v.y = acc[mt][nt][hf * 2 + 1];
                    *(float2*)(crow + n) = v;
                }
            }
        return;
    }

    // MODE 0: this CTA's 128 cols == one head of q/k/v.
    int type = bn / INNER;               // 0=q, 1=k, 2=v
    int head = (bn % INNER) / HDIM;

    if (type == 2) {
        #pragma unroll
        for (int mt = 0; mt < 4; mt++)
            #pragma unroll
            for (int hf = 0; hf < 2; hf++) {
                int m = bm + wm * 64 + mt * 16 + r4 + hf * 8;
                int b = m / SEQ, s = m % SEQ;
                __half* dst = g_vh
                    + ((size_t)(b * HEADS + head) * SEQ + s) * HDIM;
                #pragma unroll
                for (int nt = 0; nt < 4; nt++) {
                    int d = wn * 32 + nt * 8 + kc * 2;
                    *(__half2*)(dst + d) =
                        __floats2half2_rn(acc[mt][nt][hf * 2],
                                          acc[mt][nt][hf * 2 + 1]);
                }
            }
        return;
    }

    // q/k: LayerNorm over the 128 CTA-resident cols, then RoPE.
    float2* stats = (float2*)sh;                  // [128][4]
    __half* Qs    = (__half*)(sh + 4096);         // [128][136]

    #pragma unroll
    for (int mt = 0; mt < 4; mt++)
        #pragma unroll
        for (int hf = 0; hf < 2; hf++) {
            float sum = 0.f, sq = 0.f;
            #pragma unroll
            for (int nt = 0; nt < 4; nt++) {
                float a = acc[mt][nt][hf * 2], c2 = acc[mt][nt][hf * 2 + 1];
                sum += a + c2; sq += a * a + c2 * c2;
            }
            sum += __shfl_xor_sync(0xffffffffu, sum, 1);
            sq  += __shfl_xor_sync(0xffffffffu, sq, 1);
            sum += __shfl_xor_sync(0xffffffffu, sum, 2);
            sq  += __shfl_xor_sync(0xffffffffu, sq, 2);
            if (kc == 0) {
                int rl = wm * 64 + mt * 16 + r4 + hf * 8;
                stats[rl * 4 + wn] = make_float2(sum, sq);
            }
        }
    __syncthreads();

    #pragma unroll
    for (int mt = 0; mt < 4; mt++)
        #pragma unroll
        for (int hf = 0; hf < 2; hf++) {
            int rl = wm * 64 + mt * 16 + r4 + hf * 8;
            float sum = 0.f, sq = 0.f;
            #pragma unroll
            for (int w = 0; w < 4; w++) {
                float2 p = stats[rl * 4 + w];
                sum += p.x; sq += p.y;
            }
            float mu = sum * (1.f / 128.f);
            float var = fmaxf(sq * (1.f / 128.f) - mu * mu, 0.f);
            float inv = rsqrtf(var + 1e-5f);
            #pragma unroll
            for (int nt = 0; nt < 4; nt++) {
                int d = wn * 32 + nt * 8 + kc * 2;
                Qs[rl * 136 + d] =
                    __float2half_rn((acc[mt][nt][hf * 2] - mu) * inv);
                Qs[rl * 136 + d + 1] =
                    __float2half_rn((acc[mt][nt][hf * 2 + 1] - mu) * inv);
            }
        }
    __syncthreads();

    __half* dstb = (type == 0) ? g_qh : g_kh;
    #pragma unroll
    for (int it = 0; it < 16; it++) {
        int i = tid + it * 256;
        int r = i >> 5, c4 = i & 31;
        int d0 = c4 * 4;
        int m = bm + r;
        int b = m / SEQ, s = m % SEQ;
        float x[4];
        #pragma unroll
        for (int j = 0; j < 4; j++) x[j] = __half2float(Qs[r * 136 + d0 + j]);
        if (s >= TXT) {
            int dp = d0 ^ 64;
            float sgn = (d0 < 64) ? -1.f : 1.f;
            float4 cv = *(const float4*)(cosb + (size_t)(s - TXT) * HDIM + d0);
            float4 sv = *(const float4*)(sinb + (size_t)(s - TXT) * HDIM + d0);
            float p[4];
            #pragma unroll
            for (int j = 0; j < 4; j++) p[j] = __half2float(Qs[r * 136 + dp + j]);
            x[0] = x[0] * cv.x + sgn * p[0] * sv.x;
            x[1] = x[1] * cv.y + sgn * p[1] * sv.y;
            x[2] = x[2] * cv.z + sgn * p[2] * sv.z;
            x[3] = x[3] * cv.w + sgn * p[3] * sv.w;
        }
        __half* dst = dstb + ((size_t)(b * HEADS + head) * SEQ + s) * HDIM + d0;
        ((__half2*)dst)[0] = __floats2half2_rn(x[0], x[1]);
        ((__half2*)dst)[1] = __floats2half2_rn(x[2], x[3]);
    }
}

// ---------------- 3. flash attention, fp16 TC, 2-stage, 2 CTA/SM -----------
#define KSTH 136
#define PSTH 72
#define KV_STAGE_H (2 * 64 * KSTH)            // 17408 halves
#define KV_STAGE_B (KV_STAGE_H * 2)           // 34816 B
#define ATT_NKV (SEQ / 64)                    // 20
#define ATT_SMEM ((size_t)(2 * KV_STAGE_H + 4 * 16 * PSTH) * 2)   // 78848 B

__global__ __launch_bounds__(128)
void attn_tc_kernel() {
    extern __shared__ __half smh[];
    uint32_t sm_u32 = (uint32_t)__cvta_generic_to_shared(smh);
    __half* Ps = smh + 2 * KV_STAGE_H;

    int qt = blockIdx.x, h = blockIdx.y, b = blockIdx.z;
    int tid = threadIdx.x, lane = tid & 31, wid = tid >> 5;
    size_t hb = (size_t)(b * HEADS + h) * SEQ * HDIM;
    const __half* qb = g_qh + hb + (size_t)qt * 64 * HDIM;
    const __half* kb = g_kh + hb;
    const __half* vb = g_vh + hb;

    __half* Pw = Ps + wid * 16 * PSTH;
    uint32_t pw_u32 = (uint32_t)__cvta_generic_to_shared(Pw);
    uint32_t paddr = pw_u32 + (lane & 15) * (PSTH * 2) + (lane >> 4) * 16;

    for (int i = tid; i < 64 * 16; i += 128) {
        int r = i >> 4, c = i & 15;
        *(uint4*)(smh + r * KSTH + c * 8) =
            *(const uint4*)(qb + (size_t)r * HDIM + c * 8);
    }
    __syncthreads();
    uint32_t qf[8][4];
    {
        uint32_t qaddr = sm_u32 + (wid * 16 + (lane & 15)) * (KSTH * 2)
                       + (lane >> 4) * 16;
        #pragma unroll
        for (int kk = 0; kk < 8; kk++)
            LDSM_X4(qf[kk][0], qf[kk][1], qf[kk][2], qf[kk][3], qaddr + kk * 32);
    }
    __syncthreads();

    auto copy_kv = [&](int kt, int s) {
        uint32_t kbase = sm_u32 + s * KV_STAGE_B;
        uint32_t vbase = kbase + 64 * KSTH * 2;
        #pragma unroll
        for (int i = 0; i < 8; i++) {
            int idx = tid + i * 128;
            int row = idx >> 4, c = idx & 15;
            const __half* srck = kb + (size_t)(kt * 64 + row) * HDIM + c * 8;
            const __half* srcv = vb + (size_t)(kt * 64 + row) * HDIM + c * 8;
            asm volatile("cp.async.cg.shared.global [%0], [%1], 16;"
                         :: "r"(kbase + row * (KSTH * 2) + c * 16), "l"(srck));
            asm volatile("cp.async.cg.shared.global [%0], [%1], 16;"
                         :: "r"(vbase + row * (KSTH * 2) + c * 16), "l"(srcv));
        }
        asm volatile("cp.async.commit_group;");
    };

    copy_kv(0, 0);

    float oacc[16][4];
    #pragma unroll
    for (int nt = 0; nt < 16; nt++)
        #pragma unroll
        for (int r = 0; r < 4; r++) oacc[nt][r] = 0.f;

    float m_lo = -INFINITY, m_hi = -INFINITY, l_lo = 0.f, l_hi = 0.f;
    const float scale = 0.08838834764831845f;

    for (int kt = 0; kt < ATT_NKV; kt++) {
        asm volatile("cp.async.wait_group 0;");
        __syncthreads();
        if (kt + 1 < ATT_NKV) copy_kv(kt + 1, (kt + 1) & 1);

        uint32_t kbase = sm_u32 + (kt & 1) * KV_STAGE_B;
        uint32_t kaddr = kbase + (lane & 15) * (KSTH * 2) + (lane >> 4) * 16;
        uint32_t vaddr = kbase + 64 * KSTH * 2
                       + (lane & 15) * (KSTH * 2) + (lane >> 4) * 16;

        float sacc[8][4];
        #pragma unroll
        for (int nt = 0; nt < 8; nt++)
            #pragma unroll
            for (int r = 0; r < 4; r++) sacc[nt][r] = 0.f;

        #pragma unroll
        for (int kk = 0; kk < 8; kk++) {
            uint32_t bb[8][2];
            #pragma unroll
            for (int g = 0; g < 4; g++) {
                uint32_t r0, r1, r2, r3;
                LDSM_X4(r0, r1, r2, r3, kaddr + g * (16 * KSTH * 2) + kk * 32);
                bb[2 * g][0] = r0; bb[2 * g][1] = r2;
                bb[2 * g + 1][0] = r1; bb[2 * g + 1][1] = r3;
            }
            #pragma unroll
            for (int nt = 0; nt < 8; nt++)
                HMMA(sacc[nt], qf[kk][0], qf[kk][1], qf[kk][2], qf[kk][3],
                     bb[nt][0], bb[nt][1]);
        }

        float mx_lo = m_lo, mx_hi = m_hi;
        #pragma unroll
        for (int nt = 0; nt < 8; nt++) {
            sacc[nt][0] *= scale; sacc[nt][1] *= scale;
            sacc[nt][2] *= scale; sacc[nt][3] *= scale;
            mx_lo = fmaxf(mx_lo, fmaxf(sacc[nt][0], sacc[nt][1]));
            mx_hi = fmaxf(mx_hi, fmaxf(sacc[nt][2], sacc[nt][3]));
        }
        #pragma unroll
        for (int o = 1; o <= 2; o <<= 1) {
            mx_lo = fmaxf(mx_lo, __shfl_xor_sync(0xffffffffu, mx_lo, o));
            mx_hi = fmaxf(mx_hi, __shfl_xor_sync(0xffffffffu, mx_hi, o));
        }
        float f_lo = __expf(m_lo - mx_lo);
        float f_hi = __expf(m_hi - mx_hi);
        float sum_lo = 0.f, sum_hi = 0.f;
        #pragma unroll
        for (int nt = 0; nt < 8; nt++) {
            float p0 = __expf(sacc[nt][0] - mx_lo);
            float p1 = __expf(sacc[nt][1] - mx_lo);
            float p2 = __expf(sacc[nt][2] - mx_hi);
            float p3 = __expf(sacc[nt][3] - mx_hi);
            sum_lo += p0 + p1; sum_hi += p2 + p3;
            int col = nt * 8 + 2 * (lane & 3);
            *(__half2*)(Pw + (lane >> 2) * PSTH + col) = __floats2half2_rn(p0, p1);
            *(__half2*)(Pw + ((lane >> 2) + 8) * PSTH + col) = __floats2half2_rn(p2, p3);
        }
        #pragma unroll
        for (int o = 1; o <= 2; o <<= 1) {
            sum_lo += __shfl_xor_sync(0xffffffffu, sum_lo, o);
            sum_hi += __shfl_xor_sync(0xffffffffu, sum_hi, o);
        }
        l_lo = l_lo * f_lo + sum_lo;
        l_hi = l_hi * f_hi + sum_hi;
        m_lo = mx_lo; m_hi = mx_hi;
        __syncwarp();

        #pragma unroll
        for (int nt = 0; nt < 16; nt++) {
            oacc[nt][0] *= f_lo; oacc[nt][1] *= f_lo;
            oacc[nt][2] *= f_hi; oacc[nt][3] *= f_hi;
        }
        #pragma unroll
        for (int kkv = 0; kkv < 4; kkv++) {
            uint32_t pf0, pf1, pf2, pf3;
            LDSM_X4(pf0, pf1, pf2, pf3, paddr + kkv * 32);
            #pragma unroll
            for (int np = 0; np < 8; np++) {
                uint32_t v0, v1, v2, v3;
                LDSM_X4_T(v0, v1, v2, v3,
                          vaddr + kkv * (16 * KSTH * 2) + np * 32);
                HMMA(oacc[2 * np],     pf0, pf1, pf2, pf3, v0, v1);
                HMMA(oacc[2 * np + 1], pf0, pf1, pf2, pf3, v2, v3);
            }
        }
    }

    float inv_lo = 1.f / l_lo, inv_hi = 1.f / l_hi;
    int r = qt * 64 + wid * 16 + (lane >> 2);
    __half* ob0 = g_oh + ((size_t)b * SEQ + r) * INNER + h * HDIM;
    __half* ob1 = g_oh + ((size_t)b * SEQ + r + 8) * INNER + h * HDIM;
    #pragma unroll
    for (int nt = 0; nt < 16; nt++) {
        int col = nt * 8 + 2 * (lane & 3);
        *(__half2*)(ob0 + col) =
            __floats2half2_rn(oacc[nt][0] * inv_lo, oacc[nt][1] * inv_lo);
        *(__half2*)(ob1 + col) =
            __floats2half2_rn(oacc[nt][2] * inv_hi, oacc[nt][3] * inv_hi);
    }
}

// ---------------- host ----------------
extern "C" void kernel_launch(void* const* d_in, const int* in_sizes, int n_in,
                              void* d_out, int out_size) {
    const float* hid   = (const float*)d_in[0];
    const float* enc   = (const float*)d_in[1];
    const float* cosb  = (const float*)d_in[2];
    const float* sinb  = (const float*)d_in[3];
    const float* w_qkv = (const float*)d_in[4];
    const float* b_qkv = (const float*)d_in[5];
    const float* w_out = (const float*)d_in[6];
    const float* b_out = (const float*)d_in[7];
    float* out = (float*)d_out;

    __half *xhp, *ohp, *wqhp, *wohp;
    cudaGetSymbolAddress((void**)&xhp,  g_xh);
    cudaGetSymbolAddress((void**)&ohp,  g_oh);
    cudaGetSymbolAddress((void**)&wqhp, g_wqh);
    cudaGetSymbolAddress((void**)&wohp, g_woh);

    static bool attr_set = false;
    if (!attr_set) {
        cudaFuncSetAttribute(mma_gemm<0>, cudaFuncAttributeMaxDynamicSharedMemorySize,
                             (int)GEMM_SMEM);
        cudaFuncSetAttribute(mma_gemm<1>, cudaFuncAttributeMaxDynamicSharedMemorySize,
                             (int)GEMM_SMEM);
        cudaFuncSetAttribute(attn_tc_kernel, cudaFuncAttributeMaxDynamicSharedMemorySize,
                             (int)ATT_SMEM);
        attr_set = true;
    }

    // 0. weights fp32 -> fp16, layout preserved [K][N]
    {
        int n8q = DMODEL * 3 * INNER / 8;
        convert_h<<<(n8q + 255) / 256, 256>>>(w_qkv, wqhp, n8q);
        int n8o = INNER * DMODEL / 8;
        convert_h<<<(n8o + 255) / 256, 256>>>(w_out, wohp, n8o);
    }
    // 1. concat -> fp16
    {
        int total = ROWS * DMODEL / 8;
        concat_kernel<<<(total + 255) / 256, 256>>>(hid, enc);
    }
    // 2. qkv gemm with fused bias+LN+RoPE epilogue -> fp16 q/k/v
    {
        dim3 grid(3 * INNER / 128, ROWS / 128);
        mma_gemm<0><<<grid, 256, GEMM_SMEM>>>(ROWS, 3 * INNER, DMODEL,
                                              xhp, wqhp, b_qkv, nullptr,
                                              cosb, sinb);
    }
    // 3. attention (fp16 HMMA, q-tile 64, 2-stage pipeline, 2 CTA/SM)
    {
        dim3 grid(SEQ / 64, HEADS, BATCH);
        attn_tc_kernel<<<grid, 128, ATT_SMEM>>>();
    }
    // 4. out proj with row remap
    {
        dim3 grid(DMODEL / 128, ROWS / 128);
        mma_gemm<1><<<grid, 256, GEMM_SMEM>>>(ROWS, DMODEL, DMODEL,
                                              ohp, wohp, b_out, out,
                                              nullptr, nullptr);
    }
}

// round 17
// speedup vs baseline: 3.3316x; 1.0148x over previous
#include <cuda_runtime.h>
#include <cuda_fp16.h>
#include <math.h>
#include <stdint.h>

#define HEADS  24
#define HDIM   128
#define BATCH  2
#define TXT    256
#define IMG    1024
#define SEQ    1280          // TXT + IMG
#define DMODEL 3072
#define INNER  3072          // HEADS*HDIM
#define ROWS   (BATCH*SEQ)   // 2560

// ---------------- scratch (static device globals: allowed) ----------------
__device__ __half g_xh [ROWS * DMODEL];           // fp16 concat input
__device__ __half g_qh [BATCH * HEADS * SEQ * HDIM]; // fp16 q (post LN/RoPE)
__device__ __half g_kh [BATCH * HEADS * SEQ * HDIM];
__device__ __half g_vh [BATCH * HEADS * SEQ * HDIM];
__device__ __half g_oh [ROWS * INNER];            // fp16 attn out
__device__ __half g_wqh[DMODEL * 3 * INNER];      // fp16 w_qkv [K][N]
__device__ __half g_woh[INNER * DMODEL];          // fp16 w_out [K][N]

// ---------------- mma / ldmatrix helpers ----------------
#define LDSM_X4(R0, R1, R2, R3, A) \
    asm volatile("ldmatrix.sync.aligned.m8n8.x4.shared.b16 {%0,%1,%2,%3}, [%4];" \
                 : "=r"(R0), "=r"(R1), "=r"(R2), "=r"(R3) : "r"(A))
#define LDSM_X4_T(R0, R1, R2, R3, A) \
    asm volatile("ldmatrix.sync.aligned.m8n8.x4.trans.shared.b16 {%0,%1,%2,%3}, [%4];" \
                 : "=r"(R0), "=r"(R1), "=r"(R2), "=r"(R3) : "r"(A))
#define HMMA(D, A0, A1, A2, A3, B0, B1) \
    asm volatile("mma.sync.aligned.m16n8k16.row.col.f32.f16.f16.f32 " \
                 "{%0,%1,%2,%3}, {%4,%5,%6,%7}, {%8,%9}, {%0,%1,%2,%3};" \
                 : "+f"((D)[0]), "+f"((D)[1]), "+f"((D)[2]), "+f"((D)[3]) \
                 : "r"(A0), "r"(A1), "r"(A2), "r"(A3), "r"(B0), "r"(B1))

// ---------------- 0. elementwise fp32 -> fp16 weight convert ----------------
__global__ void convert_h(const float* __restrict__ src,
                          __half* __restrict__ dst, int n8) {
    int idx = blockIdx.x * blockDim.x + threadIdx.x;
    if (idx >= n8) return;
    float4 v0 = ((const float4*)src)[idx * 2];
    float4 v1 = ((const float4*)src)[idx * 2 + 1];
    __half2 h[4];
    h[0] = __floats2half2_rn(v0.x, v0.y);
    h[1] = __floats2half2_rn(v0.z, v0.w);
    h[2] = __floats2half2_rn(v1.x, v1.y);
    h[3] = __floats2half2_rn(v1.z, v1.w);
    ((uint4*)dst)[idx] = *(uint4*)h;
}

// ---------------- 1. concat -> fp16 ----------------
__global__ void concat_kernel(const float* __restrict__ hid,
                              const float* __restrict__ enc) {
    int idx = blockIdx.x * blockDim.x + threadIdx.x;   // 8-float chunk
    const int total = ROWS * DMODEL / 8;
    if (idx >= total) return;
    int row = idx / (DMODEL / 8);
    int c8  = idx % (DMODEL / 8);
    int b = row / SEQ, s = row % SEQ;
    const float4* src = (s < TXT)
        ? (const float4*)(enc + (size_t)(b * TXT + s) * DMODEL)
        : (const float4*)(hid + (size_t)(b * IMG + (s - TXT)) * DMODEL);
    float4 v0 = src[c8 * 2], v1 = src[c8 * 2 + 1];
    __half2 h[4];
    h[0] = __floats2half2_rn(v0.x, v0.y);
    h[1] = __floats2half2_rn(v0.z, v0.w);
    h[2] = __floats2half2_rn(v1.x, v1.y);
    h[3] = __floats2half2_rn(v1.z, v1.w);
    *(uint4*)(g_xh + (size_t)row * DMODEL + c8 * 8) = *(uint4*)h;
}

// ---------------- 2/4. FP16 GEMM (m16n8k16, BK=64, 3-stage) ----------------
#define BK 64
#define ROWB 144                           // A smem row stride (bytes)
#define ATILE_BYTES (128 * ROWB)           // 18432
#define BROWB 272                          // B smem row stride (136 halves)
#define BTILE_BYTES (BK * BROWB)           // 17408
#define STAGE_BYTES (ATILE_BYTES + BTILE_BYTES)   // 35840
#define GEMM_SMEM ((size_t)3 * STAGE_BYTES)       // 107520

template <int MODE>
__global__ __launch_bounds__(256, 2)
void mma_gemm(int M, int N, int K,
              const __half* __restrict__ A, const __half* __restrict__ W,
              const float* __restrict__ bias, float* __restrict__ C,
              const float* __restrict__ cosb, const float* __restrict__ sinb) {
    extern __shared__ char sh[];
    uint32_t sh_u32 = (uint32_t)__cvta_generic_to_shared(sh);
    int tid  = threadIdx.x;
    int lane = tid & 31, wid = tid >> 5;
    int wm = wid >> 2;
    int wn = wid & 3;
    int bm = blockIdx.y * 128;
    int bn = blockIdx.x * 128;
    int r4 = lane >> 2, kc = lane & 3;

    const __half* Ab = A + (size_t)bm * K;
    const __half* Wb = W + bn;               // [K][N], column offset bn

    uint32_t a_off = (uint32_t)((wm * 64 + (lane & 15)) * ROWB + (lane >> 4) * 16);
    uint32_t b_off = (uint32_t)(ATILE_BYTES + (lane & 15) * BROWB + (lane >> 4) * 16);

    float acc[4][4][4];
    #pragma unroll
    for (int i = 0; i < 4; i++)
        #pragma unroll
        for (int j = 0; j < 4; j++)
            #pragma unroll
            for (int r = 0; r < 4; r++) acc[i][j][r] = 0.f;

    auto copy_tile = [&](int k0, int s) {
        char* As = sh + s * STAGE_BYTES;
        char* Bs = As + ATILE_BYTES;
        #pragma unroll
        for (int i = 0; i < 4; i++) {
            int idx = tid + i * 256;          // 0..1023
            int row = idx >> 3, c = idx & 7;  // A: 128 rows x 8 chunks
            uint32_t da = (uint32_t)__cvta_generic_to_shared(
                As + row * ROWB + c * 16);
            asm volatile("cp.async.cg.shared.global [%0], [%1], 16;"
                         :: "r"(da), "l"(Ab + (size_t)row * K + k0 + c * 8));
        }
        #pragma unroll
        for (int i = 0; i < 4; i++) {
            int idx = tid + i * 256;          // B: 64 k-rows x 16 chunks
            int row = idx >> 4, c = idx & 15;
            uint32_t db = (uint32_t)__cvta_generic_to_shared(
                Bs + row * BROWB + c * 16);
            asm volatile("cp.async.cg.shared.global [%0], [%1], 16;"
                         :: "r"(db), "l"(Wb + (size_t)(k0 + row) * N + c * 8));
        }
        asm volatile("cp.async.commit_group;");
    };

    int nK = K / BK;                          // 48
    copy_tile(0, 0);
    copy_tile(BK, 1);

    int s_nxt = 2;
    for (int kt = 0; kt < nK; kt++) {
        asm volatile("cp.async.wait_group 1;");   // tile kt landed; kt+1 in flight
        __syncthreads();                          // single barrier per tile
        {
            int tc = kt + 2; if (tc > nK - 1) tc = nK - 1;   // clamp, always commit
            copy_tile(tc * BK, s_nxt);
            s_nxt = (s_nxt == 2) ? 0 : s_nxt + 1;
        }

        uint32_t sb = sh_u32 + (kt % 3) * STAGE_BYTES;

        #pragma unroll
        for (int kk = 0; kk < 4; kk++) {          // four k16 steps per BK=64
            uint32_t af[4][4], bf[4][2];
            #pragma unroll
            for (int mt = 0; mt < 4; mt++)
                LDSM_X4(af[mt][0], af[mt][1], af[mt][2], af[mt][3],
                        sb + a_off + mt * (16 * ROWB) + kk * 32);
            #pragma unroll
            for (int g = 0; g < 2; g++) {
                uint32_t r0, r1, r2, r3;
                LDSM_X4_T(r0, r1, r2, r3,
                          sb + b_off + kk * (16 * BROWB)
                             + (wn * 32 + g * 16) * 2);
                bf[2 * g][0] = r0; bf[2 * g][1] = r1;
                bf[2 * g + 1][0] = r2; bf[2 * g + 1][1] = r3;
            }
            #pragma unroll
            for (int mt = 0; mt < 4; mt++)
                #pragma unroll
                for (int nt = 0; nt < 4; nt++)
                    HMMA(acc[mt][nt], af[mt][0], af[mt][1], af[mt][2], af[mt][3],
                         bf[nt][0], bf[nt][1]);
        }
    }
    // drain in-flight clamped copies before smem reuse in the epilogue
    asm volatile("cp.async.wait_all;");
    __syncthreads();

    // -------- epilogue --------
    {
        float bv0[4], bv1[4];
        #pragma unroll
        for (int nt = 0; nt < 4; nt++) {
            int n = bn + wn * 32 + nt * 8 + kc * 2;
            bv0[nt] = bias[n]; bv1[nt] = bias[n + 1];
        }
        #pragma unroll
        for (int mt = 0; mt < 4; mt++)
            #pragma unroll
            for (int nt = 0; nt < 4; nt++) {
                acc[mt][nt][0] += bv0[nt]; acc[mt][nt][1] += bv1[nt];
                acc[mt][nt][2] += bv0[nt]; acc[mt][nt][3] += bv1[nt];
            }
    }

    if (MODE == 1) {
        #pragma unroll
        for (int mt = 0; mt < 4; mt++)
            #pragma unroll
            for (int hf = 0; hf < 2; hf++) {
                int m = bm + wm * 64 + mt * 16 + r4 + hf * 8;
                int b = m / SEQ, s = m % SEQ;
                int orow = (s < TXT) ? (BATCH * IMG + b * TXT + s)
                                     : (b * IMG + (s - TXT));
                float* crow = C + (size_t)orow * N;
                #pragma unroll
                for (int nt = 0; nt < 4; nt++) {
                    int n = bn + wn * 32 + nt * 8 + kc * 2;
                    float2 v;
                    v.x = acc[mt][nt][hf * 2 + 0];
                    v.y = acc[mt][nt][hf * 2 + 1];
                    *(float2*)(crow + n) = v;
                }
            }
        return;
    }

    // MODE 0: this CTA's 128 cols == one head of q/k/v.
    int type = bn / INNER;               // 0=q, 1=k, 2=v
    int head = (bn % INNER) / HDIM;

    if (type == 2) {
        #pragma unroll
        for (int mt = 0; mt < 4; mt++)
            #pragma unroll
            for (int hf = 0; hf < 2; hf++) {
                int m = bm + wm * 64 + mt * 16 + r4 + hf * 8;
                int b = m / SEQ, s = m % SEQ;
                __half* dst = g_vh
                    + ((size_t)(b * HEADS + head) * SEQ + s) * HDIM;
                #pragma unroll
                for (int nt = 0; nt < 4; nt++) {
                    int d = wn * 32 + nt * 8 + kc * 2;
                    *(__half2*)(dst + d) =
                        __floats2half2_rn(acc[mt][nt][hf * 2],
                                          acc[mt][nt][hf * 2 + 1]);
                }
            }
        return;
    }

    // q/k: LayerNorm over the 128 CTA-resident cols, then RoPE.
    float2* stats = (float2*)sh;                  // [128][4]
    __half* Qs    = (__half*)(sh + 4096);         // [128][136]

    #pragma unroll
    for (int mt = 0; mt < 4; mt++)
        #pragma unroll
        for (int hf = 0; hf < 2; hf++) {
            float sum = 0.f, sq = 0.f;
            #pragma unroll
            for (int nt = 0; nt < 4; nt++) {
                float a = acc[mt][nt][hf * 2], c2 = acc[mt][nt][hf * 2 + 1];
                sum += a + c2; sq += a * a + c2 * c2;
            }
            sum += __shfl_xor_sync(0xffffffffu, sum, 1);
            sq  += __shfl_xor_sync(0xffffffffu, sq, 1);
            sum += __shfl_xor_sync(0xffffffffu, sum, 2);
            sq  += __shfl_xor_sync(0xffffffffu, sq, 2);
            if (kc == 0) {
                int rl = wm * 64 + mt * 16 + r4 + hf * 8;
                stats[rl * 4 + wn] = make_float2(sum, sq);
            }
        }
    __syncthreads();

    #pragma unroll
    for (int mt = 0; mt < 4; mt++)
        #pragma unroll
        for (int hf = 0; hf < 2; hf++) {
            int rl = wm * 64 + mt * 16 + r4 + hf * 8;
            float sum = 0.f, sq = 0.f;
            #pragma unroll
            for (int w = 0; w < 4; w++) {
                float2 p = stats[rl * 4 + w];
                sum += p.x; sq += p.y;
            }
            float mu = sum * (1.f / 128.f);
            float var = fmaxf(sq * (1.f / 128.f) - mu * mu, 0.f);
            float inv = rsqrtf(var + 1e-5f);
            #pragma unroll
            for (int nt = 0; nt < 4; nt++) {
                int d = wn * 32 + nt * 8 + kc * 2;
                Qs[rl * 136 + d] =
                    __float2half_rn((acc[mt][nt][hf * 2] - mu) * inv);
                Qs[rl * 136 + d + 1] =
                    __float2half_rn((acc[mt][nt][hf * 2 + 1] - mu) * inv);
            }
        }
    __syncthreads();

    __half* dstb = (type == 0) ? g_qh : g_kh;
    #pragma unroll
    for (int it = 0; it < 16; it++) {
        int i = tid + it * 256;
        int r = i >> 5, c4 = i & 31;
        int d0 = c4 * 4;
        int m = bm + r;
        int b = m / SEQ, s = m % SEQ;
        float x[4];
        #pragma unroll
        for (int j = 0; j < 4; j++) x[j] = __half2float(Qs[r * 136 + d0 + j]);
        if (s >= TXT) {
            int dp = d0 ^ 64;
            float sgn = (d0 < 64) ? -1.f : 1.f;
            float4 cv = *(const float4*)(cosb + (size_t)(s - TXT) * HDIM + d0);
            float4 sv = *(const float4*)(sinb + (size_t)(s - TXT) * HDIM + d0);
            float p[4];
            #pragma unroll
            for (int j = 0; j < 4; j++) p[j] = __half2float(Qs[r * 136 + dp + j]);
            x[0] = x[0] * cv.x + sgn * p[0] * sv.x;
            x[1] = x[1] * cv.y + sgn * p[1] * sv.y;
            x[2] = x[2] * cv.z + sgn * p[2] * sv.z;
            x[3] = x[3] * cv.w + sgn * p[3] * sv.w;
        }
        __half* dst = dstb + ((size_t)(b * HEADS + head) * SEQ + s) * HDIM + d0;
        ((__half2*)dst)[0] = __floats2half2_rn(x[0], x[1]);
        ((__half2*)dst)[1] = __floats2half2_rn(x[2], x[3]);
    }
}

// ---------------- 3. flash attention, fp16 TC, 3-stage, 2 CTA/SM -----------
// 128 threads / 4 warps; q-tile 64 (16 rows/warp), kv-tile 64, D=128.
// 3-stage cp.async ring, wait_group 1, ONE barrier per kv-iter.
#define KSTH 136
#define PSTH 72
#define KV_STAGE_H (2 * 64 * KSTH)            // 17408 halves
#define KV_STAGE_B (KV_STAGE_H * 2)           // 34816 B
#define ATT_NKV (SEQ / 64)                    // 20
#define ATT_SMEM ((size_t)(3 * KV_STAGE_H + 4 * 16 * PSTH) * 2)   // 113664 B

__global__ __launch_bounds__(128)
void attn_tc_kernel() {
    extern __shared__ __half smh[];
    uint32_t sm_u32 = (uint32_t)__cvta_generic_to_shared(smh);
    __half* Ps = smh + 3 * KV_STAGE_H;

    int qt = blockIdx.x, h = blockIdx.y, b = blockIdx.z;
    int tid = threadIdx.x, lane = tid & 31, wid = tid >> 5;
    size_t hb = (size_t)(b * HEADS + h) * SEQ * HDIM;
    const __half* qb = g_qh + hb + (size_t)qt * 64 * HDIM;
    const __half* kb = g_kh + hb;
    const __half* vb = g_vh + hb;

    __half* Pw = Ps + wid * 16 * PSTH;
    uint32_t pw_u32 = (uint32_t)__cvta_generic_to_shared(Pw);
    uint32_t paddr = pw_u32 + (lane & 15) * (PSTH * 2) + (lane >> 4) * 16;

    // ---- stage Q into stage-0 region (sync loads), extract fragments ----
    for (int i = tid; i < 64 * 16; i += 128) {
        int r = i >> 4, c = i & 15;
        *(uint4*)(smh + r * KSTH + c * 8) =
            *(const uint4*)(qb + (size_t)r * HDIM + c * 8);
    }
    __syncthreads();
    uint32_t qf[8][4];
    {
        uint32_t qaddr = sm_u32 + (wid * 16 + (lane & 15)) * (KSTH * 2)
                       + (lane >> 4) * 16;
        #pragma unroll
        for (int kk = 0; kk < 8; kk++)
            LDSM_X4(qf[kk][0], qf[kk][1], qf[kk][2], qf[kk][3], qaddr + kk * 32);
    }
    __syncthreads();

    auto copy_kv = [&](int kt, int s) {
        uint32_t kbase = sm_u32 + s * KV_STAGE_B;
        uint32_t vbase = kbase + 64 * KSTH * 2;
        #pragma unroll
        for (int i = 0; i < 8; i++) {
            int idx = tid + i * 128;
            int row = idx >> 4, c = idx & 15;
            const __half* srck = kb + (size_t)(kt * 64 + row) * HDIM + c * 8;
            const __half* srcv = vb + (size_t)(kt * 64 + row) * HDIM + c * 8;
            asm volatile("cp.async.cg.shared.global [%0], [%1], 16;"
                         :: "r"(kbase + row * (KSTH * 2) + c * 16), "l"(srck));
            asm volatile("cp.async.cg.shared.global [%0], [%1], 16;"
                         :: "r"(vbase + row * (KSTH * 2) + c * 16), "l"(srcv));
        }
        asm volatile("cp.async.commit_group;");
    };

    copy_kv(0, 0);
    copy_kv(1, 1);

    float oacc[16][4];
    #pragma unroll
    for (int nt = 0; nt < 16; nt++)
        #pragma unroll
        for (int r = 0; r < 4; r++) oacc[nt][r] = 0.f;

    float m_lo = -INFINITY, m_hi = -INFINITY, l_lo = 0.f, l_hi = 0.f;
    const float scale = 0.08838834764831845f;

    int s_nxt = 2;
    for (int kt = 0; kt < ATT_NKV; kt++) {
        asm volatile("cp.async.wait_group 1;");   // tile kt landed; kt+1 in flight
        __syncthreads();                          // single barrier per iter
        {
            int tc = kt + 2; if (tc > ATT_NKV - 1) tc = ATT_NKV - 1;
            copy_kv(tc, s_nxt);
            s_nxt = (s_nxt == 2) ? 0 : s_nxt + 1;
        }

        uint32_t kbase = sm_u32 + (kt % 3) * KV_STAGE_B;
        uint32_t kaddr = kbase + (lane & 15) * (KSTH * 2) + (lane >> 4) * 16;
        uint32_t vaddr = kbase + 64 * KSTH * 2
                       + (lane & 15) * (KSTH * 2) + (lane >> 4) * 16;

        // ---- S = Q @ K^T (16 x 64 per warp) ----
        float sacc[8][4];
        #pragma unroll
        for (int nt = 0; nt < 8; nt++)
            #pragma unroll
            for (int r = 0; r < 4; r++) sacc[nt][r] = 0.f;

        #pragma unroll
        for (int kk = 0; kk < 8; kk++) {
            uint32_t bb[8][2];
            #pragma unroll
            for (int g = 0; g < 4; g++) {
                uint32_t r0, r1, r2, r3;
                LDSM_X4(r0, r1, r2, r3, kaddr + g * (16 * KSTH * 2) + kk * 32);
                bb[2 * g][0] = r0; bb[2 * g][1] = r2;
                bb[2 * g + 1][0] = r1; bb[2 * g + 1][1] = r3;
            }
            #pragma unroll
            for (int nt = 0; nt < 8; nt++)
                HMMA(sacc[nt], qf[kk][0], qf[kk][1], qf[kk][2], qf[kk][3],
                     bb[nt][0], bb[nt][1]);
        }

        // ---- online softmax ----
        float mx_lo = m_lo, mx_hi = m_hi;
        #pragma unroll
        for (int nt = 0; nt < 8; nt++) {
            sacc[nt][0] *= scale; sacc[nt][1] *= scale;
            sacc[nt][2] *= scale; sacc[nt][3] *= scale;
            mx_lo = fmaxf(mx_lo, fmaxf(sacc[nt][0], sacc[nt][1]));
            mx_hi = fmaxf(mx_hi, fmaxf(sacc[nt][2], sacc[nt][3]));
        }
        #pragma unroll
        for (int o = 1; o <= 2; o <<= 1) {
            mx_lo = fmaxf(mx_lo, __shfl_xor_sync(0xffffffffu, mx_lo, o));
            mx_hi = fmaxf(mx_hi, __shfl_xor_sync(0xffffffffu, mx_hi, o));
        }
        float f_lo = __expf(m_lo - mx_lo);
        float f_hi = __expf(m_hi - mx_hi);
        float sum_lo = 0.f, sum_hi = 0.f;
        #pragma unroll
        for (int nt = 0; nt < 8; nt++) {
            float p0 = __expf(sacc[nt][0] - mx_lo);
            float p1 = __expf(sacc[nt][1] - mx_lo);
            float p2 = __expf(sacc[nt][2] - mx_hi);
            float p3 = __expf(sacc[nt][3] - mx_hi);
            sum_lo += p0 + p1; sum_hi += p2 + p3;
            int col = nt * 8 + 2 * (lane & 3);
            *(__half2*)(Pw + (lane >> 2) * PSTH + col) = __floats2half2_rn(p0, p1);
            *(__half2*)(Pw + ((lane >> 2) + 8) * PSTH + col) = __floats2half2_rn(p2, p3);
        }
        #pragma unroll
        for (int o = 1; o <= 2; o <<= 1) {
            sum_lo += __shfl_xor_sync(0xffffffffu, sum_lo, o);
            sum_hi += __shfl_xor_sync(0xffffffffu, sum_hi, o);
        }
        l_lo = l_lo * f_lo + sum_lo;
        l_hi = l_hi * f_hi + sum_hi;
        m_lo = mx_lo; m_hi = mx_hi;
        __syncwarp();

        // ---- rescale O, then O += P @ V (ldmatrix.trans for V) ----
        #pragma unroll
        for (int nt = 0; nt < 16; nt++) {
            oacc[nt][0] *= f_lo; oacc[nt][1] *= f_lo;
            oacc[nt][2] *= f_hi; oacc[nt][3] *= f_hi;
        }
        #pragma unroll
        for (int kkv = 0; kkv < 4; kkv++) {
            uint32_t pf0, pf1, pf2, pf3;
            LDSM_X4(pf0, pf1, pf2, pf3, paddr + kkv * 32);
            #pragma unroll
            for (int np = 0; np < 8; np++) {
                uint32_t v0, v1, v2, v3;
                LDSM_X4_T(v0, v1, v2, v3,
                          vaddr + kkv * (16 * KSTH * 2) + np * 32);
                HMMA(oacc[2 * np],     pf0, pf1, pf2, pf3, v0, v1);
                HMMA(oacc[2 * np + 1], pf0, pf1, pf2, pf3, v2, v3);
            }
        }
    }

    // ---- epilogue ----
    float inv_lo = 1.f / l_lo, inv_hi = 1.f / l_hi;
    int r = qt * 64 + wid * 16 + (lane >> 2);
    __half* ob0 = g_oh + ((size_t)b * SEQ + r) * INNER + h * HDIM;
    __half* ob1 = g_oh + ((size_t)b * SEQ + r + 8) * INNER + h * HDIM;
    #pragma unroll
    for (int nt = 0; nt < 16; nt++) {
        int col = nt * 8 + 2 * (lane & 3);
        *(__half2*)(ob0 + col) =
            __floats2half2_rn(oacc[nt][0] * inv_lo, oacc[nt][1] * inv_lo);
        *(__half2*)(ob1 + col) =
            __floats2half2_rn(oacc[nt][2] * inv_hi, oacc[nt][3] * inv_hi);
    }
}

// ---------------- host ----------------
extern "C" void kernel_launch(void* const* d_in, const int* in_sizes, int n_in,
                              void* d_out, int out_size) {
    const float* hid   = (const float*)d_in[0];
    const float* enc   = (const float*)d_in[1];
    const float* cosb  = (const float*)d_in[2];
    const float* sinb  = (const float*)d_in[3];
    const float* w_qkv = (const float*)d_in[4];
    const float* b_qkv = (const float*)d_in[5];
    const float* w_out = (const float*)d_in[6];
    const float* b_out = (const float*)d_in[7];
    float* out = (float*)d_out;

    __half *xhp, *ohp, *wqhp, *wohp;
    cudaGetSymbolAddress((void**)&xhp,  g_xh);
    cudaGetSymbolAddress((void**)&ohp,  g_oh);
    cudaGetSymbolAddress((void**)&wqhp, g_wqh);
    cudaGetSymbolAddress((void**)&wohp, g_woh);

    static bool attr_set = false;
    if (!attr_set) {
        cudaFuncSetAttribute(mma_gemm<0>, cudaFuncAttributeMaxDynamicSharedMemorySize,
                             (int)GEMM_SMEM);
        cudaFuncSetAttribute(mma_gemm<1>, cudaFuncAttributeMaxDynamicSharedMemorySize,
                             (int)GEMM_SMEM);
        cudaFuncSetAttribute(attn_tc_kernel, cudaFuncAttributeMaxDynamicSharedMemorySize,
                             (int)ATT_SMEM);
        attr_set = true;
    }

    // 0. weights fp32 -> fp16, layout preserved [K][N]
    {
        int n8q = DMODEL * 3 * INNER / 8;
        convert_h<<<(n8q + 255) / 256, 256>>>(w_qkv, wqhp, n8q);
        int n8o = INNER * DMODEL / 8;
        convert_h<<<(n8o + 255) / 256, 256>>>(w_out, wohp, n8o);
    }
    // 1. concat -> fp16
    {
        int total = ROWS * DMODEL / 8;
        concat_kernel<<<(total + 255) / 256, 256>>>(hid, enc);
    }
    // 2. qkv gemm with fused bias+LN+RoPE epilogue -> fp16 q/k/v
    {
        dim3 grid(3 * INNER / 128, ROWS / 128);
        mma_gemm<0><<<grid, 256, GEMM_SMEM>>>(ROWS, 3 * INNER, DMODEL,
                                              xhp, wqhp, b_qkv, nullptr,
                                              cosb, sinb);
    }
    // 3. attention (fp16 HMMA, q-tile 64, 3-stage pipeline, 2 CTA/SM)
    {
        dim3 grid(SEQ / 64, HEADS, BATCH);
        attn_tc_kernel<<<grid, 128, ATT_SMEM>>>();
    }
    // 4. out proj with row remap
    {
        dim3 grid(DMODEL / 128, ROWS / 128);
        mma_gemm<1><<<grid, 256, GEMM_SMEM>>>(ROWS, DMODEL, DMODEL,
                                              ohp, wohp, b_out, out,
                                              nullptr, nullptr);
    }
}